// round 2
// baseline (speedup 1.0000x reference)
#include <cuda_runtime.h>
#include <math.h>

#define NTOK 16384   // B*T*S = 2*32*256
#define DIMV 768
#define HEADS 12
#define DH 64
#define DFF 2048
#define TT 32
#define SS 256

// ---------------- scratch (device globals: allocation-free) ----------------
__device__ float g_x[NTOK * DIMV];
__device__ float g_tn[NTOK * DIMV];
__device__ float g_q[NTOK * DIMV];
__device__ float g_k[NTOK * DIMV];
__device__ float g_v[NTOK * DIMV];
__device__ float g_o[NTOK * DIMV];
__device__ float g_rv[NTOK * DIMV];
__device__ float g_h[NTOK * 2 * DFF];
__device__ float g_act[NTOK * DFF];
__device__ float g_mix[NTOK * HEADS];
__device__ float g_gate[NTOK * HEADS];

// ---------------- simple elementwise ----------------
__global__ void copy_kernel(const float* __restrict__ src, float* __restrict__ dst, int n) {
    int i = blockIdx.x * blockDim.x + threadIdx.x;
    if (i < n) dst[i] = src[i];
}

// ---------------- rmsnorm: one block (256 thr) per token, 768 elems ----------------
__global__ void rmsnorm_kernel(const float* __restrict__ x, const float* __restrict__ w,
                               float* __restrict__ out) {
    int tok = blockIdx.x;
    int tid = threadIdx.x;
    const float* xr = x + (long)tok * DIMV;
    float v0 = xr[tid], v1 = xr[tid + 256], v2 = xr[tid + 512];
    __shared__ float red[256];
    red[tid] = v0 * v0 + v1 * v1 + v2 * v2;
    __syncthreads();
    for (int off = 128; off > 0; off >>= 1) {
        if (tid < off) red[tid] += red[tid + off];
        __syncthreads();
    }
    float inv = rsqrtf(red[0] / (float)DIMV + 1e-6f);
    float* orow = out + (long)tok * DIMV;
    orow[tid]       = v0 * inv * w[tid];
    orow[tid + 256] = v1 * inv * w[tid + 256];
    orow[tid + 512] = v2 * inv * w[tid + 512];
}

// ---------------- GEMM: C[M,N] = A[M,K] @ B[K,N] (+bias) (+=) ----------------
// 128x128 tile, 256 threads, 8x8 micro-tile, K step 8. M,N %128==0, K%8==0.
__global__ __launch_bounds__(256) void gemm_kernel(
    const float* __restrict__ A, const float* __restrict__ B,
    const float* __restrict__ bias, float* __restrict__ C,
    int N, int K, int accumulate)
{
    __shared__ float As[8][128];
    __shared__ float Bs[8][128];
    int tid = threadIdx.x;
    int m0 = blockIdx.y * 128, n0 = blockIdx.x * 128;
    int tr = tid / 16, tc = tid % 16;
    float acc[8][8];
    #pragma unroll
    for (int i = 0; i < 8; i++)
        #pragma unroll
        for (int j = 0; j < 8; j++) acc[i][j] = 0.f;

    for (int k0 = 0; k0 < K; k0 += 8) {
        #pragma unroll
        for (int e = 0; e < 4; e++) {
            int idx = tid + e * 256;
            int r = idx >> 3, c = idx & 7;
            As[c][r] = A[(long)(m0 + r) * K + k0 + c];
            int kr = idx >> 7, cc = idx & 127;
            Bs[kr][cc] = B[(long)(k0 + kr) * N + n0 + cc];
        }
        __syncthreads();
        #pragma unroll
        for (int kk = 0; kk < 8; kk++) {
            float a[8], b[8];
            #pragma unroll
            for (int i = 0; i < 8; i++) a[i] = As[kk][tr * 8 + i];
            #pragma unroll
            for (int j = 0; j < 8; j++) b[j] = Bs[kk][tc * 8 + j];
            #pragma unroll
            for (int i = 0; i < 8; i++)
                #pragma unroll
                for (int j = 0; j < 8; j++) acc[i][j] += a[i] * b[j];
        }
        __syncthreads();
    }
    #pragma unroll
    for (int i = 0; i < 8; i++) {
        long row = m0 + tr * 8 + i;
        #pragma unroll
        for (int j = 0; j < 8; j++) {
            int col = n0 + tc * 8 + j;
            float vv = acc[i][j];
            if (bias) vv += bias[col];
            if (accumulate) C[row * N + col] += vv;
            else            C[row * N + col]  = vv;
        }
    }
}

// ---------------- mix & gate projection: sig(tn@Wmix+bmix), sig(tn@Wg) ----------------
// one warp per token
__global__ void mixgate_kernel(const float* __restrict__ tn,
                               const float* __restrict__ Wmix, const float* __restrict__ bmix,
                               const float* __restrict__ Wg,
                               float* __restrict__ mix, float* __restrict__ gate)
{
    int tok = blockIdx.x;
    int lane = threadIdx.x;
    const float* x = tn + (long)tok * DIMV;
    float t[24];
    #pragma unroll
    for (int e = 0; e < 24; e++) t[e] = x[lane + 32 * e];
    for (int col = 0; col < HEADS; col++) {
        float am = 0.f, ag = 0.f;
        #pragma unroll
        for (int e = 0; e < 24; e++) {
            int d = lane + 32 * e;
            am += t[e] * Wmix[d * HEADS + col];
            ag += t[e] * Wg[d * HEADS + col];
        }
        for (int off = 16; off > 0; off >>= 1) {
            am += __shfl_xor_sync(0xffffffffu, am, off);
            ag += __shfl_xor_sync(0xffffffffu, ag, off);
        }
        if (lane == 0) {
            mix[tok * HEADS + col]  = 1.f / (1.f + expf(-(am + bmix[col])));
            gate[tok * HEADS + col] = 1.f / (1.f + expf(-ag));
        }
    }
}

// ---------------- value-residual lerp: v += mix*(rv - v) ----------------
__global__ void vlerp_kernel(float* __restrict__ v, const float* __restrict__ rv,
                             const float* __restrict__ mix) {
    int idx = blockIdx.x * blockDim.x + threadIdx.x;
    if (idx >= NTOK * DIMV) return;
    int tok = idx / DIMV;
    int h = (idx % DIMV) / DH;
    float m = mix[tok * HEADS + h];
    float vv = v[idx];
    v[idx] = vv + m * (rv[idx] - vv);
}

// ---------------- k per-head l2norm * (gamma+1)*sqrt(DH) ----------------
__global__ void knorm_kernel(float* __restrict__ k, const float* __restrict__ kgam) {
    int tok = blockIdx.x;
    int h = threadIdx.y;
    int lane = threadIdx.x;
    float* kr = k + (long)tok * DIMV + h * DH;
    float a = kr[lane], b = kr[lane + 32];
    float ss = a * a + b * b;
    for (int off = 16; off > 0; off >>= 1) ss += __shfl_xor_sync(0xffffffffu, ss, off);
    float nrm = fmaxf(sqrtf(ss), 1e-12f);
    float inv = 1.f / nrm;
    kr[lane]      = a * inv * (kgam[h * DH + lane]      + 1.f) * 8.0f;
    kr[lane + 32] = b * inv * (kgam[h * DH + lane + 32] + 1.f) * 8.0f;
}

// ---------------- rotary for time layers (applied to q and k) ----------------
__global__ void rotary_kernel(float* __restrict__ q, float* __restrict__ k) {
    int idx = blockIdx.x * blockDim.x + threadIdx.x;  // over NTOK*HEADS*32
    if (idx >= NTOK * HEADS * 32) return;
    int j = idx & 31;
    int h = (idx >> 5) % HEADS;
    int tok = idx / (32 * HEADS);
    int t = (tok / SS) % TT;
    float invf = powf(10000.0f, -(float)(2 * j) / (float)DH);
    float ang = (float)t * invf;
    float c = cosf(ang), s = sinf(ang);
    long off = (long)tok * DIMV + h * DH + j;
    float x1 = q[off], x2 = q[off + 32];
    q[off]      = x1 * c - x2 * s;
    q[off + 32] = x2 * c + x1 * s;
    x1 = k[off]; x2 = k[off + 32];
    k[off]      = x1 * c - x2 * s;
    k[off + 32] = x2 * c + x1 * s;
}

// ---------------- attention: one block per (row, head, query) ----------------
// timeMode=0: row r in [0,64): base=r*SS, stride=1, n=SS, no causal
// timeMode=1: row r in [0,512): b=r/SS, s=r%SS, base=b*TT*SS+s, stride=SS, n=TT, causal
__global__ void attn_kernel(const float* __restrict__ q, const float* __restrict__ k,
                            const float* __restrict__ v, const float* __restrict__ gate,
                            float* __restrict__ o, int n, int stride, int causal, int timeMode)
{
    int i = blockIdx.x, h = blockIdx.y, r = blockIdx.z;
    long base;
    if (timeMode) { int b = r / SS; int s = r % SS; base = (long)b * (TT * SS) + s; }
    else          { base = (long)r * SS; }
    int tid = threadIdx.x;
    __shared__ float sq[DH];
    __shared__ float sc[SS];
    __shared__ float red[128];
    long qi = (base + (long)i * stride) * DIMV + h * DH;
    if (tid < DH) sq[tid] = q[qi + tid];
    __syncthreads();

    for (int j = tid; j < n; j += 128) {
        const float* kr = k + (base + (long)j * stride) * DIMV + h * DH;
        float acc = 0.f;
        #pragma unroll
        for (int d = 0; d < DH; d++) acc += sq[d] * kr[d];
        acc *= 0.125f;                       // DH^-0.5
        acc = tanhf(acc * 0.02f) * 50.0f;    // softclamp
        if (causal && j > i) acc = -3.0e38f;
        sc[j] = acc;
    }
    __syncthreads();

    float m = -3.0e38f;
    for (int j = tid; j < n; j += 128) m = fmaxf(m, sc[j]);
    red[tid] = m; __syncthreads();
    for (int off = 64; off > 0; off >>= 1) {
        if (tid < off) red[tid] = fmaxf(red[tid], red[tid + off]);
        __syncthreads();
    }
    m = red[0]; __syncthreads();

    float sum = 0.f;
    for (int j = tid; j < n; j += 128) {
        float e = expf(sc[j] - m);
        sc[j] = e;
        sum += e;
    }
    red[tid] = sum; __syncthreads();
    for (int off = 64; off > 0; off >>= 1) {
        if (tid < off) red[tid] += red[tid + off];
        __syncthreads();
    }
    float inv = 1.f / red[0];

    if (tid < DH) {
        float acc = 0.f;
        for (int j = 0; j < n; j++)
            acc += sc[j] * v[(base + (long)j * stride) * DIMV + h * DH + tid];
        acc *= inv;
        float g = gate[(base + (long)i * stride) * HEADS + h];
        o[qi + tid] = acc * g;
    }
}

// ---------------- a * gelu_exact(g) from h[N, 2*DFF] ----------------
__global__ void act_kernel(const float* __restrict__ h, float* __restrict__ act) {
    int idx = blockIdx.x * blockDim.x + threadIdx.x;
    if (idx >= NTOK * DFF) return;
    int tok = idx / DFF;
    int c = idx % DFF;
    float a = h[(long)tok * (2 * DFF) + c];
    float g = h[(long)tok * (2 * DFF) + DFF + c];
    float gl = 0.5f * g * (1.f + erff(g * 0.70710678118654752f));
    act[idx] = a * gl;
}

// ---------------- launch ----------------
extern "C" void kernel_launch(void* const* d_in, const int* in_sizes, int n_in,
                              void* d_out, int out_size) {
    const float* tokens      = (const float*)d_in[0];
    const float* attn_norm_w = (const float*)d_in[1];
    const float* Wq          = (const float*)d_in[2];
    const float* Wk          = (const float*)d_in[3];
    const float* Wv          = (const float*)d_in[4];
    const float* Wo          = (const float*)d_in[5];
    const float* Wg          = (const float*)d_in[6];
    const float* Wmix        = (const float*)d_in[7];
    const float* bmix        = (const float*)d_in[8];
    const float* kgam        = (const float*)d_in[9];
    const float* ff_norm_w   = (const float*)d_in[10];
    const float* Win         = (const float*)d_in[11];
    const float* b_in        = (const float*)d_in[12];
    const float* Wout        = (const float*)d_in[13];
    const float* b_out       = (const float*)d_in[14];
    const float* vr_norm_w   = (const float*)d_in[15];
    const float* vr_W        = (const float*)d_in[16];
    const float* final_norm_w= (const float*)d_in[17];

    float *x, *tn, *q, *k, *v, *o, *rv, *h, *act, *mix, *gate;
    cudaGetSymbolAddress((void**)&x,   g_x);
    cudaGetSymbolAddress((void**)&tn,  g_tn);
    cudaGetSymbolAddress((void**)&q,   g_q);
    cudaGetSymbolAddress((void**)&k,   g_k);
    cudaGetSymbolAddress((void**)&v,   g_v);
    cudaGetSymbolAddress((void**)&o,   g_o);
    cudaGetSymbolAddress((void**)&rv,  g_rv);
    cudaGetSymbolAddress((void**)&h,   g_h);
    cudaGetSymbolAddress((void**)&act, g_act);
    cudaGetSymbolAddress((void**)&mix, g_mix);
    cudaGetSymbolAddress((void**)&gate,g_gate);

    const int NTOT = NTOK * DIMV;

    // x = tokens
    copy_kernel<<<(NTOT + 255) / 256, 256>>>(tokens, x, NTOT);

    // value residual: rv = rmsnorm(tokens, vr_norm_w) @ vr_W
    rmsnorm_kernel<<<NTOK, 256>>>(x, vr_norm_w, tn);
    gemm_kernel<<<dim3(DIMV / 128, NTOK / 128), 256>>>(tn, vr_W, nullptr, rv, DIMV, DIMV, 0);

    for (int i = 0; i < 8; i++) {
        const float* aw   = attn_norm_w + (long)i * DIMV;
        const float* wq   = Wq   + (long)i * DIMV * DIMV;
        const float* wk   = Wk   + (long)i * DIMV * DIMV;
        const float* wv   = Wv   + (long)i * DIMV * DIMV;
        const float* wo   = Wo   + (long)i * DIMV * DIMV;
        const float* wg   = Wg   + (long)i * DIMV * HEADS;
        const float* wmix = Wmix + (long)i * DIMV * HEADS;
        const float* bm   = bmix + (long)i * HEADS;
        const float* kg   = kgam + (long)i * HEADS * DH;
        const float* fw   = ff_norm_w + (long)i * DIMV;
        const float* win  = Win  + (long)i * DIMV * (2 * DFF);
        const float* bi   = b_in + (long)i * (2 * DFF);
        const float* wout = Wout + (long)i * DFF * DIMV;
        const float* bo   = b_out + (long)i * DIMV;
        bool is_time = ((i + 1) % 4 == 0);

        // attention block
        rmsnorm_kernel<<<NTOK, 256>>>(x, aw, tn);
        gemm_kernel<<<dim3(DIMV / 128, NTOK / 128), 256>>>(tn, wq, nullptr, q, DIMV, DIMV, 0);
        gemm_kernel<<<dim3(DIMV / 128, NTOK / 128), 256>>>(tn, wk, nullptr, k, DIMV, DIMV, 0);
        gemm_kernel<<<dim3(DIMV / 128, NTOK / 128), 256>>>(tn, wv, nullptr, v, DIMV, DIMV, 0);
        mixgate_kernel<<<NTOK, 32>>>(tn, wmix, bm, wg, mix, gate);
        vlerp_kernel<<<(NTOT + 255) / 256, 256>>>(v, rv, mix);
        knorm_kernel<<<NTOK, dim3(32, HEADS)>>>(k, kg);
        if (is_time) {
            rotary_kernel<<<(NTOK * HEADS * 32 + 255) / 256, 256>>>(q, k);
            attn_kernel<<<dim3(TT, HEADS, NTOK / TT), 128>>>(q, k, v, gate, o, TT, SS, 1, 1);
        } else {
            attn_kernel<<<dim3(SS, HEADS, NTOK / SS), 128>>>(q, k, v, gate, o, SS, 1, 0, 0);
        }
        gemm_kernel<<<dim3(DIMV / 128, NTOK / 128), 256>>>(o, wo, nullptr, x, DIMV, DIMV, 1);

        // feed-forward block
        rmsnorm_kernel<<<NTOK, 256>>>(x, fw, tn);
        gemm_kernel<<<dim3((2 * DFF) / 128, NTOK / 128), 256>>>(tn, win, bi, h, 2 * DFF, DIMV, 0);
        act_kernel<<<(NTOK * DFF + 255) / 256, 256>>>(h, act);
        gemm_kernel<<<dim3(DIMV / 128, NTOK / 128), 256>>>(act, wout, bo, x, DIMV, DFF, 1);
    }

    rmsnorm_kernel<<<NTOK, 256>>>(x, final_norm_w, (float*)d_out);
}

// round 5
// speedup vs baseline: 1.1542x; 1.1542x over previous
#include <cuda_runtime.h>
#include <cuda_bf16.h>
#include <math.h>
#include <stdint.h>

#define NTOK 16384   // B*T*S = 2*32*256
#define DIMV 768
#define HEADS 12
#define DH 64
#define DFF 2048
#define TT 32
#define SS 256

// ---------------- scratch (device globals: allocation-free) ----------------
__device__ float g_x[NTOK * DIMV];
__device__ float g_tn[NTOK * DIMV];
__device__ float g_q[NTOK * DIMV];
__device__ float g_k[NTOK * DIMV];
__device__ float g_v[NTOK * DIMV];
__device__ float g_o[NTOK * DIMV];
__device__ float g_rv[NTOK * DIMV];
__device__ float g_h[NTOK * 2 * DFF];
__device__ float g_act[NTOK * DFF];
__device__ float g_mix[NTOK * HEADS];
__device__ float g_gate[NTOK * HEADS];

// ==================== bf16 HMMA GEMM ====================
// C[M,N] = A[M,K] @ B[K,N] (+bias) (+=), fp32 in/out.
// 3-term bf16 split: A=Ah+Al, B=Bh+Bl; C += AhBh + AhBl + AlBh (err ~2^-16).
// CTA tile 128x128, 8 warps (2x4), warp tile 64x32, K chunk 32.
#define PAD 40

__device__ __forceinline__ void mma_bf16(float* d, const uint32_t* a, const uint32_t* b) {
    asm volatile(
        "mma.sync.aligned.m16n8k16.row.col.f32.bf16.bf16.f32 "
        "{%0,%1,%2,%3}, {%4,%5,%6,%7}, {%8,%9}, {%0,%1,%2,%3};"
        : "+f"(d[0]), "+f"(d[1]), "+f"(d[2]), "+f"(d[3])
        : "r"(a[0]), "r"(a[1]), "r"(a[2]), "r"(a[3]), "r"(b[0]), "r"(b[1]));
}

__global__ __launch_bounds__(256) void gemm_mma(
    const float* __restrict__ A, const float* __restrict__ B,
    const float* __restrict__ bias, float* __restrict__ C,
    int N, int K, int accumulate)
{
    __shared__ __nv_bfloat16 Ah[128][PAD], Al[128][PAD];
    __shared__ __nv_bfloat16 Bh[128][PAD], Bl[128][PAD];

    int tid = threadIdx.x, wid = tid >> 5, lane = tid & 31;
    int m0 = blockIdx.y * 128, n0 = blockIdx.x * 128;
    int wm = (wid & 1) * 64, wn = (wid >> 1) * 32;
    int g = lane >> 2, tig = lane & 3;

    float acc[4][4][4];
    #pragma unroll
    for (int mt = 0; mt < 4; mt++)
        #pragma unroll
        for (int nt = 0; nt < 4; nt++)
            #pragma unroll
            for (int e = 0; e < 4; e++) acc[mt][nt][e] = 0.f;

    for (int kc = 0; kc < K; kc += 32) {
        // load + split A chunk [128 x 32]
        #pragma unroll
        for (int e = 0; e < 16; e++) {
            int idx = tid + e * 256;
            int r = idx >> 5, c = idx & 31;
            float x = A[(long)(m0 + r) * K + kc + c];
            __nv_bfloat16 h = __float2bfloat16(x);
            Ah[r][c] = h;
            Al[r][c] = __float2bfloat16(x - __bfloat162float(h));
        }
        // load + split B chunk [32 x 128] -> store K-major Bs[n][k]
        #pragma unroll
        for (int e = 0; e < 16; e++) {
            int idx = tid + e * 256;
            int kk = idx >> 7, n = idx & 127;
            float x = B[(long)(kc + kk) * N + n0 + n];
            __nv_bfloat16 h = __float2bfloat16(x);
            Bh[n][kk] = h;
            Bl[n][kk] = __float2bfloat16(x - __bfloat162float(h));
        }
        __syncthreads();

        #pragma unroll
        for (int ks = 0; ks < 32; ks += 16) {
            uint32_t bh[4][2], bl[4][2];
            #pragma unroll
            for (int nt = 0; nt < 4; nt++) {
                int rn = wn + nt * 8 + g;
                int cb = ks + tig * 2;
                bh[nt][0] = *(const uint32_t*)&Bh[rn][cb];
                bh[nt][1] = *(const uint32_t*)&Bh[rn][cb + 8];
                bl[nt][0] = *(const uint32_t*)&Bl[rn][cb];
                bl[nt][1] = *(const uint32_t*)&Bl[rn][cb + 8];
            }
            #pragma unroll
            for (int mt = 0; mt < 4; mt++) {
                int ra = wm + mt * 16 + g;
                int ca = ks + tig * 2;
                uint32_t ah[4], al[4];
                ah[0] = *(const uint32_t*)&Ah[ra][ca];
                ah[1] = *(const uint32_t*)&Ah[ra + 8][ca];
                ah[2] = *(const uint32_t*)&Ah[ra][ca + 8];
                ah[3] = *(const uint32_t*)&Ah[ra + 8][ca + 8];
                al[0] = *(const uint32_t*)&Al[ra][ca];
                al[1] = *(const uint32_t*)&Al[ra + 8][ca];
                al[2] = *(const uint32_t*)&Al[ra][ca + 8];
                al[3] = *(const uint32_t*)&Al[ra + 8][ca + 8];
                #pragma unroll
                for (int nt = 0; nt < 4; nt++) {
                    mma_bf16(acc[mt][nt], ah, bh[nt]);
                    mma_bf16(acc[mt][nt], ah, bl[nt]);
                    mma_bf16(acc[mt][nt], al, bh[nt]);
                }
            }
        }
        __syncthreads();
    }

    // epilogue
    #pragma unroll
    for (int mt = 0; mt < 4; mt++) {
        long r = m0 + wm + mt * 16 + g;
        #pragma unroll
        for (int nt = 0; nt < 4; nt++) {
            int c = n0 + wn + nt * 8 + tig * 2;
            float v0 = acc[mt][nt][0], v1 = acc[mt][nt][1];
            float v2 = acc[mt][nt][2], v3 = acc[mt][nt][3];
            if (bias) { v0 += bias[c]; v1 += bias[c + 1]; v2 += bias[c]; v3 += bias[c + 1]; }
            if (accumulate) {
                C[r * N + c]           += v0;
                C[r * N + c + 1]       += v1;
                C[(r + 8) * N + c]     += v2;
                C[(r + 8) * N + c + 1] += v3;
            } else {
                C[r * N + c]           = v0;
                C[r * N + c + 1]       = v1;
                C[(r + 8) * N + c]     = v2;
                C[(r + 8) * N + c + 1] = v3;
            }
        }
    }
}

// ---------------- simple elementwise ----------------
__global__ void copy_kernel(const float* __restrict__ src, float* __restrict__ dst, int n) {
    int i = blockIdx.x * blockDim.x + threadIdx.x;
    if (i < n) dst[i] = src[i];
}

// ---------------- rmsnorm ----------------
__global__ void rmsnorm_kernel(const float* __restrict__ x, const float* __restrict__ w,
                               float* __restrict__ out) {
    int tok = blockIdx.x;
    int tid = threadIdx.x;
    const float* xr = x + (long)tok * DIMV;
    float v0 = xr[tid], v1 = xr[tid + 256], v2 = xr[tid + 512];
    __shared__ float red[256];
    red[tid] = v0 * v0 + v1 * v1 + v2 * v2;
    __syncthreads();
    for (int off = 128; off > 0; off >>= 1) {
        if (tid < off) red[tid] += red[tid + off];
        __syncthreads();
    }
    float inv = rsqrtf(red[0] / (float)DIMV + 1e-6f);
    float* orow = out + (long)tok * DIMV;
    orow[tid]       = v0 * inv * w[tid];
    orow[tid + 256] = v1 * inv * w[tid + 256];
    orow[tid + 512] = v2 * inv * w[tid + 512];
}

// ---------------- mix & gate projection ----------------
__global__ void mixgate_kernel(const float* __restrict__ tn,
                               const float* __restrict__ Wmix, const float* __restrict__ bmix,
                               const float* __restrict__ Wg,
                               float* __restrict__ mix, float* __restrict__ gate)
{
    int tok = blockIdx.x;
    int lane = threadIdx.x;
    const float* x = tn + (long)tok * DIMV;
    float t[24];
    #pragma unroll
    for (int e = 0; e < 24; e++) t[e] = x[lane + 32 * e];
    for (int col = 0; col < HEADS; col++) {
        float am = 0.f, ag = 0.f;
        #pragma unroll
        for (int e = 0; e < 24; e++) {
            int d = lane + 32 * e;
            am += t[e] * Wmix[d * HEADS + col];
            ag += t[e] * Wg[d * HEADS + col];
        }
        for (int off = 16; off > 0; off >>= 1) {
            am += __shfl_xor_sync(0xffffffffu, am, off);
            ag += __shfl_xor_sync(0xffffffffu, ag, off);
        }
        if (lane == 0) {
            mix[tok * HEADS + col]  = 1.f / (1.f + expf(-(am + bmix[col])));
            gate[tok * HEADS + col] = 1.f / (1.f + expf(-ag));
        }
    }
}

// ---------------- value-residual lerp ----------------
__global__ void vlerp_kernel(float* __restrict__ v, const float* __restrict__ rv,
                             const float* __restrict__ mix) {
    int idx = blockIdx.x * blockDim.x + threadIdx.x;
    if (idx >= NTOK * DIMV) return;
    int tok = idx / DIMV;
    int h = (idx % DIMV) / DH;
    float m = mix[tok * HEADS + h];
    float vv = v[idx];
    v[idx] = vv + m * (rv[idx] - vv);
}

// ---------------- k per-head l2norm ----------------
__global__ void knorm_kernel(float* __restrict__ k, const float* __restrict__ kgam) {
    int tok = blockIdx.x;
    int h = threadIdx.y;
    int lane = threadIdx.x;
    float* kr = k + (long)tok * DIMV + h * DH;
    float a = kr[lane], b = kr[lane + 32];
    float ss = a * a + b * b;
    for (int off = 16; off > 0; off >>= 1) ss += __shfl_xor_sync(0xffffffffu, ss, off);
    float nrm = fmaxf(sqrtf(ss), 1e-12f);
    float inv = 1.f / nrm;
    kr[lane]      = a * inv * (kgam[h * DH + lane]      + 1.f) * 8.0f;
    kr[lane + 32] = b * inv * (kgam[h * DH + lane + 32] + 1.f) * 8.0f;
}

// ---------------- rotary for time layers ----------------
__global__ void rotary_kernel(float* __restrict__ q, float* __restrict__ k) {
    int idx = blockIdx.x * blockDim.x + threadIdx.x;
    if (idx >= NTOK * HEADS * 32) return;
    int j = idx & 31;
    int h = (idx >> 5) % HEADS;
    int tok = idx / (32 * HEADS);
    int t = (tok / SS) % TT;
    float invf = powf(10000.0f, -(float)(2 * j) / (float)DH);
    float ang = (float)t * invf;
    float c = cosf(ang), s = sinf(ang);
    long off = (long)tok * DIMV + h * DH + j;
    float x1 = q[off], x2 = q[off + 32];
    q[off]      = x1 * c - x2 * s;
    q[off + 32] = x2 * c + x1 * s;
    x1 = k[off]; x2 = k[off + 32];
    k[off]      = x1 * c - x2 * s;
    k[off + 32] = x2 * c + x1 * s;
}

// ---------------- attention ----------------
__global__ void attn_kernel(const float* __restrict__ q, const float* __restrict__ k,
                            const float* __restrict__ v, const float* __restrict__ gate,
                            float* __restrict__ o, int n, int stride, int causal, int timeMode)
{
    int i = blockIdx.x, h = blockIdx.y, r = blockIdx.z;
    long base;
    if (timeMode) { int b = r / SS; int s = r % SS; base = (long)b * (TT * SS) + s; }
    else          { base = (long)r * SS; }
    int tid = threadIdx.x;
    __shared__ float sq[DH];
    __shared__ float sc[SS];
    __shared__ float red[128];
    long qi = (base + (long)i * stride) * DIMV + h * DH;
    if (tid < DH) sq[tid] = q[qi + tid];
    __syncthreads();

    for (int j = tid; j < n; j += 128) {
        const float* kr = k + (base + (long)j * stride) * DIMV + h * DH;
        float acc = 0.f;
        #pragma unroll
        for (int d = 0; d < DH; d++) acc += sq[d] * kr[d];
        acc *= 0.125f;
        acc = tanhf(acc * 0.02f) * 50.0f;
        if (causal && j > i) acc = -3.0e38f;
        sc[j] = acc;
    }
    __syncthreads();

    float m = -3.0e38f;
    for (int j = tid; j < n; j += 128) m = fmaxf(m, sc[j]);
    red[tid] = m; __syncthreads();
    for (int off = 64; off > 0; off >>= 1) {
        if (tid < off) red[tid] = fmaxf(red[tid], red[tid + off]);
        __syncthreads();
    }
    m = red[0]; __syncthreads();

    float sum = 0.f;
    for (int j = tid; j < n; j += 128) {
        float e = expf(sc[j] - m);
        sc[j] = e;
        sum += e;
    }
    red[tid] = sum; __syncthreads();
    for (int off = 64; off > 0; off >>= 1) {
        if (tid < off) red[tid] += red[tid + off];
        __syncthreads();
    }
    float inv = 1.f / red[0];

    if (tid < DH) {
        float acc = 0.f;
        for (int j = 0; j < n; j++)
            acc += sc[j] * v[(base + (long)j * stride) * DIMV + h * DH + tid];
        acc *= inv;
        float g = gate[(base + (long)i * stride) * HEADS + h];
        o[qi + tid] = acc * g;
    }
}

// ---------------- a * gelu_exact(g) ----------------
__global__ void act_kernel(const float* __restrict__ h, float* __restrict__ act) {
    int idx = blockIdx.x * blockDim.x + threadIdx.x;
    if (idx >= NTOK * DFF) return;
    int tok = idx / DFF;
    int c = idx % DFF;
    float a = h[(long)tok * (2 * DFF) + c];
    float g = h[(long)tok * (2 * DFF) + DFF + c];
    float gl = 0.5f * g * (1.f + erff(g * 0.70710678118654752f));
    act[idx] = a * gl;
}

// ---------------- launch ----------------
extern "C" void kernel_launch(void* const* d_in, const int* in_sizes, int n_in,
                              void* d_out, int out_size) {
    const float* tokens      = (const float*)d_in[0];
    const float* attn_norm_w = (const float*)d_in[1];
    const float* Wq          = (const float*)d_in[2];
    const float* Wk          = (const float*)d_in[3];
    const float* Wv          = (const float*)d_in[4];
    const float* Wo          = (const float*)d_in[5];
    const float* Wg          = (const float*)d_in[6];
    const float* Wmix        = (const float*)d_in[7];
    const float* bmix        = (const float*)d_in[8];
    const float* kgam        = (const float*)d_in[9];
    const float* ff_norm_w   = (const float*)d_in[10];
    const float* Win         = (const float*)d_in[11];
    const float* bi_in       = (const float*)d_in[12];
    const float* Wout        = (const float*)d_in[13];
    const float* b_out       = (const float*)d_in[14];
    const float* vr_norm_w   = (const float*)d_in[15];
    const float* vr_W        = (const float*)d_in[16];
    const float* final_norm_w= (const float*)d_in[17];

    float *x, *tn, *q, *k, *v, *o, *rv, *h, *act, *mix, *gate;
    cudaGetSymbolAddress((void**)&x,   g_x);
    cudaGetSymbolAddress((void**)&tn,  g_tn);
    cudaGetSymbolAddress((void**)&q,   g_q);
    cudaGetSymbolAddress((void**)&k,   g_k);
    cudaGetSymbolAddress((void**)&v,   g_v);
    cudaGetSymbolAddress((void**)&o,   g_o);
    cudaGetSymbolAddress((void**)&rv,  g_rv);
    cudaGetSymbolAddress((void**)&h,   g_h);
    cudaGetSymbolAddress((void**)&act, g_act);
    cudaGetSymbolAddress((void**)&mix, g_mix);
    cudaGetSymbolAddress((void**)&gate,g_gate);

    const int NTOT = NTOK * DIMV;

    copy_kernel<<<(NTOT + 255) / 256, 256>>>(tokens, x, NTOT);

    // value residual: rv = rmsnorm(tokens) @ vr_W
    rmsnorm_kernel<<<NTOK, 256>>>(x, vr_norm_w, tn);
    gemm_mma<<<dim3(DIMV / 128, NTOK / 128), 256>>>(tn, vr_W, nullptr, rv, DIMV, DIMV, 0);

    for (int i = 0; i < 8; i++) {
        const float* aw   = attn_norm_w + (long)i * DIMV;
        const float* wq   = Wq   + (long)i * DIMV * DIMV;
        const float* wk   = Wk   + (long)i * DIMV * DIMV;
        const float* wv   = Wv   + (long)i * DIMV * DIMV;
        const float* wo   = Wo   + (long)i * DIMV * DIMV;
        const float* wg   = Wg   + (long)i * DIMV * HEADS;
        const float* wmix = Wmix + (long)i * DIMV * HEADS;
        const float* bm   = bmix + (long)i * HEADS;
        const float* kg   = kgam + (long)i * HEADS * DH;
        const float* fw   = ff_norm_w + (long)i * DIMV;
        const float* win  = Win  + (long)i * DIMV * (2 * DFF);
        const float* bi   = bi_in + (long)i * (2 * DFF);
        const float* wout = Wout + (long)i * DFF * DIMV;
        const float* bo   = b_out + (long)i * DIMV;
        bool is_time = ((i + 1) % 4 == 0);

        // attention block
        rmsnorm_kernel<<<NTOK, 256>>>(x, aw, tn);
        gemm_mma<<<dim3(DIMV / 128, NTOK / 128), 256>>>(tn, wq, nullptr, q, DIMV, DIMV, 0);
        gemm_mma<<<dim3(DIMV / 128, NTOK / 128), 256>>>(tn, wk, nullptr, k, DIMV, DIMV, 0);
        gemm_mma<<<dim3(DIMV / 128, NTOK / 128), 256>>>(tn, wv, nullptr, v, DIMV, DIMV, 0);
        mixgate_kernel<<<NTOK, 32>>>(tn, wmix, bm, wg, mix, gate);
        vlerp_kernel<<<(NTOT + 255) / 256, 256>>>(v, rv, mix);
        knorm_kernel<<<NTOK, dim3(32, HEADS)>>>(k, kg);
        if (is_time) {
            rotary_kernel<<<(NTOK * HEADS * 32 + 255) / 256, 256>>>(q, k);
            attn_kernel<<<dim3(TT, HEADS, NTOK / TT), 128>>>(q, k, v, gate, o, TT, SS, 1, 1);
        } else {
            attn_kernel<<<dim3(SS, HEADS, NTOK / SS), 128>>>(q, k, v, gate, o, SS, 1, 0, 0);
        }
        gemm_mma<<<dim3(DIMV / 128, NTOK / 128), 256>>>(o, wo, nullptr, x, DIMV, DIMV, 1);

        // feed-forward block
        rmsnorm_kernel<<<NTOK, 256>>>(x, fw, tn);
        gemm_mma<<<dim3((2 * DFF) / 128, NTOK / 128), 256>>>(tn, win, bi, h, 2 * DFF, DIMV, 0);
        act_kernel<<<(NTOK * DFF + 255) / 256, 256>>>(h, act);
        gemm_mma<<<dim3(DIMV / 128, NTOK / 128), 256>>>(act, wout, bo, x, DIMV, DFF, 1);
    }

    rmsnorm_kernel<<<NTOK, 256>>>(x, final_norm_w, (float*)d_out);
}

// round 6
// speedup vs baseline: 4.6390x; 4.0192x over previous
#include <cuda_runtime.h>
#include <cuda_bf16.h>
#include <math.h>
#include <stdint.h>

#define NTOK 16384   // B*T*S = 2*32*256
#define DIMV 768
#define HEADS 12
#define DH 64
#define DFF 2048
#define TT 32
#define SS 256

// weight sizes
#define SZ_SQ   (768*768)
#define SZ_WIN  (768*4096)
#define SZ_WOUT (2048*768)
#define SZ_LAYER (4*SZ_SQ + SZ_WIN + SZ_WOUT)       // 7077888
#define SZ_WTOT (SZ_SQ + 8*SZ_LAYER)                 // 57212928

// ---------------- scratch (device globals: allocation-free) ----------------
__device__ float g_x[NTOK * DIMV];
__device__ float g_tn[NTOK * DIMV];
__device__ float g_q[NTOK * DIMV];
__device__ float g_k[NTOK * DIMV];
__device__ float g_v[NTOK * DIMV];
__device__ float g_o[NTOK * DIMV];
__device__ float g_rv[NTOK * DIMV];
__device__ float g_h[NTOK * 2 * DFF];
__device__ float g_act[NTOK * DFF];
__device__ float g_mix[NTOK * HEADS];
__device__ float g_gate[NTOK * HEADS];
__device__ __nv_bfloat16 g_wthi[SZ_WTOT];   // transposed split weights [N][K]
__device__ __nv_bfloat16 g_wtlo[SZ_WTOT];
__device__ __nv_bfloat16 g_ahi[NTOK * DFF]; // activation split (max M*K = 16384*2048)
__device__ __nv_bfloat16 g_alo[NTOK * DFF];

// ==================== weight transpose + split ====================
// W [K x N] fp32  ->  Wt hi/lo [N x K] bf16
__global__ void tsplit_kernel(const float* __restrict__ W,
                              __nv_bfloat16* __restrict__ hi, __nv_bfloat16* __restrict__ lo,
                              int K, int N) {
    __shared__ float tile[32][33];
    int bn = blockIdx.x * 32, bk = blockIdx.y * 32;
    int tx = threadIdx.x, ty = threadIdx.y;   // 32 x 8
    #pragma unroll
    for (int i = ty; i < 32; i += 8)
        tile[i][tx] = W[(long)(bk + i) * N + bn + tx];
    __syncthreads();
    #pragma unroll
    for (int i = ty; i < 32; i += 8) {
        float x = tile[tx][i];                 // = W[bk+tx][bn+i]
        __nv_bfloat16 h = __float2bfloat16(x);
        long out = (long)(bn + i) * K + bk + tx;
        hi[out] = h;
        lo[out] = __float2bfloat16(x - __bfloat162float(h));
    }
}

// ---------------- activation split (no transpose) ----------------
__global__ void split_kernel(const float* __restrict__ x,
                             __nv_bfloat16* __restrict__ hi, __nv_bfloat16* __restrict__ lo,
                             int n) {
    int i = blockIdx.x * blockDim.x + threadIdx.x;
    if (i >= n) return;
    float v = x[i];
    __nv_bfloat16 h = __float2bfloat16(v);
    hi[i] = h;
    lo[i] = __float2bfloat16(v - __bfloat162float(h));
}

// ==================== bf16 HMMA GEMM (pre-split inputs, cp.async double-buffer) ====================
// C[M,N] = A[M,K] @ B[K,N] (+bias) (+=).  A given as hi/lo bf16 [M][K];
// B given as hi/lo bf16 TRANSPOSED [N][K].  3-term: AhBh + AhBl + AlBh.
// CTA tile 128x128, 8 warps (2x4), warp tile 64x32, K chunk 32, 2-stage pipeline.
#define CH_BYTES 10240                       // one [128][40] bf16 array
#define BUF_BYTES (4 * CH_BYTES)             // Ah,Al,Bh,Bl
#define GEMM_SMEM (2 * BUF_BYTES)            // 81920

__device__ __forceinline__ uint32_t smem_u32(const void* p) {
    uint32_t a;
    asm("{ .reg .u64 t; cvta.to.shared.u64 t, %1; cvt.u32.u64 %0, t; }" : "=r"(a) : "l"(p));
    return a;
}
__device__ __forceinline__ void cp16(uint32_t dst, const void* src) {
    asm volatile("cp.async.ca.shared.global [%0], [%1], 16;" :: "r"(dst), "l"(src));
}
__device__ __forceinline__ void cp_commit() { asm volatile("cp.async.commit_group;"); }
__device__ __forceinline__ void cp_wait1() { asm volatile("cp.async.wait_group 1;"); }
__device__ __forceinline__ void cp_wait0() { asm volatile("cp.async.wait_group 0;"); }

__device__ __forceinline__ void mma_bf16(float* d, const uint32_t* a, const uint32_t* b) {
    asm volatile(
        "mma.sync.aligned.m16n8k16.row.col.f32.bf16.bf16.f32 "
        "{%0,%1,%2,%3}, {%4,%5,%6,%7}, {%8,%9}, {%0,%1,%2,%3};"
        : "+f"(d[0]), "+f"(d[1]), "+f"(d[2]), "+f"(d[3])
        : "r"(a[0]), "r"(a[1]), "r"(a[2]), "r"(a[3]), "r"(b[0]), "r"(b[1]));
}

__global__ __launch_bounds__(256) void gemm_bf16(
    const __nv_bfloat16* __restrict__ Ah, const __nv_bfloat16* __restrict__ Al,
    const __nv_bfloat16* __restrict__ Bh, const __nv_bfloat16* __restrict__ Bl,
    const float* __restrict__ bias, float* __restrict__ C,
    int N, int K, int accumulate)
{
    extern __shared__ char smem[];
    uint32_t sb = smem_u32(smem);
    int tid = threadIdx.x, wid = tid >> 5, lane = tid & 31;
    int m0 = blockIdx.y * 128, n0 = blockIdx.x * 128;
    int wm = (wid & 1) * 64, wn = (wid >> 1) * 32;
    int g = lane >> 2, tig = lane & 3;

    float acc[4][4][4];
    #pragma unroll
    for (int mt = 0; mt < 4; mt++)
        #pragma unroll
        for (int nt = 0; nt < 4; nt++)
            #pragma unroll
            for (int e = 0; e < 4; e++) acc[mt][nt][e] = 0.f;

    int nchunks = K >> 5;
    // loader indices: seg = tid + t*256, row = seg>>2, s4 = seg&3
    int r0 = tid >> 2, s0 = (tid & 3) * 8;        // t=0
    int r1 = (tid + 256) >> 2, s1 = s0;           // t=1 (same s4 since +256 = +64 rows)

    #define LOADCHUNK(b, kc_) do {                                                     \
        uint32_t base = sb + (b) * BUF_BYTES;                                          \
        const __nv_bfloat16* aph = Ah + (long)(m0 + r0) * K + (kc_) + s0;              \
        const __nv_bfloat16* apl = Al + (long)(m0 + r0) * K + (kc_) + s0;              \
        const __nv_bfloat16* bph = Bh + (long)(n0 + r0) * K + (kc_) + s0;              \
        const __nv_bfloat16* bpl = Bl + (long)(n0 + r0) * K + (kc_) + s0;              \
        cp16(base + r0 * 80 + (s0 << 1), aph);                                         \
        cp16(base + CH_BYTES + r0 * 80 + (s0 << 1), apl);                              \
        cp16(base + 2 * CH_BYTES + r0 * 80 + (s0 << 1), bph);                          \
        cp16(base + 3 * CH_BYTES + r0 * 80 + (s0 << 1), bpl);                          \
        const __nv_bfloat16* aph2 = Ah + (long)(m0 + r1) * K + (kc_) + s1;             \
        const __nv_bfloat16* apl2 = Al + (long)(m0 + r1) * K + (kc_) + s1;             \
        const __nv_bfloat16* bph2 = Bh + (long)(n0 + r1) * K + (kc_) + s1;             \
        const __nv_bfloat16* bpl2 = Bl + (long)(n0 + r1) * K + (kc_) + s1;             \
        cp16(base + r1 * 80 + (s1 << 1), aph2);                                        \
        cp16(base + CH_BYTES + r1 * 80 + (s1 << 1), apl2);                             \
        cp16(base + 2 * CH_BYTES + r1 * 80 + (s1 << 1), bph2);                         \
        cp16(base + 3 * CH_BYTES + r1 * 80 + (s1 << 1), bpl2);                         \
    } while (0)

    LOADCHUNK(0, 0);
    cp_commit();

    for (int c = 0; c < nchunks; c++) {
        if (c + 1 < nchunks) {
            LOADCHUNK((c + 1) & 1, (c + 1) << 5);
            cp_commit();
            cp_wait1();
        } else {
            cp_wait0();
        }
        __syncthreads();

        const char* buf = smem + (c & 1) * BUF_BYTES;
        const char* pAh = buf;
        const char* pAl = buf + CH_BYTES;
        const char* pBh = buf + 2 * CH_BYTES;
        const char* pBl = buf + 3 * CH_BYTES;

        #pragma unroll
        for (int ks = 0; ks < 32; ks += 16) {
            uint32_t bh[4][2], bl[4][2];
            #pragma unroll
            for (int nt = 0; nt < 4; nt++) {
                int rn = wn + nt * 8 + g;
                int cb = (ks + tig * 2) * 2;
                bh[nt][0] = *(const uint32_t*)(pBh + rn * 80 + cb);
                bh[nt][1] = *(const uint32_t*)(pBh + rn * 80 + cb + 16);
                bl[nt][0] = *(const uint32_t*)(pBl + rn * 80 + cb);
                bl[nt][1] = *(const uint32_t*)(pBl + rn * 80 + cb + 16);
            }
            #pragma unroll
            for (int mt = 0; mt < 4; mt++) {
                int ra = wm + mt * 16 + g;
                int ca = (ks + tig * 2) * 2;
                uint32_t ah[4], al[4];
                ah[0] = *(const uint32_t*)(pAh + ra * 80 + ca);
                ah[1] = *(const uint32_t*)(pAh + (ra + 8) * 80 + ca);
                ah[2] = *(const uint32_t*)(pAh + ra * 80 + ca + 16);
                ah[3] = *(const uint32_t*)(pAh + (ra + 8) * 80 + ca + 16);
                al[0] = *(const uint32_t*)(pAl + ra * 80 + ca);
                al[1] = *(const uint32_t*)(pAl + (ra + 8) * 80 + ca);
                al[2] = *(const uint32_t*)(pAl + ra * 80 + ca + 16);
                al[3] = *(const uint32_t*)(pAl + (ra + 8) * 80 + ca + 16);
                #pragma unroll
                for (int nt = 0; nt < 4; nt++) {
                    mma_bf16(acc[mt][nt], ah, bh[nt]);
                    mma_bf16(acc[mt][nt], ah, bl[nt]);
                    mma_bf16(acc[mt][nt], al, bh[nt]);
                }
            }
        }
        __syncthreads();
    }

    // epilogue
    #pragma unroll
    for (int mt = 0; mt < 4; mt++) {
        long r = m0 + wm + mt * 16 + g;
        #pragma unroll
        for (int nt = 0; nt < 4; nt++) {
            int c = n0 + wn + nt * 8 + tig * 2;
            float v0 = acc[mt][nt][0], v1 = acc[mt][nt][1];
            float v2 = acc[mt][nt][2], v3 = acc[mt][nt][3];
            if (bias) { v0 += bias[c]; v1 += bias[c + 1]; v2 += bias[c]; v3 += bias[c + 1]; }
            if (accumulate) {
                C[r * N + c]           += v0;
                C[r * N + c + 1]       += v1;
                C[(r + 8) * N + c]     += v2;
                C[(r + 8) * N + c + 1] += v3;
            } else {
                C[r * N + c]           = v0;
                C[r * N + c + 1]       = v1;
                C[(r + 8) * N + c]     = v2;
                C[(r + 8) * N + c + 1] = v3;
            }
        }
    }
}

// ---------------- simple elementwise ----------------
__global__ void copy_kernel(const float* __restrict__ src, float* __restrict__ dst, int n) {
    int i = blockIdx.x * blockDim.x + threadIdx.x;
    if (i < n) dst[i] = src[i];
}

// ---------------- rmsnorm ----------------
__global__ void rmsnorm_kernel(const float* __restrict__ x, const float* __restrict__ w,
                               float* __restrict__ out) {
    int tok = blockIdx.x;
    int tid = threadIdx.x;
    const float* xr = x + (long)tok * DIMV;
    float v0 = xr[tid], v1 = xr[tid + 256], v2 = xr[tid + 512];
    __shared__ float red[256];
    red[tid] = v0 * v0 + v1 * v1 + v2 * v2;
    __syncthreads();
    for (int off = 128; off > 0; off >>= 1) {
        if (tid < off) red[tid] += red[tid + off];
        __syncthreads();
    }
    float inv = rsqrtf(red[0] / (float)DIMV + 1e-6f);
    float* orow = out + (long)tok * DIMV;
    orow[tid]       = v0 * inv * w[tid];
    orow[tid + 256] = v1 * inv * w[tid + 256];
    orow[tid + 512] = v2 * inv * w[tid + 512];
}

// ---------------- mix & gate projection ----------------
__global__ void mixgate_kernel(const float* __restrict__ tn,
                               const float* __restrict__ Wmix, const float* __restrict__ bmix,
                               const float* __restrict__ Wg,
                               float* __restrict__ mix, float* __restrict__ gate)
{
    int tok = blockIdx.x;
    int lane = threadIdx.x;
    const float* x = tn + (long)tok * DIMV;
    float t[24];
    #pragma unroll
    for (int e = 0; e < 24; e++) t[e] = x[lane + 32 * e];
    for (int col = 0; col < HEADS; col++) {
        float am = 0.f, ag = 0.f;
        #pragma unroll
        for (int e = 0; e < 24; e++) {
            int d = lane + 32 * e;
            am += t[e] * Wmix[d * HEADS + col];
            ag += t[e] * Wg[d * HEADS + col];
        }
        for (int off = 16; off > 0; off >>= 1) {
            am += __shfl_xor_sync(0xffffffffu, am, off);
            ag += __shfl_xor_sync(0xffffffffu, ag, off);
        }
        if (lane == 0) {
            mix[tok * HEADS + col]  = 1.f / (1.f + expf(-(am + bmix[col])));
            gate[tok * HEADS + col] = 1.f / (1.f + expf(-ag));
        }
    }
}

// ---------------- value-residual lerp ----------------
__global__ void vlerp_kernel(float* __restrict__ v, const float* __restrict__ rv,
                             const float* __restrict__ mix) {
    int idx = blockIdx.x * blockDim.x + threadIdx.x;
    if (idx >= NTOK * DIMV) return;
    int tok = idx / DIMV;
    int h = (idx % DIMV) / DH;
    float m = mix[tok * HEADS + h];
    float vv = v[idx];
    v[idx] = vv + m * (rv[idx] - vv);
}

// ---------------- k per-head l2norm ----------------
__global__ void knorm_kernel(float* __restrict__ k, const float* __restrict__ kgam) {
    int tok = blockIdx.x;
    int h = threadIdx.y;
    int lane = threadIdx.x;
    float* kr = k + (long)tok * DIMV + h * DH;
    float a = kr[lane], b = kr[lane + 32];
    float ss = a * a + b * b;
    for (int off = 16; off > 0; off >>= 1) ss += __shfl_xor_sync(0xffffffffu, ss, off);
    float nrm = fmaxf(sqrtf(ss), 1e-12f);
    float inv = 1.f / nrm;
    kr[lane]      = a * inv * (kgam[h * DH + lane]      + 1.f) * 8.0f;
    kr[lane + 32] = b * inv * (kgam[h * DH + lane + 32] + 1.f) * 8.0f;
}

// ---------------- rotary for time layers ----------------
__global__ void rotary_kernel(float* __restrict__ q, float* __restrict__ k) {
    int idx = blockIdx.x * blockDim.x + threadIdx.x;
    if (idx >= NTOK * HEADS * 32) return;
    int j = idx & 31;
    int h = (idx >> 5) % HEADS;
    int tok = idx / (32 * HEADS);
    int t = (tok / SS) % TT;
    float invf = powf(10000.0f, -(float)(2 * j) / (float)DH);
    float ang = (float)t * invf;
    float c = cosf(ang), s = sinf(ang);
    long off = (long)tok * DIMV + h * DH + j;
    float x1 = q[off], x2 = q[off + 32];
    q[off]      = x1 * c - x2 * s;
    q[off + 32] = x2 * c + x1 * s;
    x1 = k[off]; x2 = k[off + 32];
    k[off]      = x1 * c - x2 * s;
    k[off + 32] = x2 * c + x1 * s;
}

// ---------------- space attention: block=(group r, head), thread=query ----------------
#define ASP_SMEM (2 * SS * DH * 4)   // 131072
__global__ __launch_bounds__(256, 1) void attn_space(
    const float* __restrict__ q, const float* __restrict__ k, const float* __restrict__ v,
    const float* __restrict__ gate, float* __restrict__ o)
{
    int r = blockIdx.x, h = blockIdx.y;
    long base = (long)r * SS;
    extern __shared__ float sm[];
    float* Ks = sm;
    float* Vs = sm + SS * DH;
    int tid = threadIdx.x;
    for (int idx = tid; idx < SS * DH; idx += 256) {
        int j = idx >> 6, d = idx & 63;
        long tok = base + j;
        Ks[idx] = k[tok * DIMV + h * DH + d];
        Vs[idx] = v[tok * DIMV + h * DH + d];
    }
    __syncthreads();

    long mytok = base + tid;
    float4 qr[16];
    const float4* qp = (const float4*)(q + mytok * DIMV + h * DH);
    #pragma unroll
    for (int e = 0; e < 16; e++) qr[e] = qp[e];

    // pass 1: online max + sum
    float m = -3.0e38f, s = 0.f;
    for (int j = 0; j < SS; j++) {
        const float4* kp = (const float4*)(Ks + j * DH);
        float acc = 0.f;
        #pragma unroll
        for (int e = 0; e < 16; e++) {
            float4 kv = kp[e];
            acc += qr[e].x * kv.x + qr[e].y * kv.y + qr[e].z * kv.z + qr[e].w * kv.w;
        }
        acc = tanhf(acc * 0.0025f) * 50.f;   // (1/8)*(1/50) then *50
        float mn = fmaxf(m, acc);
        s = s * expf(m - mn) + expf(acc - mn);
        m = mn;
    }
    float inv = 1.f / s;

    // pass 2: recompute probs, accumulate o
    float4 oa[16];
    #pragma unroll
    for (int e = 0; e < 16; e++) oa[e] = make_float4(0.f, 0.f, 0.f, 0.f);
    for (int j = 0; j < SS; j++) {
        const float4* kp = (const float4*)(Ks + j * DH);
        float acc = 0.f;
        #pragma unroll
        for (int e = 0; e < 16; e++) {
            float4 kv = kp[e];
            acc += qr[e].x * kv.x + qr[e].y * kv.y + qr[e].z * kv.z + qr[e].w * kv.w;
        }
        acc = tanhf(acc * 0.0025f) * 50.f;
        float p = expf(acc - m) * inv;
        const float4* vp = (const float4*)(Vs + j * DH);
        #pragma unroll
        for (int e = 0; e < 16; e++) {
            float4 vv = vp[e];
            oa[e].x += p * vv.x; oa[e].y += p * vv.y;
            oa[e].z += p * vv.z; oa[e].w += p * vv.w;
        }
    }
    float gg = gate[mytok * HEADS + h];
    float4* op = (float4*)(o + mytok * DIMV + h * DH);
    #pragma unroll
    for (int e = 0; e < 16; e++) {
        oa[e].x *= gg; oa[e].y *= gg; oa[e].z *= gg; oa[e].w *= gg;
        op[e] = oa[e];
    }
}

// ---------------- time attention (causal): block=(b*s, head), thread=query t ----------------
__global__ __launch_bounds__(32) void attn_time(
    const float* __restrict__ q, const float* __restrict__ k, const float* __restrict__ v,
    const float* __restrict__ gate, float* __restrict__ o)
{
    int r = blockIdx.x, h = blockIdx.y;
    int b = r / SS, s0 = r % SS;
    long base = (long)b * (TT * SS) + s0;          // token = base + t*SS
    __shared__ float Ks[TT * DH], Vs[TT * DH];
    int tid = threadIdx.x;
    for (int idx = tid; idx < TT * DH; idx += 32) {
        int j = idx >> 6, d = idx & 63;
        long tok = base + (long)j * SS;
        Ks[idx] = k[tok * DIMV + h * DH + d];
        Vs[idx] = v[tok * DIMV + h * DH + d];
    }
    __syncthreads();

    long mytok = base + (long)tid * SS;
    float4 qr[16];
    const float4* qp = (const float4*)(q + mytok * DIMV + h * DH);
    #pragma unroll
    for (int e = 0; e < 16; e++) qr[e] = qp[e];

    int nkeys = tid + 1;   // causal
    float m = -3.0e38f, s = 0.f;
    for (int j = 0; j < nkeys; j++) {
        const float4* kp = (const float4*)(Ks + j * DH);
        float acc = 0.f;
        #pragma unroll
        for (int e = 0; e < 16; e++) {
            float4 kv = kp[e];
            acc += qr[e].x * kv.x + qr[e].y * kv.y + qr[e].z * kv.z + qr[e].w * kv.w;
        }
        acc = tanhf(acc * 0.0025f) * 50.f;
        float mn = fmaxf(m, acc);
        s = s * expf(m - mn) + expf(acc - mn);
        m = mn;
    }
    float inv = 1.f / s;

    float4 oa[16];
    #pragma unroll
    for (int e = 0; e < 16; e++) oa[e] = make_float4(0.f, 0.f, 0.f, 0.f);
    for (int j = 0; j < nkeys; j++) {
        const float4* kp = (const float4*)(Ks + j * DH);
        float acc = 0.f;
        #pragma unroll
        for (int e = 0; e < 16; e++) {
            float4 kv = kp[e];
            acc += qr[e].x * kv.x + qr[e].y * kv.y + qr[e].z * kv.z + qr[e].w * kv.w;
        }
        acc = tanhf(acc * 0.0025f) * 50.f;
        float p = expf(acc - m) * inv;
        const float4* vp = (const float4*)(Vs + j * DH);
        #pragma unroll
        for (int e = 0; e < 16; e++) {
            float4 vv = vp[e];
            oa[e].x += p * vv.x; oa[e].y += p * vv.y;
            oa[e].z += p * vv.z; oa[e].w += p * vv.w;
        }
    }
    float gg = gate[mytok * HEADS + h];
    float4* op = (float4*)(o + mytok * DIMV + h * DH);
    #pragma unroll
    for (int e = 0; e < 16; e++) {
        oa[e].x *= gg; oa[e].y *= gg; oa[e].z *= gg; oa[e].w *= gg;
        op[e] = oa[e];
    }
}

// ---------------- a * gelu_exact(g) ----------------
__global__ void act_kernel(const float* __restrict__ h, float* __restrict__ act) {
    int idx = blockIdx.x * blockDim.x + threadIdx.x;
    if (idx >= NTOK * DFF) return;
    int tok = idx / DFF;
    int c = idx % DFF;
    float a = h[(long)tok * (2 * DFF) + c];
    float g = h[(long)tok * (2 * DFF) + DFF + c];
    float gl = 0.5f * g * (1.f + erff(g * 0.70710678118654752f));
    act[idx] = a * gl;
}

// ---------------- launch ----------------
extern "C" void kernel_launch(void* const* d_in, const int* in_sizes, int n_in,
                              void* d_out, int out_size) {
    const float* tokens      = (const float*)d_in[0];
    const float* attn_norm_w = (const float*)d_in[1];
    const float* Wq          = (const float*)d_in[2];
    const float* Wk          = (const float*)d_in[3];
    const float* Wv          = (const float*)d_in[4];
    const float* Wo          = (const float*)d_in[5];
    const float* Wg          = (const float*)d_in[6];
    const float* Wmix        = (const float*)d_in[7];
    const float* bmix        = (const float*)d_in[8];
    const float* kgam        = (const float*)d_in[9];
    const float* ff_norm_w   = (const float*)d_in[10];
    const float* Win         = (const float*)d_in[11];
    const float* bi_in       = (const float*)d_in[12];
    const float* Wout        = (const float*)d_in[13];
    const float* b_out       = (const float*)d_in[14];
    const float* vr_norm_w   = (const float*)d_in[15];
    const float* vr_W        = (const float*)d_in[16];
    const float* final_norm_w= (const float*)d_in[17];

    float *x, *tn, *q, *k, *v, *o, *rv, *h, *act, *mix, *gate;
    __nv_bfloat16 *wthi, *wtlo, *ahi, *alo;
    cudaGetSymbolAddress((void**)&x,   g_x);
    cudaGetSymbolAddress((void**)&tn,  g_tn);
    cudaGetSymbolAddress((void**)&q,   g_q);
    cudaGetSymbolAddress((void**)&k,   g_k);
    cudaGetSymbolAddress((void**)&v,   g_v);
    cudaGetSymbolAddress((void**)&o,   g_o);
    cudaGetSymbolAddress((void**)&rv,  g_rv);
    cudaGetSymbolAddress((void**)&h,   g_h);
    cudaGetSymbolAddress((void**)&act, g_act);
    cudaGetSymbolAddress((void**)&mix, g_mix);
    cudaGetSymbolAddress((void**)&gate,g_gate);
    cudaGetSymbolAddress((void**)&wthi,g_wthi);
    cudaGetSymbolAddress((void**)&wtlo,g_wtlo);
    cudaGetSymbolAddress((void**)&ahi, g_ahi);
    cudaGetSymbolAddress((void**)&alo, g_alo);

    static int attr_done = 0;
    if (!attr_done) {
        cudaFuncSetAttribute(gemm_bf16, cudaFuncAttributeMaxDynamicSharedMemorySize, GEMM_SMEM);
        cudaFuncSetAttribute(attn_space, cudaFuncAttributeMaxDynamicSharedMemorySize, ASP_SMEM);
        attr_done = 1;
    }

    const int NTOT = NTOK * DIMV;
    dim3 ts_blk(32, 8);

    // ---- transpose-split all weights ----
    tsplit_kernel<<<dim3(768/32, 768/32), ts_blk>>>(vr_W, wthi, wtlo, 768, 768);
    for (int i = 0; i < 8; i++) {
        size_t lb = SZ_SQ + (size_t)i * SZ_LAYER;
        tsplit_kernel<<<dim3(768/32, 768/32), ts_blk>>>(Wq + (long)i*SZ_SQ,  wthi + lb,           wtlo + lb,           768, 768);
        tsplit_kernel<<<dim3(768/32, 768/32), ts_blk>>>(Wk + (long)i*SZ_SQ,  wthi + lb + SZ_SQ,   wtlo + lb + SZ_SQ,   768, 768);
        tsplit_kernel<<<dim3(768/32, 768/32), ts_blk>>>(Wv + (long)i*SZ_SQ,  wthi + lb + 2*SZ_SQ, wtlo + lb + 2*SZ_SQ, 768, 768);
        tsplit_kernel<<<dim3(768/32, 768/32), ts_blk>>>(Wo + (long)i*SZ_SQ,  wthi + lb + 3*SZ_SQ, wtlo + lb + 3*SZ_SQ, 768, 768);
        tsplit_kernel<<<dim3(4096/32, 768/32), ts_blk>>>(Win + (long)i*SZ_WIN, wthi + lb + 4*SZ_SQ, wtlo + lb + 4*SZ_SQ, 768, 4096);
        tsplit_kernel<<<dim3(768/32, 2048/32), ts_blk>>>(Wout + (long)i*SZ_WOUT, wthi + lb + 4*SZ_SQ + SZ_WIN, wtlo + lb + 4*SZ_SQ + SZ_WIN, 2048, 768);
    }

    copy_kernel<<<(NTOT + 255) / 256, 256>>>(tokens, x, NTOT);

    // value residual: rv = rmsnorm(tokens) @ vr_W
    rmsnorm_kernel<<<NTOK, 256>>>(x, vr_norm_w, tn);
    split_kernel<<<(NTOT + 255) / 256, 256>>>(tn, ahi, alo, NTOT);
    gemm_bf16<<<dim3(6, 128), 256, GEMM_SMEM>>>(ahi, alo, wthi, wtlo, nullptr, rv, DIMV, DIMV, 0);

    for (int i = 0; i < 8; i++) {
        size_t lb = SZ_SQ + (size_t)i * SZ_LAYER;
        const __nv_bfloat16* wtq = wthi + lb;
        const __nv_bfloat16* wtq_l = wtlo + lb;
        const float* aw   = attn_norm_w + (long)i * DIMV;
        const float* wg   = Wg   + (long)i * DIMV * HEADS;
        const float* wmix = Wmix + (long)i * DIMV * HEADS;
        const float* bm   = bmix + (long)i * HEADS;
        const float* kg   = kgam + (long)i * HEADS * DH;
        const float* fw   = ff_norm_w + (long)i * DIMV;
        const float* bi   = bi_in + (long)i * (2 * DFF);
        const float* bo   = b_out + (long)i * DIMV;
        bool is_time = ((i + 1) % 4 == 0);

        // attention block
        rmsnorm_kernel<<<NTOK, 256>>>(x, aw, tn);
        split_kernel<<<(NTOT + 255) / 256, 256>>>(tn, ahi, alo, NTOT);
        gemm_bf16<<<dim3(6, 128), 256, GEMM_SMEM>>>(ahi, alo, wtq,            wtq_l,            nullptr, q, DIMV, DIMV, 0);
        gemm_bf16<<<dim3(6, 128), 256, GEMM_SMEM>>>(ahi, alo, wtq + SZ_SQ,    wtq_l + SZ_SQ,    nullptr, k, DIMV, DIMV, 0);
        gemm_bf16<<<dim3(6, 128), 256, GEMM_SMEM>>>(ahi, alo, wtq + 2*SZ_SQ,  wtq_l + 2*SZ_SQ,  nullptr, v, DIMV, DIMV, 0);
        mixgate_kernel<<<NTOK, 32>>>(tn, wmix, bm, wg, mix, gate);
        vlerp_kernel<<<(NTOT + 255) / 256, 256>>>(v, rv, mix);
        knorm_kernel<<<NTOK, dim3(32, HEADS)>>>(k, kg);
        if (is_time) {
            rotary_kernel<<<(NTOK * HEADS * 32 + 255) / 256, 256>>>(q, k);
            attn_time<<<dim3(NTOK / TT, HEADS), 32>>>(q, k, v, gate, o);
        } else {
            attn_space<<<dim3(NTOK / SS, HEADS), 256, ASP_SMEM>>>(q, k, v, gate, o);
        }
        split_kernel<<<(NTOT + 255) / 256, 256>>>(o, ahi, alo, NTOT);
        gemm_bf16<<<dim3(6, 128), 256, GEMM_SMEM>>>(ahi, alo, wtq + 3*SZ_SQ, wtq_l + 3*SZ_SQ, nullptr, x, DIMV, DIMV, 1);

        // feed-forward block
        rmsnorm_kernel<<<NTOK, 256>>>(x, fw, tn);
        split_kernel<<<(NTOT + 255) / 256, 256>>>(tn, ahi, alo, NTOT);
        gemm_bf16<<<dim3(32, 128), 256, GEMM_SMEM>>>(ahi, alo, wtq + 4*SZ_SQ, wtq_l + 4*SZ_SQ, bi, h, 2 * DFF, DIMV, 0);
        act_kernel<<<(NTOK * DFF + 255) / 256, 256>>>(h, act);
        split_kernel<<<(NTOK * DFF + 255) / 256, 256>>>(act, ahi, alo, NTOK * DFF);
        gemm_bf16<<<dim3(6, 128), 256, GEMM_SMEM>>>(ahi, alo, wtq + 4*SZ_SQ + SZ_WIN, wtq_l + 4*SZ_SQ + SZ_WIN, bo, x, DIMV, DFF, 1);
    }

    rmsnorm_kernel<<<NTOK, 256>>>(x, final_norm_w, (float*)d_out);
}

// round 8
// speedup vs baseline: 5.1149x; 1.1026x over previous
#include <cuda_runtime.h>
#include <cuda_bf16.h>
#include <math.h>
#include <stdint.h>

#define NTOK 16384   // B*T*S = 2*32*256
#define DIMV 768
#define HEADS 12
#define DH 64
#define DFF 2048
#define TT 32
#define SS 256
#define QKVW 2304    // fused qkv row width

// weight sizes
#define SZ_SQ   (768*768)
#define SZ_WIN  (768*4096)
#define SZ_WOUT (2048*768)
#define SZ_LAYER (4*SZ_SQ + SZ_WIN + SZ_WOUT)
#define SZ_WTOT (SZ_SQ + 8*SZ_LAYER)

// ---------------- scratch ----------------
__device__ float g_x[NTOK * DIMV];
__device__ float g_tn[NTOK * DIMV];
__device__ float g_qkv[NTOK * QKVW];
__device__ float g_rv[NTOK * DIMV];
__device__ float g_h[NTOK * 2 * DFF];
__device__ float g_gate[NTOK * HEADS];
__device__ __nv_bfloat16 g_wthi[SZ_WTOT];
__device__ __nv_bfloat16 g_wtlo[SZ_WTOT];
__device__ __nv_bfloat16 g_ahi[NTOK * DFF];
__device__ __nv_bfloat16 g_alo[NTOK * DFF];

// ==================== weight transpose + split ====================
__global__ void tsplit_kernel(const float* __restrict__ W,
                              __nv_bfloat16* __restrict__ hi, __nv_bfloat16* __restrict__ lo,
                              int K, int N) {
    __shared__ float tile[32][33];
    int bn = blockIdx.x * 32, bk = blockIdx.y * 32;
    int tx = threadIdx.x, ty = threadIdx.y;
    #pragma unroll
    for (int i = ty; i < 32; i += 8)
        tile[i][tx] = W[(long)(bk + i) * N + bn + tx];
    __syncthreads();
    #pragma unroll
    for (int i = ty; i < 32; i += 8) {
        float x = tile[tx][i];
        __nv_bfloat16 h = __float2bfloat16(x);
        long out = (long)(bn + i) * K + bk + tx;
        hi[out] = h;
        lo[out] = __float2bfloat16(x - __bfloat162float(h));
    }
}

// ==================== bf16 HMMA GEMM (ldmatrix + cp.async double-buffer) ====================
#define CH_BYTES 10240
#define BUF_BYTES (4 * CH_BYTES)
#define GEMM_SMEM (2 * BUF_BYTES)

__device__ __forceinline__ uint32_t smem_u32(const void* p) {
    uint32_t a;
    asm("{ .reg .u64 t; cvta.to.shared.u64 t, %1; cvt.u32.u64 %0, t; }" : "=r"(a) : "l"(p));
    return a;
}
__device__ __forceinline__ void cp16(uint32_t dst, const void* src) {
    asm volatile("cp.async.ca.shared.global [%0], [%1], 16;" :: "r"(dst), "l"(src));
}
__device__ __forceinline__ void cp_commit() { asm volatile("cp.async.commit_group;"); }
__device__ __forceinline__ void cp_wait1() { asm volatile("cp.async.wait_group 1;"); }
__device__ __forceinline__ void cp_wait0() { asm volatile("cp.async.wait_group 0;"); }

__device__ __forceinline__ void mma_bf16(float* d, const uint32_t* a, const uint32_t* b) {
    asm volatile(
        "mma.sync.aligned.m16n8k16.row.col.f32.bf16.bf16.f32 "
        "{%0,%1,%2,%3}, {%4,%5,%6,%7}, {%8,%9}, {%0,%1,%2,%3};"
        : "+f"(d[0]), "+f"(d[1]), "+f"(d[2]), "+f"(d[3])
        : "r"(a[0]), "r"(a[1]), "r"(a[2]), "r"(a[3]), "r"(b[0]), "r"(b[1]));
}
__device__ __forceinline__ void ldsm4(uint32_t addr, uint32_t* d) {
    asm volatile("ldmatrix.sync.aligned.m8n8.x4.shared.b16 {%0,%1,%2,%3}, [%4];"
                 : "=r"(d[0]), "=r"(d[1]), "=r"(d[2]), "=r"(d[3]) : "r"(addr));
}

__global__ __launch_bounds__(256) void gemm_bf16(
    const __nv_bfloat16* __restrict__ Ah, const __nv_bfloat16* __restrict__ Al,
    const __nv_bfloat16* __restrict__ Bh, const __nv_bfloat16* __restrict__ Bl,
    const float* __restrict__ bias, float* __restrict__ C,
    int N, int K, int accumulate)
{
    extern __shared__ char smem[];
    uint32_t sb = smem_u32(smem);
    int tid = threadIdx.x, wid = tid >> 5, lane = tid & 31;
    int m0 = blockIdx.y * 128, n0 = blockIdx.x * 128;
    int wm = (wid & 1) * 64, wn = (wid >> 1) * 32;
    int g = lane >> 2, tig = lane & 3;
    int mi = lane >> 3, r8 = lane & 7;
    uint32_t offA = (uint32_t)(((mi & 1) * 8 + r8) * 80 + (mi >> 1) * 16);
    uint32_t offB = (uint32_t)(((mi >> 1) * 8 + r8) * 80 + (mi & 1) * 16);

    float acc[4][4][4];
    #pragma unroll
    for (int mt = 0; mt < 4; mt++)
        #pragma unroll
        for (int nt = 0; nt < 4; nt++)
            #pragma unroll
            for (int e = 0; e < 4; e++) acc[mt][nt][e] = 0.f;

    int nchunks = K >> 5;
    int r0 = tid >> 2, s0 = (tid & 3) * 8;
    int r1 = (tid + 256) >> 2, s1 = s0;

    #define LOADCHUNK(b, kc_) do {                                                     \
        uint32_t base = sb + (b) * BUF_BYTES;                                          \
        cp16(base + r0 * 80 + (s0 << 1),                 Ah + (long)(m0 + r0) * K + (kc_) + s0); \
        cp16(base + CH_BYTES + r0 * 80 + (s0 << 1),      Al + (long)(m0 + r0) * K + (kc_) + s0); \
        cp16(base + 2 * CH_BYTES + r0 * 80 + (s0 << 1),  Bh + (long)(n0 + r0) * K + (kc_) + s0); \
        cp16(base + 3 * CH_BYTES + r0 * 80 + (s0 << 1),  Bl + (long)(n0 + r0) * K + (kc_) + s0); \
        cp16(base + r1 * 80 + (s1 << 1),                 Ah + (long)(m0 + r1) * K + (kc_) + s1); \
        cp16(base + CH_BYTES + r1 * 80 + (s1 << 1),      Al + (long)(m0 + r1) * K + (kc_) + s1); \
        cp16(base + 2 * CH_BYTES + r1 * 80 + (s1 << 1),  Bh + (long)(n0 + r1) * K + (kc_) + s1); \
        cp16(base + 3 * CH_BYTES + r1 * 80 + (s1 << 1),  Bl + (long)(n0 + r1) * K + (kc_) + s1); \
    } while (0)

    LOADCHUNK(0, 0);
    cp_commit();

    for (int c = 0; c < nchunks; c++) {
        if (c + 1 < nchunks) {
            LOADCHUNK((c + 1) & 1, (c + 1) << 5);
            cp_commit();
            cp_wait1();
        } else {
            cp_wait0();
        }
        __syncthreads();

        uint32_t bufAh = sb + (c & 1) * BUF_BYTES;
        uint32_t bufAl = bufAh + CH_BYTES;
        uint32_t bufBh = bufAh + 2 * CH_BYTES;
        uint32_t bufBl = bufAh + 3 * CH_BYTES;

        #pragma unroll
        for (int ks = 0; ks < 32; ks += 16) {
            uint32_t kb = (uint32_t)(ks * 2);
            uint32_t bh[8], bl[8];
            ldsm4(bufBh + (uint32_t)(wn) * 80 + kb + offB, bh);
            ldsm4(bufBh + (uint32_t)(wn + 16) * 80 + kb + offB, bh + 4);
            ldsm4(bufBl + (uint32_t)(wn) * 80 + kb + offB, bl);
            ldsm4(bufBl + (uint32_t)(wn + 16) * 80 + kb + offB, bl + 4);
            #pragma unroll
            for (int mt = 0; mt < 4; mt++) {
                uint32_t ah[4], al[4];
                ldsm4(bufAh + (uint32_t)(wm + mt * 16) * 80 + kb + offA, ah);
                ldsm4(bufAl + (uint32_t)(wm + mt * 16) * 80 + kb + offA, al);
                #pragma unroll
                for (int nt = 0; nt < 4; nt++) {
                    mma_bf16(acc[mt][nt], ah, bh + nt * 2);
                    mma_bf16(acc[mt][nt], ah, bl + nt * 2);
                    mma_bf16(acc[mt][nt], al, bh + nt * 2);
                }
            }
        }
        __syncthreads();
    }

    #pragma unroll
    for (int mt = 0; mt < 4; mt++) {
        long r = m0 + wm + mt * 16 + g;
        #pragma unroll
        for (int nt = 0; nt < 4; nt++) {
            int c = n0 + wn + nt * 8 + tig * 2;
            float v0 = acc[mt][nt][0], v1 = acc[mt][nt][1];
            float v2 = acc[mt][nt][2], v3 = acc[mt][nt][3];
            if (bias) { v0 += bias[c]; v1 += bias[c + 1]; v2 += bias[c]; v3 += bias[c + 1]; }
            if (accumulate) {
                C[r * N + c]           += v0;
                C[r * N + c + 1]       += v1;
                C[(r + 8) * N + c]     += v2;
                C[(r + 8) * N + c + 1] += v3;
            } else {
                C[r * N + c]           = v0;
                C[r * N + c + 1]       = v1;
                C[(r + 8) * N + c]     = v2;
                C[(r + 8) * N + c + 1] = v3;
            }
        }
    }
}

// ---------------- elementwise ----------------
__global__ void copy_kernel(const float* __restrict__ src, float* __restrict__ dst, int n) {
    int i = blockIdx.x * blockDim.x + threadIdx.x;
    if (i < n) dst[i] = src[i];
}

// rmsnorm + bf16 split (fp32 out optional; hi/lo optional)
__global__ void rmsnorm_split(const float* __restrict__ x, const float* __restrict__ w,
                              float* __restrict__ outf,
                              __nv_bfloat16* __restrict__ hi, __nv_bfloat16* __restrict__ lo) {
    int tok = blockIdx.x;
    int tid = threadIdx.x;
    const float* xr = x + (long)tok * DIMV;
    float v0 = xr[tid], v1 = xr[tid + 256], v2 = xr[tid + 512];
    __shared__ float red[256];
    red[tid] = v0 * v0 + v1 * v1 + v2 * v2;
    __syncthreads();
    for (int off = 128; off > 0; off >>= 1) {
        if (tid < off) red[tid] += red[tid + off];
        __syncthreads();
    }
    float inv = rsqrtf(red[0] / (float)DIMV + 1e-6f);
    float r0 = v0 * inv * w[tid];
    float r1 = v1 * inv * w[tid + 256];
    float r2 = v2 * inv * w[tid + 512];
    long base = (long)tok * DIMV;
    if (outf) { outf[base + tid] = r0; outf[base + tid + 256] = r1; outf[base + tid + 512] = r2; }
    if (hi) {
        __nv_bfloat16 h0 = __float2bfloat16(r0), h1 = __float2bfloat16(r1), h2 = __float2bfloat16(r2);
        hi[base + tid] = h0; hi[base + tid + 256] = h1; hi[base + tid + 512] = h2;
        lo[base + tid]       = __float2bfloat16(r0 - __bfloat162float(h0));
        lo[base + tid + 256] = __float2bfloat16(r1 - __bfloat162float(h1));
        lo[base + tid + 512] = __float2bfloat16(r2 - __bfloat162float(h2));
    }
}

// ---------------- fused qkv post-processing ----------------
// one block per token, 12 warps (one per head):
// mix/gate projections, v value-residual lerp, k l2norm, optional rotary
__global__ __launch_bounds__(384) void qkv_post(
    float* __restrict__ qkv, const float* __restrict__ rv, const float* __restrict__ tn,
    const float* __restrict__ Wmix, const float* __restrict__ bmix,
    const float* __restrict__ Wg, const float* __restrict__ kgam,
    float* __restrict__ gate, int isTime)
{
    int tok = blockIdx.x;
    int wid = threadIdx.x >> 5, lane = threadIdx.x & 31;
    int h = wid;
    const float* trow = tn + (long)tok * DIMV;

    float am = 0.f, ag = 0.f;
    #pragma unroll
    for (int e = 0; e < 24; e++) {
        int d = lane + 32 * e;
        float t = trow[d];
        am += t * Wmix[d * HEADS + h];
        ag += t * Wg[d * HEADS + h];
    }
    #pragma unroll
    for (int off = 16; off > 0; off >>= 1) {
        am += __shfl_xor_sync(0xffffffffu, am, off);
        ag += __shfl_xor_sync(0xffffffffu, ag, off);
    }
    float mix = 1.f / (1.f + __expf(-(am + bmix[h])));
    if (lane == 0) gate[tok * HEADS + h] = 1.f / (1.f + __expf(-ag));

    long base = (long)tok * QKVW;
    // v lerp
    float* vp = qkv + base + 1536 + h * DH;
    const float* rvp = rv + (long)tok * DIMV + h * DH;
    float va = vp[lane], vb = vp[lane + 32];
    vp[lane]      = va + mix * (rvp[lane] - va);
    vp[lane + 32] = vb + mix * (rvp[lane + 32] - vb);
    // k norm
    float* kp = qkv + base + 768 + h * DH;
    float ka = kp[lane], kb = kp[lane + 32];
    float ss = ka * ka + kb * kb;
    #pragma unroll
    for (int off = 16; off > 0; off >>= 1) ss += __shfl_xor_sync(0xffffffffu, ss, off);
    float inv = 1.f / fmaxf(sqrtf(ss), 1e-12f);
    ka = ka * inv * (kgam[h * DH + lane] + 1.f) * 8.0f;
    kb = kb * inv * (kgam[h * DH + lane + 32] + 1.f) * 8.0f;
    if (isTime) {
        int t = (tok / SS) % TT;
        float invf = __powf(10000.0f, -(float)(2 * lane) / (float)DH);
        float ang = (float)t * invf;
        float cc = cosf(ang), sn = sinf(ang);
        float* qp = qkv + base + h * DH;
        float qa = qp[lane], qb = qp[lane + 32];
        qp[lane]      = qa * cc - qb * sn;
        qp[lane + 32] = qb * cc + qa * sn;
        float k1 = ka * cc - kb * sn;
        float k2 = kb * cc + ka * sn;
        ka = k1; kb = k2;
    }
    kp[lane] = ka; kp[lane + 32] = kb;
}

__device__ __forceinline__ float softclamp(float acc) {
    // 50*tanh(acc/400)  where acc is raw dot (scale 1/8 and 1/50 folded)
    float t = __expf(acc * 0.005f);
    return 50.f * __fdividef(t - 1.f, t + 1.f);
}

// ---------------- space attention ----------------
#define ASP_SMEM (2 * SS * DH * 4)
__global__ __launch_bounds__(256, 1) void attn_space(
    const float* __restrict__ qkv, const float* __restrict__ gate,
    __nv_bfloat16* __restrict__ ohi, __nv_bfloat16* __restrict__ olo)
{
    int r = blockIdx.x, h = blockIdx.y;
    long base = (long)r * SS;
    extern __shared__ float sm[];
    float* Ks = sm;
    float* Vs = sm + SS * DH;
    int tid = threadIdx.x;
    for (int idx = tid; idx < SS * DH; idx += 256) {
        int j = idx >> 6, d = idx & 63;
        long tb = (base + j) * QKVW + h * DH + d;
        Ks[idx] = qkv[tb + 768];
        Vs[idx] = qkv[tb + 1536];
    }
    __syncthreads();

    long mytok = base + tid;
    float4 qr[16];
    const float4* qp = (const float4*)(qkv + mytok * QKVW + h * DH);
    #pragma unroll
    for (int e = 0; e < 16; e++) qr[e] = qp[e];

    float m = -3.0e38f, s = 0.f;
    for (int j = 0; j < SS; j++) {
        const float4* kp = (const float4*)(Ks + j * DH);
        float acc = 0.f;
        #pragma unroll
        for (int e = 0; e < 16; e++) {
            float4 kv = kp[e];
            acc += qr[e].x * kv.x + qr[e].y * kv.y + qr[e].z * kv.z + qr[e].w * kv.w;
        }
        acc = softclamp(acc);
        float mn = fmaxf(m, acc);
        s = s * __expf(m - mn) + __expf(acc - mn);
        m = mn;
    }
    float inv = 1.f / s;

    float4 oa[16];
    #pragma unroll
    for (int e = 0; e < 16; e++) oa[e] = make_float4(0.f, 0.f, 0.f, 0.f);
    for (int j = 0; j < SS; j++) {
        const float4* kp = (const float4*)(Ks + j * DH);
        float acc = 0.f;
        #pragma unroll
        for (int e = 0; e < 16; e++) {
            float4 kv = kp[e];
            acc += qr[e].x * kv.x + qr[e].y * kv.y + qr[e].z * kv.z + qr[e].w * kv.w;
        }
        float p = __expf(softclamp(acc) - m) * inv;
        const float4* vp = (const float4*)(Vs + j * DH);
        #pragma unroll
        for (int e = 0; e < 16; e++) {
            float4 vv = vp[e];
            oa[e].x += p * vv.x; oa[e].y += p * vv.y;
            oa[e].z += p * vv.z; oa[e].w += p * vv.w;
        }
    }
    float gg = gate[mytok * HEADS + h];
    long ob = mytok * DIMV + h * DH;
    #pragma unroll
    for (int e = 0; e < 16; e++) {
        float vals[4] = {oa[e].x * gg, oa[e].y * gg, oa[e].z * gg, oa[e].w * gg};
        #pragma unroll
        for (int u = 0; u < 4; u++) {
            __nv_bfloat16 hh = __float2bfloat16(vals[u]);
            ohi[ob + e * 4 + u] = hh;
            olo[ob + e * 4 + u] = __float2bfloat16(vals[u] - __bfloat162float(hh));
        }
    }
}

// ---------------- time attention (causal) ----------------
__global__ __launch_bounds__(32) void attn_time(
    const float* __restrict__ qkv, const float* __restrict__ gate,
    __nv_bfloat16* __restrict__ ohi, __nv_bfloat16* __restrict__ olo)
{
    int r = blockIdx.x, h = blockIdx.y;
    int b = r / SS, s0 = r % SS;
    long base = (long)b * (TT * SS) + s0;
    __shared__ float Ks[TT * DH], Vs[TT * DH];
    int tid = threadIdx.x;
    for (int idx = tid; idx < TT * DH; idx += 32) {
        int j = idx >> 6, d = idx & 63;
        long tb = (base + (long)j * SS) * QKVW + h * DH + d;
        Ks[idx] = qkv[tb + 768];
        Vs[idx] = qkv[tb + 1536];
    }
    __syncwarp();

    long mytok = base + (long)tid * SS;
    float4 qr[16];
    const float4* qp = (const float4*)(qkv + mytok * QKVW + h * DH);
    #pragma unroll
    for (int e = 0; e < 16; e++) qr[e] = qp[e];

    int nkeys = tid + 1;
    float m = -3.0e38f, s = 0.f;
    for (int j = 0; j < nkeys; j++) {
        const float4* kp = (const float4*)(Ks + j * DH);
        float acc = 0.f;
        #pragma unroll
        for (int e = 0; e < 16; e++) {
            float4 kv = kp[e];
            acc += qr[e].x * kv.x + qr[e].y * kv.y + qr[e].z * kv.z + qr[e].w * kv.w;
        }
        acc = softclamp(acc);
        float mn = fmaxf(m, acc);
        s = s * __expf(m - mn) + __expf(acc - mn);
        m = mn;
    }
    float inv = 1.f / s;

    float4 oa[16];
    #pragma unroll
    for (int e = 0; e < 16; e++) oa[e] = make_float4(0.f, 0.f, 0.f, 0.f);
    for (int j = 0; j < nkeys; j++) {
        const float4* kp = (const float4*)(Ks + j * DH);
        float acc = 0.f;
        #pragma unroll
        for (int e = 0; e < 16; e++) {
            float4 kv = kp[e];
            acc += qr[e].x * kv.x + qr[e].y * kv.y + qr[e].z * kv.z + qr[e].w * kv.w;
        }
        float p = __expf(softclamp(acc) - m) * inv;
        const float4* vp = (const float4*)(Vs + j * DH);
        #pragma unroll
        for (int e = 0; e < 16; e++) {
            float4 vv = vp[e];
            oa[e].x += p * vv.x; oa[e].y += p * vv.y;
            oa[e].z += p * vv.z; oa[e].w += p * vv.w;
        }
    }
    float gg = gate[mytok * HEADS + h];
    long ob = mytok * DIMV + h * DH;
    #pragma unroll
    for (int e = 0; e < 16; e++) {
        float vals[4] = {oa[e].x * gg, oa[e].y * gg, oa[e].z * gg, oa[e].w * gg};
        #pragma unroll
        for (int u = 0; u < 4; u++) {
            __nv_bfloat16 hh = __float2bfloat16(vals[u]);
            ohi[ob + e * 4 + u] = hh;
            olo[ob + e * 4 + u] = __float2bfloat16(vals[u] - __bfloat162float(hh));
        }
    }
}

// ---------------- a * gelu(g) -> bf16 split ----------------
__global__ void act_split(const float* __restrict__ h,
                          __nv_bfloat16* __restrict__ hi, __nv_bfloat16* __restrict__ lo) {
    int idx = blockIdx.x * blockDim.x + threadIdx.x;
    if (idx >= NTOK * DFF) return;
    int tok = idx / DFF;
    int c = idx % DFF;
    float a = h[(long)tok * (2 * DFF) + c];
    float g = h[(long)tok * (2 * DFF) + DFF + c];
    float r = a * 0.5f * g * (1.f + erff(g * 0.70710678118654752f));
    __nv_bfloat16 hh = __float2bfloat16(r);
    hi[idx] = hh;
    lo[idx] = __float2bfloat16(r - __bfloat162float(hh));
}

// ---------------- launch ----------------
extern "C" void kernel_launch(void* const* d_in, const int* in_sizes, int n_in,
                              void* d_out, int out_size) {
    const float* tokens      = (const float*)d_in[0];
    const float* attn_norm_w = (const float*)d_in[1];
    const float* Wq          = (const float*)d_in[2];
    const float* Wk          = (const float*)d_in[3];
    const float* Wv          = (const float*)d_in[4];
    const float* Wo          = (const float*)d_in[5];
    const float* Wg          = (const float*)d_in[6];
    const float* Wmix        = (const float*)d_in[7];
    const float* bmix        = (const float*)d_in[8];
    const float* kgam        = (const float*)d_in[9];
    const float* ff_norm_w   = (const float*)d_in[10];
    const float* Win         = (const float*)d_in[11];
    const float* bi_in       = (const float*)d_in[12];
    const float* Wout        = (const float*)d_in[13];
    const float* b_out       = (const float*)d_in[14];
    const float* vr_norm_w   = (const float*)d_in[15];
    const float* vr_W        = (const float*)d_in[16];
    const float* final_norm_w= (const float*)d_in[17];

    float *x, *tn, *qkv, *rv, *h, *gate;
    __nv_bfloat16 *wthi, *wtlo, *ahi, *alo;
    cudaGetSymbolAddress((void**)&x,   g_x);
    cudaGetSymbolAddress((void**)&tn,  g_tn);
    cudaGetSymbolAddress((void**)&qkv, g_qkv);
    cudaGetSymbolAddress((void**)&rv,  g_rv);
    cudaGetSymbolAddress((void**)&h,   g_h);
    cudaGetSymbolAddress((void**)&gate,g_gate);
    cudaGetSymbolAddress((void**)&wthi,g_wthi);
    cudaGetSymbolAddress((void**)&wtlo,g_wtlo);
    cudaGetSymbolAddress((void**)&ahi, g_ahi);
    cudaGetSymbolAddress((void**)&alo, g_alo);

    static int attr_done = 0;
    if (!attr_done) {
        cudaFuncSetAttribute(gemm_bf16, cudaFuncAttributeMaxDynamicSharedMemorySize, GEMM_SMEM);
        cudaFuncSetAttribute(attn_space, cudaFuncAttributeMaxDynamicSharedMemorySize, ASP_SMEM);
        attr_done = 1;
    }

    const int NTOT = NTOK * DIMV;
    dim3 ts_blk(32, 8);

    // ---- transpose-split all weights ----
    tsplit_kernel<<<dim3(768/32, 768/32), ts_blk>>>(vr_W, wthi, wtlo, 768, 768);
    for (int i = 0; i < 8; i++) {
        size_t lb = SZ_SQ + (size_t)i * SZ_LAYER;
        tsplit_kernel<<<dim3(768/32, 768/32), ts_blk>>>(Wq + (long)i*SZ_SQ,  wthi + lb,           wtlo + lb,           768, 768);
        tsplit_kernel<<<dim3(768/32, 768/32), ts_blk>>>(Wk + (long)i*SZ_SQ,  wthi + lb + SZ_SQ,   wtlo + lb + SZ_SQ,   768, 768);
        tsplit_kernel<<<dim3(768/32, 768/32), ts_blk>>>(Wv + (long)i*SZ_SQ,  wthi + lb + 2*SZ_SQ, wtlo + lb + 2*SZ_SQ, 768, 768);
        tsplit_kernel<<<dim3(768/32, 768/32), ts_blk>>>(Wo + (long)i*SZ_SQ,  wthi + lb + 3*SZ_SQ, wtlo + lb + 3*SZ_SQ, 768, 768);
        tsplit_kernel<<<dim3(4096/32, 768/32), ts_blk>>>(Win + (long)i*SZ_WIN, wthi + lb + 4*SZ_SQ, wtlo + lb + 4*SZ_SQ, 768, 4096);
        tsplit_kernel<<<dim3(768/32, 2048/32), ts_blk>>>(Wout + (long)i*SZ_WOUT, wthi + lb + 4*SZ_SQ + SZ_WIN, wtlo + lb + 4*SZ_SQ + SZ_WIN, 2048, 768);
    }

    copy_kernel<<<(NTOT + 255) / 256, 256>>>(tokens, x, NTOT);

    // value residual: rv = rmsnorm(tokens) @ vr_W
    rmsnorm_split<<<NTOK, 256>>>(tokens, vr_norm_w, nullptr, ahi, alo);
    gemm_bf16<<<dim3(6, 128), 256, GEMM_SMEM>>>(ahi, alo, wthi, wtlo, nullptr, rv, DIMV, DIMV, 0);

    for (int i = 0; i < 8; i++) {
        size_t lb = SZ_SQ + (size_t)i * SZ_LAYER;
        const __nv_bfloat16* wh = wthi + lb;
        const __nv_bfloat16* wl = wtlo + lb;
        const float* aw   = attn_norm_w + (long)i * DIMV;
        const float* wg   = Wg   + (long)i * DIMV * HEADS;
        const float* wmix = Wmix + (long)i * DIMV * HEADS;
        const float* bm   = bmix + (long)i * HEADS;
        const float* kg   = kgam + (long)i * HEADS * DH;
        const float* fw   = ff_norm_w + (long)i * DIMV;
        const float* bi   = bi_in + (long)i * (2 * DFF);
        const float* bo   = b_out + (long)i * DIMV;
        int is_time = ((i + 1) % 4 == 0) ? 1 : 0;

        // attention block
        rmsnorm_split<<<NTOK, 256>>>(x, aw, tn, ahi, alo);
        gemm_bf16<<<dim3(18, 128), 256, GEMM_SMEM>>>(ahi, alo, wh, wl, nullptr, qkv, QKVW, DIMV, 0);
        qkv_post<<<NTOK, 384>>>(qkv, rv, tn, wmix, bm, wg, kg, gate, is_time);
        if (is_time) attn_time<<<dim3(NTOK / TT, HEADS), 32>>>(qkv, gate, ahi, alo);
        else         attn_space<<<dim3(NTOK / SS, HEADS), 256, ASP_SMEM>>>(qkv, gate, ahi, alo);
        gemm_bf16<<<dim3(6, 128), 256, GEMM_SMEM>>>(ahi, alo, wh + 3*SZ_SQ, wl + 3*SZ_SQ, nullptr, x, DIMV, DIMV, 1);

        // feed-forward block
        rmsnorm_split<<<NTOK, 256>>>(x, fw, nullptr, ahi, alo);
        gemm_bf16<<<dim3(32, 128), 256, GEMM_SMEM>>>(ahi, alo, wh + 4*SZ_SQ, wl + 4*SZ_SQ, bi, h, 2 * DFF, DIMV, 0);
        act_split<<<(NTOK * DFF + 255) / 256, 256>>>(h, ahi, alo);
        gemm_bf16<<<dim3(6, 128), 256, GEMM_SMEM>>>(ahi, alo, wh + 4*SZ_SQ + SZ_WIN, wl + 4*SZ_SQ + SZ_WIN, bo, x, DIMV, DFF, 1);
    }

    rmsnorm_split<<<NTOK, 256>>>(x, final_norm_w, (float*)d_out, nullptr, nullptr);
}

// round 9
// speedup vs baseline: 5.4674x; 1.0689x over previous
#include <cuda_runtime.h>
#include <cuda_bf16.h>
#include <math.h>
#include <stdint.h>

#define NTOK 16384   // B*T*S = 2*32*256
#define DIMV 768
#define HEADS 12
#define DH 64
#define DFF 2048
#define TT 32
#define SS 256
#define QKVW 2304    // fused qkv row width

// weight sizes
#define SZ_SQ   (768*768)
#define SZ_WIN  (768*4096)
#define SZ_WOUT (2048*768)
#define SZ_LAYER (4*SZ_SQ + SZ_WIN + SZ_WOUT)
#define SZ_WTOT (SZ_SQ + 8*SZ_LAYER)

// ---------------- scratch ----------------
__device__ float g_x[NTOK * DIMV];
__device__ float g_tn[NTOK * DIMV];
__device__ float g_qkv[NTOK * QKVW];
__device__ float g_rv[NTOK * DIMV];
__device__ float g_h[NTOK * 2 * DFF];
__device__ float g_mix[NTOK * HEADS];
__device__ float g_gate[NTOK * HEADS];
__device__ __nv_bfloat16 g_wthi[SZ_WTOT];
__device__ __nv_bfloat16 g_wtlo[SZ_WTOT];
__device__ __nv_bfloat16 g_ahi[NTOK * DFF];
__device__ __nv_bfloat16 g_alo[NTOK * DFF];

// ==================== weight transpose + split ====================
__global__ void tsplit_kernel(const float* __restrict__ W,
                              __nv_bfloat16* __restrict__ hi, __nv_bfloat16* __restrict__ lo,
                              int K, int N) {
    __shared__ float tile[32][33];
    int bn = blockIdx.x * 32, bk = blockIdx.y * 32;
    int tx = threadIdx.x, ty = threadIdx.y;
    #pragma unroll
    for (int i = ty; i < 32; i += 8)
        tile[i][tx] = W[(long)(bk + i) * N + bn + tx];
    __syncthreads();
    #pragma unroll
    for (int i = ty; i < 32; i += 8) {
        float x = tile[tx][i];
        __nv_bfloat16 h = __float2bfloat16(x);
        long out = (long)(bn + i) * K + bk + tx;
        hi[out] = h;
        lo[out] = __float2bfloat16(x - __bfloat162float(h));
    }
}

// ==================== bf16 HMMA GEMM (ldmatrix + cp.async double-buffer) ====================
#define CH_BYTES 10240
#define BUF_BYTES (4 * CH_BYTES)
#define GEMM_SMEM (2 * BUF_BYTES)

__device__ __forceinline__ uint32_t smem_u32(const void* p) {
    uint32_t a;
    asm("{ .reg .u64 t; cvta.to.shared.u64 t, %1; cvt.u32.u64 %0, t; }" : "=r"(a) : "l"(p));
    return a;
}
__device__ __forceinline__ void cp16(uint32_t dst, const void* src) {
    asm volatile("cp.async.ca.shared.global [%0], [%1], 16;" :: "r"(dst), "l"(src));
}
__device__ __forceinline__ void cp_commit() { asm volatile("cp.async.commit_group;"); }
__device__ __forceinline__ void cp_wait1() { asm volatile("cp.async.wait_group 1;"); }
__device__ __forceinline__ void cp_wait0() { asm volatile("cp.async.wait_group 0;"); }

__device__ __forceinline__ void mma_bf16(float* d, const uint32_t* a, const uint32_t* b) {
    asm volatile(
        "mma.sync.aligned.m16n8k16.row.col.f32.bf16.bf16.f32 "
        "{%0,%1,%2,%3}, {%4,%5,%6,%7}, {%8,%9}, {%0,%1,%2,%3};"
        : "+f"(d[0]), "+f"(d[1]), "+f"(d[2]), "+f"(d[3])
        : "r"(a[0]), "r"(a[1]), "r"(a[2]), "r"(a[3]), "r"(b[0]), "r"(b[1]));
}
__device__ __forceinline__ void ldsm4(uint32_t addr, uint32_t* d) {
    asm volatile("ldmatrix.sync.aligned.m8n8.x4.shared.b16 {%0,%1,%2,%3}, [%4];"
                 : "=r"(d[0]), "=r"(d[1]), "=r"(d[2]), "=r"(d[3]) : "r"(addr));
}

__global__ __launch_bounds__(256) void gemm_bf16(
    const __nv_bfloat16* __restrict__ Ah, const __nv_bfloat16* __restrict__ Al,
    const __nv_bfloat16* __restrict__ Bh, const __nv_bfloat16* __restrict__ Bl,
    const float* __restrict__ bias, float* __restrict__ C,
    int N, int K, int accumulate)
{
    extern __shared__ char smem[];
    uint32_t sb = smem_u32(smem);
    int tid = threadIdx.x, wid = tid >> 5, lane = tid & 31;
    int m0 = blockIdx.y * 128, n0 = blockIdx.x * 128;
    int wm = (wid & 1) * 64, wn = (wid >> 1) * 32;
    int g = lane >> 2, tig = lane & 3;
    int mi = lane >> 3, r8 = lane & 7;
    uint32_t offA = (uint32_t)(((mi & 1) * 8 + r8) * 80 + (mi >> 1) * 16);
    uint32_t offB = (uint32_t)(((mi >> 1) * 8 + r8) * 80 + (mi & 1) * 16);

    float acc[4][4][4];
    #pragma unroll
    for (int mt = 0; mt < 4; mt++)
        #pragma unroll
        for (int nt = 0; nt < 4; nt++)
            #pragma unroll
            for (int e = 0; e < 4; e++) acc[mt][nt][e] = 0.f;

    int nchunks = K >> 5;
    int r0 = tid >> 2, s0 = (tid & 3) * 8;
    int r1 = (tid + 256) >> 2, s1 = s0;

    #define LOADCHUNK(b, kc_) do {                                                     \
        uint32_t base = sb + (b) * BUF_BYTES;                                          \
        cp16(base + r0 * 80 + (s0 << 1),                 Ah + (long)(m0 + r0) * K + (kc_) + s0); \
        cp16(base + CH_BYTES + r0 * 80 + (s0 << 1),      Al + (long)(m0 + r0) * K + (kc_) + s0); \
        cp16(base + 2 * CH_BYTES + r0 * 80 + (s0 << 1),  Bh + (long)(n0 + r0) * K + (kc_) + s0); \
        cp16(base + 3 * CH_BYTES + r0 * 80 + (s0 << 1),  Bl + (long)(n0 + r0) * K + (kc_) + s0); \
        cp16(base + r1 * 80 + (s1 << 1),                 Ah + (long)(m0 + r1) * K + (kc_) + s1); \
        cp16(base + CH_BYTES + r1 * 80 + (s1 << 1),      Al + (long)(m0 + r1) * K + (kc_) + s1); \
        cp16(base + 2 * CH_BYTES + r1 * 80 + (s1 << 1),  Bh + (long)(n0 + r1) * K + (kc_) + s1); \
        cp16(base + 3 * CH_BYTES + r1 * 80 + (s1 << 1),  Bl + (long)(n0 + r1) * K + (kc_) + s1); \
    } while (0)

    LOADCHUNK(0, 0);
    cp_commit();

    for (int c = 0; c < nchunks; c++) {
        if (c + 1 < nchunks) {
            LOADCHUNK((c + 1) & 1, (c + 1) << 5);
            cp_commit();
            cp_wait1();
        } else {
            cp_wait0();
        }
        __syncthreads();

        uint32_t bufAh = sb + (c & 1) * BUF_BYTES;
        uint32_t bufAl = bufAh + CH_BYTES;
        uint32_t bufBh = bufAh + 2 * CH_BYTES;
        uint32_t bufBl = bufAh + 3 * CH_BYTES;

        #pragma unroll
        for (int ks = 0; ks < 32; ks += 16) {
            uint32_t kb = (uint32_t)(ks * 2);
            uint32_t bh[8], bl[8];
            ldsm4(bufBh + (uint32_t)(wn) * 80 + kb + offB, bh);
            ldsm4(bufBh + (uint32_t)(wn + 16) * 80 + kb + offB, bh + 4);
            ldsm4(bufBl + (uint32_t)(wn) * 80 + kb + offB, bl);
            ldsm4(bufBl + (uint32_t)(wn + 16) * 80 + kb + offB, bl + 4);
            #pragma unroll
            for (int mt = 0; mt < 4; mt++) {
                uint32_t ah[4], al[4];
                ldsm4(bufAh + (uint32_t)(wm + mt * 16) * 80 + kb + offA, ah);
                ldsm4(bufAl + (uint32_t)(wm + mt * 16) * 80 + kb + offA, al);
                #pragma unroll
                for (int nt = 0; nt < 4; nt++) {
                    mma_bf16(acc[mt][nt], ah, bh + nt * 2);
                    mma_bf16(acc[mt][nt], ah, bl + nt * 2);
                    mma_bf16(acc[mt][nt], al, bh + nt * 2);
                }
            }
        }
        __syncthreads();
    }

    #pragma unroll
    for (int mt = 0; mt < 4; mt++) {
        long r = m0 + wm + mt * 16 + g;
        #pragma unroll
        for (int nt = 0; nt < 4; nt++) {
            int c = n0 + wn + nt * 8 + tig * 2;
            float v0 = acc[mt][nt][0], v1 = acc[mt][nt][1];
            float v2 = acc[mt][nt][2], v3 = acc[mt][nt][3];
            if (bias) { v0 += bias[c]; v1 += bias[c + 1]; v2 += bias[c]; v3 += bias[c + 1]; }
            if (accumulate) {
                C[r * N + c]           += v0;
                C[r * N + c + 1]       += v1;
                C[(r + 8) * N + c]     += v2;
                C[(r + 8) * N + c + 1] += v3;
            } else {
                C[r * N + c]           = v0;
                C[r * N + c + 1]       = v1;
                C[(r + 8) * N + c]     = v2;
                C[(r + 8) * N + c + 1] = v3;
            }
        }
    }
}

// ---------------- elementwise ----------------
__global__ void copy_kernel(const float* __restrict__ src, float* __restrict__ dst, int n) {
    int i = blockIdx.x * blockDim.x + threadIdx.x;
    if (i < n) dst[i] = src[i];
}

// rmsnorm + bf16 split (fp32 out optional; hi/lo optional)
__global__ void rmsnorm_split(const float* __restrict__ x, const float* __restrict__ w,
                              float* __restrict__ outf,
                              __nv_bfloat16* __restrict__ hi, __nv_bfloat16* __restrict__ lo) {
    int tok = blockIdx.x;
    int tid = threadIdx.x;
    const float* xr = x + (long)tok * DIMV;
    float v0 = xr[tid], v1 = xr[tid + 256], v2 = xr[tid + 512];
    __shared__ float red[256];
    red[tid] = v0 * v0 + v1 * v1 + v2 * v2;
    __syncthreads();
    for (int off = 128; off > 0; off >>= 1) {
        if (tid < off) red[tid] += red[tid + off];
        __syncthreads();
    }
    float inv = rsqrtf(red[0] / (float)DIMV + 1e-6f);
    float r0 = v0 * inv * w[tid];
    float r1 = v1 * inv * w[tid + 256];
    float r2 = v2 * inv * w[tid + 512];
    long base = (long)tok * DIMV;
    if (outf) { outf[base + tid] = r0; outf[base + tid + 256] = r1; outf[base + tid + 512] = r2; }
    if (hi) {
        __nv_bfloat16 h0 = __float2bfloat16(r0), h1 = __float2bfloat16(r1), h2 = __float2bfloat16(r2);
        hi[base + tid] = h0; hi[base + tid + 256] = h1; hi[base + tid + 512] = h2;
        lo[base + tid]       = __float2bfloat16(r0 - __bfloat162float(h0));
        lo[base + tid + 256] = __float2bfloat16(r1 - __bfloat162float(h1));
        lo[base + tid + 512] = __float2bfloat16(r2 - __bfloat162float(h2));
    }
}

// ---------------- mix & gate projection: one warp per token ----------------
__global__ __launch_bounds__(128) void mixgate_kernel(
    const float* __restrict__ tn,
    const float* __restrict__ Wmix, const float* __restrict__ bmix,
    const float* __restrict__ Wg,
    float* __restrict__ mix, float* __restrict__ gate)
{
    int tok = blockIdx.x * 4 + (threadIdx.x >> 5);
    int lane = threadIdx.x & 31;
    const float* x = tn + (long)tok * DIMV;
    float t[24];
    #pragma unroll
    for (int e = 0; e < 24; e++) t[e] = x[lane + 32 * e];
    for (int col = 0; col < HEADS; col++) {
        float am = 0.f, ag = 0.f;
        #pragma unroll
        for (int e = 0; e < 24; e++) {
            int d = lane + 32 * e;
            am += t[e] * Wmix[d * HEADS + col];
            ag += t[e] * Wg[d * HEADS + col];
        }
        #pragma unroll
        for (int off = 16; off > 0; off >>= 1) {
            am += __shfl_xor_sync(0xffffffffu, am, off);
            ag += __shfl_xor_sync(0xffffffffu, ag, off);
        }
        if (lane == 0) {
            mix[tok * HEADS + col]  = 1.f / (1.f + __expf(-(am + bmix[col])));
            gate[tok * HEADS + col] = 1.f / (1.f + __expf(-ag));
        }
    }
}

__device__ __forceinline__ float softclamp(float acc) {
    // 50*tanh(acc*(1/8)*(1/50))
    float t = __expf(acc * 0.005f);
    return 50.f * __fdividef(t - 1.f, t + 1.f);
}

// ---------------- space attention (fused vlerp + knorm, one-pass softmax) ----------------
#define ASP_SMEM (2 * SS * DH * 4 + SS * 4)
__global__ __launch_bounds__(256, 1) void attn_space(
    const float* __restrict__ qkv, const float* __restrict__ rv,
    const float* __restrict__ mix, const float* __restrict__ gate,
    const float* __restrict__ kgam,
    __nv_bfloat16* __restrict__ ohi, __nv_bfloat16* __restrict__ olo)
{
    int r = blockIdx.x, h = blockIdx.y;
    long base = (long)r * SS;
    extern __shared__ float sm[];
    float* Ks = sm;
    float* Vs = sm + SS * DH;
    float* mixs = sm + 2 * SS * DH;
    int tid = threadIdx.x;

    if (tid < SS) mixs[tid] = mix[(base + tid) * HEADS + h];
    __syncthreads();

    for (int idx = tid; idx < SS * DH; idx += 256) {
        int j = idx >> 6, d = idx & 63;
        long tok = base + j;
        float vv = qkv[tok * QKVW + 1536 + h * DH + d];
        Vs[idx] = vv + mixs[j] * (rv[tok * DIMV + h * DH + d] - vv);
        Ks[idx] = qkv[tok * QKVW + 768 + h * DH + d];
    }
    __syncthreads();

    // normalize K rows: warp w handles rows [w*32, w*32+32)
    {
        int wid = tid >> 5, lane = tid & 31;
        float g1 = (kgam[h * DH + lane] + 1.f) * 8.0f;
        float g2 = (kgam[h * DH + lane + 32] + 1.f) * 8.0f;
        for (int j = wid * 32; j < wid * 32 + 32; j++) {
            float a = Ks[j * DH + lane], b = Ks[j * DH + lane + 32];
            float ss = a * a + b * b;
            #pragma unroll
            for (int off = 16; off > 0; off >>= 1) ss += __shfl_xor_sync(0xffffffffu, ss, off);
            float inv = 1.f / fmaxf(sqrtf(ss), 1e-12f);
            Ks[j * DH + lane]      = a * inv * g1;
            Ks[j * DH + lane + 32] = b * inv * g2;
        }
    }
    __syncthreads();

    long mytok = base + tid;
    float4 qr[16];
    const float4* qp = (const float4*)(qkv + mytok * QKVW + h * DH);
    #pragma unroll
    for (int e = 0; e < 16; e++) qr[e] = qp[e];

    // one pass: softclamped scores bounded by +-50, no max needed
    float s = 0.f;
    float4 oa[16];
    #pragma unroll
    for (int e = 0; e < 16; e++) oa[e] = make_float4(0.f, 0.f, 0.f, 0.f);
    for (int j = 0; j < SS; j++) {
        const float4* kp = (const float4*)(Ks + j * DH);
        float acc = 0.f;
        #pragma unroll
        for (int e = 0; e < 16; e++) {
            float4 kv = kp[e];
            acc += qr[e].x * kv.x + qr[e].y * kv.y + qr[e].z * kv.z + qr[e].w * kv.w;
        }
        float p = __expf(softclamp(acc));
        s += p;
        const float4* vp = (const float4*)(Vs + j * DH);
        #pragma unroll
        for (int e = 0; e < 16; e++) {
            float4 vv = vp[e];
            oa[e].x += p * vv.x; oa[e].y += p * vv.y;
            oa[e].z += p * vv.z; oa[e].w += p * vv.w;
        }
    }
    float gg = gate[mytok * HEADS + h] / s;
    long ob = mytok * DIMV + h * DH;
    #pragma unroll
    for (int e = 0; e < 16; e++) {
        float vals[4] = {oa[e].x * gg, oa[e].y * gg, oa[e].z * gg, oa[e].w * gg};
        #pragma unroll
        for (int u = 0; u < 4; u++) {
            __nv_bfloat16 hh = __float2bfloat16(vals[u]);
            ohi[ob + e * 4 + u] = hh;
            olo[ob + e * 4 + u] = __float2bfloat16(vals[u] - __bfloat162float(hh));
        }
    }
}

// ---------------- time attention (causal, fused vlerp + knorm + rotary, one-pass) ----------------
__global__ __launch_bounds__(32) void attn_time(
    const float* __restrict__ qkv, const float* __restrict__ rv,
    const float* __restrict__ mix, const float* __restrict__ gate,
    const float* __restrict__ kgam,
    __nv_bfloat16* __restrict__ ohi, __nv_bfloat16* __restrict__ olo)
{
    int r = blockIdx.x, h = blockIdx.y;
    int b = r / SS, s0 = r % SS;
    long base = (long)b * (TT * SS) + s0;
    __shared__ float Ks[TT * DH], Vs[TT * DH], mixs[TT];
    int tid = threadIdx.x;   // lane == tid (one warp)

    mixs[tid] = mix[(base + (long)tid * SS) * HEADS + h];
    __syncwarp();
    for (int idx = tid; idx < TT * DH; idx += 32) {
        int j = idx >> 6, d = idx & 63;
        long tok = base + (long)j * SS;
        float vv = qkv[tok * QKVW + 1536 + h * DH + d];
        Vs[idx] = vv + mixs[j] * (rv[tok * DIMV + h * DH + d] - vv);
        Ks[idx] = qkv[tok * QKVW + 768 + h * DH + d];
    }
    __syncwarp();

    // normalize + rotary on K rows (key j has time index j)
    {
        float g1 = (kgam[h * DH + tid] + 1.f) * 8.0f;
        float g2 = (kgam[h * DH + tid + 32] + 1.f) * 8.0f;
        float invf = __powf(10000.0f, -(float)(2 * tid) / (float)DH);
        for (int j = 0; j < TT; j++) {
            float a = Ks[j * DH + tid], b2 = Ks[j * DH + tid + 32];
            float ss = a * a + b2 * b2;
            #pragma unroll
            for (int off = 16; off > 0; off >>= 1) ss += __shfl_xor_sync(0xffffffffu, ss, off);
            float inv = 1.f / fmaxf(sqrtf(ss), 1e-12f);
            a = a * inv * g1;
            b2 = b2 * inv * g2;
            float ang = (float)j * invf;
            float cc = cosf(ang), sn = sinf(ang);
            Ks[j * DH + tid]      = a * cc - b2 * sn;
            Ks[j * DH + tid + 32] = b2 * cc + a * sn;
        }
    }
    __syncwarp();

    long mytok = base + (long)tid * SS;
    float qf[64];
    {
        const float4* qp = (const float4*)(qkv + mytok * QKVW + h * DH);
        #pragma unroll
        for (int e = 0; e < 16; e++) ((float4*)qf)[e] = qp[e];
        // rotary on q with t = tid
        #pragma unroll
        for (int d = 0; d < 32; d++) {
            float invf = __powf(10000.0f, -(float)(2 * d) / (float)DH);
            float ang = (float)tid * invf;
            float cc = cosf(ang), sn = sinf(ang);
            float x1 = qf[d], x2 = qf[d + 32];
            qf[d]      = x1 * cc - x2 * sn;
            qf[d + 32] = x2 * cc + x1 * sn;
        }
    }

    int nkeys = tid + 1;   // causal
    float s = 0.f;
    float oa[64];
    #pragma unroll
    for (int e = 0; e < 64; e++) oa[e] = 0.f;
    for (int j = 0; j < nkeys; j++) {
        const float* kp = Ks + j * DH;
        float acc = 0.f;
        #pragma unroll
        for (int e = 0; e < 64; e++) acc += qf[e] * kp[e];
        float p = __expf(softclamp(acc));
        s += p;
        const float* vp = Vs + j * DH;
        #pragma unroll
        for (int e = 0; e < 64; e++) oa[e] += p * vp[e];
    }
    float gg = gate[mytok * HEADS + h] / s;
    long ob = mytok * DIMV + h * DH;
    #pragma unroll
    for (int e = 0; e < 64; e++) {
        float val = oa[e] * gg;
        __nv_bfloat16 hh = __float2bfloat16(val);
        ohi[ob + e] = hh;
        olo[ob + e] = __float2bfloat16(val - __bfloat162float(hh));
    }
}

// ---------------- a * gelu(g) -> bf16 split ----------------
__global__ void act_split(const float* __restrict__ h,
                          __nv_bfloat16* __restrict__ hi, __nv_bfloat16* __restrict__ lo) {
    int idx = blockIdx.x * blockDim.x + threadIdx.x;
    if (idx >= NTOK * DFF) return;
    int tok = idx / DFF;
    int c = idx % DFF;
    float a = h[(long)tok * (2 * DFF) + c];
    float g = h[(long)tok * (2 * DFF) + DFF + c];
    float r = a * 0.5f * g * (1.f + erff(g * 0.70710678118654752f));
    __nv_bfloat16 hh = __float2bfloat16(r);
    hi[idx] = hh;
    lo[idx] = __float2bfloat16(r - __bfloat162float(hh));
}

// ---------------- launch ----------------
extern "C" void kernel_launch(void* const* d_in, const int* in_sizes, int n_in,
                              void* d_out, int out_size) {
    const float* tokens      = (const float*)d_in[0];
    const float* attn_norm_w = (const float*)d_in[1];
    const float* Wq          = (const float*)d_in[2];
    const float* Wk          = (const float*)d_in[3];
    const float* Wv          = (const float*)d_in[4];
    const float* Wo          = (const float*)d_in[5];
    const float* Wg          = (const float*)d_in[6];
    const float* Wmix        = (const float*)d_in[7];
    const float* bmix        = (const float*)d_in[8];
    const float* kgam        = (const float*)d_in[9];
    const float* ff_norm_w   = (const float*)d_in[10];
    const float* Win         = (const float*)d_in[11];
    const float* bi_in       = (const float*)d_in[12];
    const float* Wout        = (const float*)d_in[13];
    const float* b_out       = (const float*)d_in[14];
    const float* vr_norm_w   = (const float*)d_in[15];
    const float* vr_W        = (const float*)d_in[16];
    const float* final_norm_w= (const float*)d_in[17];

    float *x, *tn, *qkv, *rv, *h, *mix, *gate;
    __nv_bfloat16 *wthi, *wtlo, *ahi, *alo;
    cudaGetSymbolAddress((void**)&x,   g_x);
    cudaGetSymbolAddress((void**)&tn,  g_tn);
    cudaGetSymbolAddress((void**)&qkv, g_qkv);
    cudaGetSymbolAddress((void**)&rv,  g_rv);
    cudaGetSymbolAddress((void**)&h,   g_h);
    cudaGetSymbolAddress((void**)&mix, g_mix);
    cudaGetSymbolAddress((void**)&gate,g_gate);
    cudaGetSymbolAddress((void**)&wthi,g_wthi);
    cudaGetSymbolAddress((void**)&wtlo,g_wtlo);
    cudaGetSymbolAddress((void**)&ahi, g_ahi);
    cudaGetSymbolAddress((void**)&alo, g_alo);

    static int attr_done = 0;
    if (!attr_done) {
        cudaFuncSetAttribute(gemm_bf16, cudaFuncAttributeMaxDynamicSharedMemorySize, GEMM_SMEM);
        cudaFuncSetAttribute(attn_space, cudaFuncAttributeMaxDynamicSharedMemorySize, ASP_SMEM);
        attr_done = 1;
    }

    const int NTOT = NTOK * DIMV;
    dim3 ts_blk(32, 8);

    // ---- transpose-split all weights ----
    tsplit_kernel<<<dim3(768/32, 768/32), ts_blk>>>(vr_W, wthi, wtlo, 768, 768);
    for (int i = 0; i < 8; i++) {
        size_t lb = SZ_SQ + (size_t)i * SZ_LAYER;
        tsplit_kernel<<<dim3(768/32, 768/32), ts_blk>>>(Wq + (long)i*SZ_SQ,  wthi + lb,           wtlo + lb,           768, 768);
        tsplit_kernel<<<dim3(768/32, 768/32), ts_blk>>>(Wk + (long)i*SZ_SQ,  wthi + lb + SZ_SQ,   wtlo + lb + SZ_SQ,   768, 768);
        tsplit_kernel<<<dim3(768/32, 768/32), ts_blk>>>(Wv + (long)i*SZ_SQ,  wthi + lb + 2*SZ_SQ, wtlo + lb + 2*SZ_SQ, 768, 768);
        tsplit_kernel<<<dim3(768/32, 768/32), ts_blk>>>(Wo + (long)i*SZ_SQ,  wthi + lb + 3*SZ_SQ, wtlo + lb + 3*SZ_SQ, 768, 768);
        tsplit_kernel<<<dim3(4096/32, 768/32), ts_blk>>>(Win + (long)i*SZ_WIN, wthi + lb + 4*SZ_SQ, wtlo + lb + 4*SZ_SQ, 768, 4096);
        tsplit_kernel<<<dim3(768/32, 2048/32), ts_blk>>>(Wout + (long)i*SZ_WOUT, wthi + lb + 4*SZ_SQ + SZ_WIN, wtlo + lb + 4*SZ_SQ + SZ_WIN, 2048, 768);
    }

    copy_kernel<<<(NTOT + 255) / 256, 256>>>(tokens, x, NTOT);

    // value residual: rv = rmsnorm(tokens) @ vr_W
    rmsnorm_split<<<NTOK, 256>>>(tokens, vr_norm_w, nullptr, ahi, alo);
    gemm_bf16<<<dim3(6, 128), 256, GEMM_SMEM>>>(ahi, alo, wthi, wtlo, nullptr, rv, DIMV, DIMV, 0);

    for (int i = 0; i < 8; i++) {
        size_t lb = SZ_SQ + (size_t)i * SZ_LAYER;
        const __nv_bfloat16* wh = wthi + lb;
        const __nv_bfloat16* wl = wtlo + lb;
        const float* aw   = attn_norm_w + (long)i * DIMV;
        const float* wg   = Wg   + (long)i * DIMV * HEADS;
        const float* wmix = Wmix + (long)i * DIMV * HEADS;
        const float* bm   = bmix + (long)i * HEADS;
        const float* kg   = kgam + (long)i * HEADS * DH;
        const float* fw   = ff_norm_w + (long)i * DIMV;
        const float* bi   = bi_in + (long)i * (2 * DFF);
        const float* bo   = b_out + (long)i * DIMV;
        int is_time = ((i + 1) % 4 == 0) ? 1 : 0;

        // attention block
        rmsnorm_split<<<NTOK, 256>>>(x, aw, tn, ahi, alo);
        gemm_bf16<<<dim3(18, 128), 256, GEMM_SMEM>>>(ahi, alo, wh, wl, nullptr, qkv, QKVW, DIMV, 0);
        mixgate_kernel<<<NTOK / 4, 128>>>(tn, wmix, bm, wg, mix, gate);
        if (is_time) attn_time<<<dim3(NTOK / TT, HEADS), 32>>>(qkv, rv, mix, gate, kg, ahi, alo);
        else         attn_space<<<dim3(NTOK / SS, HEADS), 256, ASP_SMEM>>>(qkv, rv, mix, gate, kg, ahi, alo);
        gemm_bf16<<<dim3(6, 128), 256, GEMM_SMEM>>>(ahi, alo, wh + 3*SZ_SQ, wl + 3*SZ_SQ, nullptr, x, DIMV, DIMV, 1);

        // feed-forward block
        rmsnorm_split<<<NTOK, 256>>>(x, fw, nullptr, ahi, alo);
        gemm_bf16<<<dim3(32, 128), 256, GEMM_SMEM>>>(ahi, alo, wh + 4*SZ_SQ, wl + 4*SZ_SQ, bi, h, 2 * DFF, DIMV, 0);
        act_split<<<(NTOK * DFF + 255) / 256, 256>>>(h, ahi, alo);
        gemm_bf16<<<dim3(6, 128), 256, GEMM_SMEM>>>(ahi, alo, wh + 4*SZ_SQ + SZ_WIN, wl + 4*SZ_SQ + SZ_WIN, bo, x, DIMV, DFF, 1);
    }

    rmsnorm_split<<<NTOK, 256>>>(x, final_norm_w, (float*)d_out, nullptr, nullptr);
}

// round 10
// speedup vs baseline: 5.4938x; 1.0048x over previous
#include <cuda_runtime.h>
#include <cuda_bf16.h>
#include <math.h>
#include <stdint.h>

#define NTOK 16384   // B*T*S = 2*32*256
#define DIMV 768
#define HEADS 12
#define DH 64
#define DFF 2048
#define TT 32
#define SS 256
#define QKVW 2304    // fused qkv row width

// weight sizes
#define SZ_SQ   (768*768)
#define SZ_WIN  (768*4096)
#define SZ_WOUT (2048*768)
#define SZ_LAYER (4*SZ_SQ + SZ_WIN + SZ_WOUT)
#define SZ_WTOT (SZ_SQ + 8*SZ_LAYER)

// ---------------- scratch ----------------
__device__ float g_x[NTOK * DIMV];
__device__ float g_tn[NTOK * DIMV];
__device__ float g_qkv[NTOK * QKVW];
__device__ float g_rv[NTOK * DIMV];
__device__ float g_h[NTOK * 2 * DFF];
__device__ float g_mix[NTOK * HEADS];
__device__ float g_gate[NTOK * HEADS];
__device__ __nv_bfloat16 g_wthi[SZ_WTOT];
__device__ __nv_bfloat16 g_wtlo[SZ_WTOT];
__device__ __nv_bfloat16 g_ahi[NTOK * DFF];
__device__ __nv_bfloat16 g_alo[NTOK * DFF];

// ==================== weight transpose + split ====================
__global__ void tsplit_kernel(const float* __restrict__ W,
                              __nv_bfloat16* __restrict__ hi, __nv_bfloat16* __restrict__ lo,
                              int K, int N) {
    __shared__ float tile[32][33];
    int bn = blockIdx.x * 32, bk = blockIdx.y * 32;
    int tx = threadIdx.x, ty = threadIdx.y;
    #pragma unroll
    for (int i = ty; i < 32; i += 8)
        tile[i][tx] = W[(long)(bk + i) * N + bn + tx];
    __syncthreads();
    #pragma unroll
    for (int i = ty; i < 32; i += 8) {
        float x = tile[tx][i];
        __nv_bfloat16 h = __float2bfloat16(x);
        long out = (long)(bn + i) * K + bk + tx;
        hi[out] = h;
        lo[out] = __float2bfloat16(x - __bfloat162float(h));
    }
}

// ==================== bf16 HMMA GEMM (ldmatrix + cp.async double-buffer) ====================
#define CH_BYTES 10240
#define BUF_BYTES (4 * CH_BYTES)
#define GEMM_SMEM (2 * BUF_BYTES)

__device__ __forceinline__ uint32_t smem_u32(const void* p) {
    uint32_t a;
    asm("{ .reg .u64 t; cvta.to.shared.u64 t, %1; cvt.u32.u64 %0, t; }" : "=r"(a) : "l"(p));
    return a;
}
__device__ __forceinline__ void cp16(uint32_t dst, const void* src) {
    asm volatile("cp.async.ca.shared.global [%0], [%1], 16;" :: "r"(dst), "l"(src));
}
__device__ __forceinline__ void cp_commit() { asm volatile("cp.async.commit_group;"); }
__device__ __forceinline__ void cp_wait1() { asm volatile("cp.async.wait_group 1;"); }
__device__ __forceinline__ void cp_wait0() { asm volatile("cp.async.wait_group 0;"); }

__device__ __forceinline__ void mma_bf16(float* d, const uint32_t* a, const uint32_t* b) {
    asm volatile(
        "mma.sync.aligned.m16n8k16.row.col.f32.bf16.bf16.f32 "
        "{%0,%1,%2,%3}, {%4,%5,%6,%7}, {%8,%9}, {%0,%1,%2,%3};"
        : "+f"(d[0]), "+f"(d[1]), "+f"(d[2]), "+f"(d[3])
        : "r"(a[0]), "r"(a[1]), "r"(a[2]), "r"(a[3]), "r"(b[0]), "r"(b[1]));
}
__device__ __forceinline__ void ldsm4(uint32_t addr, uint32_t* d) {
    asm volatile("ldmatrix.sync.aligned.m8n8.x4.shared.b16 {%0,%1,%2,%3}, [%4];"
                 : "=r"(d[0]), "=r"(d[1]), "=r"(d[2]), "=r"(d[3]) : "r"(addr));
}

__global__ __launch_bounds__(256) void gemm_bf16(
    const __nv_bfloat16* __restrict__ Ah, const __nv_bfloat16* __restrict__ Al,
    const __nv_bfloat16* __restrict__ Bh, const __nv_bfloat16* __restrict__ Bl,
    const float* __restrict__ bias, float* __restrict__ C,
    int N, int K, int accumulate)
{
    extern __shared__ char smem[];
    uint32_t sb = smem_u32(smem);
    int tid = threadIdx.x, wid = tid >> 5, lane = tid & 31;
    int m0 = blockIdx.y * 128, n0 = blockIdx.x * 128;
    int wm = (wid & 1) * 64, wn = (wid >> 1) * 32;
    int g = lane >> 2, tig = lane & 3;
    int mi = lane >> 3, r8 = lane & 7;
    uint32_t offA = (uint32_t)(((mi & 1) * 8 + r8) * 80 + (mi >> 1) * 16);
    uint32_t offB = (uint32_t)(((mi >> 1) * 8 + r8) * 80 + (mi & 1) * 16);

    float acc[4][4][4];
    #pragma unroll
    for (int mt = 0; mt < 4; mt++)
        #pragma unroll
        for (int nt = 0; nt < 4; nt++)
            #pragma unroll
            for (int e = 0; e < 4; e++) acc[mt][nt][e] = 0.f;

    int nchunks = K >> 5;
    int r0 = tid >> 2, s0 = (tid & 3) * 8;
    int r1 = (tid + 256) >> 2, s1 = s0;

    #define LOADCHUNK(b, kc_) do {                                                     \
        uint32_t base = sb + (b) * BUF_BYTES;                                          \
        cp16(base + r0 * 80 + (s0 << 1),                 Ah + (long)(m0 + r0) * K + (kc_) + s0); \
        cp16(base + CH_BYTES + r0 * 80 + (s0 << 1),      Al + (long)(m0 + r0) * K + (kc_) + s0); \
        cp16(base + 2 * CH_BYTES + r0 * 80 + (s0 << 1),  Bh + (long)(n0 + r0) * K + (kc_) + s0); \
        cp16(base + 3 * CH_BYTES + r0 * 80 + (s0 << 1),  Bl + (long)(n0 + r0) * K + (kc_) + s0); \
        cp16(base + r1 * 80 + (s1 << 1),                 Ah + (long)(m0 + r1) * K + (kc_) + s1); \
        cp16(base + CH_BYTES + r1 * 80 + (s1 << 1),      Al + (long)(m0 + r1) * K + (kc_) + s1); \
        cp16(base + 2 * CH_BYTES + r1 * 80 + (s1 << 1),  Bh + (long)(n0 + r1) * K + (kc_) + s1); \
        cp16(base + 3 * CH_BYTES + r1 * 80 + (s1 << 1),  Bl + (long)(n0 + r1) * K + (kc_) + s1); \
    } while (0)

    LOADCHUNK(0, 0);
    cp_commit();

    for (int c = 0; c < nchunks; c++) {
        if (c + 1 < nchunks) {
            LOADCHUNK((c + 1) & 1, (c + 1) << 5);
            cp_commit();
            cp_wait1();
        } else {
            cp_wait0();
        }
        __syncthreads();

        uint32_t bufAh = sb + (c & 1) * BUF_BYTES;
        uint32_t bufAl = bufAh + CH_BYTES;
        uint32_t bufBh = bufAh + 2 * CH_BYTES;
        uint32_t bufBl = bufAh + 3 * CH_BYTES;

        #pragma unroll
        for (int ks = 0; ks < 32; ks += 16) {
            uint32_t kb = (uint32_t)(ks * 2);
            // load ALL fragments for this k-step first
            uint32_t bh[8], bl[8], ah[16], al[16];
            ldsm4(bufBh + (uint32_t)(wn) * 80 + kb + offB, bh);
            ldsm4(bufBh + (uint32_t)(wn + 16) * 80 + kb + offB, bh + 4);
            ldsm4(bufBl + (uint32_t)(wn) * 80 + kb + offB, bl);
            ldsm4(bufBl + (uint32_t)(wn + 16) * 80 + kb + offB, bl + 4);
            #pragma unroll
            for (int mt = 0; mt < 4; mt++) {
                ldsm4(bufAh + (uint32_t)(wm + mt * 16) * 80 + kb + offA, ah + mt * 4);
                ldsm4(bufAl + (uint32_t)(wm + mt * 16) * 80 + kb + offA, al + mt * 4);
            }
            // pass 1: Ah*Bh — 16 independent MMAs
            #pragma unroll
            for (int mt = 0; mt < 4; mt++)
                #pragma unroll
                for (int nt = 0; nt < 4; nt++)
                    mma_bf16(acc[mt][nt], ah + mt * 4, bh + nt * 2);
            // pass 2: Ah*Bl
            #pragma unroll
            for (int mt = 0; mt < 4; mt++)
                #pragma unroll
                for (int nt = 0; nt < 4; nt++)
                    mma_bf16(acc[mt][nt], ah + mt * 4, bl + nt * 2);
            // pass 3: Al*Bh
            #pragma unroll
            for (int mt = 0; mt < 4; mt++)
                #pragma unroll
                for (int nt = 0; nt < 4; nt++)
                    mma_bf16(acc[mt][nt], al + mt * 4, bh + nt * 2);
        }
        __syncthreads();
    }

    #pragma unroll
    for (int mt = 0; mt < 4; mt++) {
        long r = m0 + wm + mt * 16 + g;
        #pragma unroll
        for (int nt = 0; nt < 4; nt++) {
            int c = n0 + wn + nt * 8 + tig * 2;
            float v0 = acc[mt][nt][0], v1 = acc[mt][nt][1];
            float v2 = acc[mt][nt][2], v3 = acc[mt][nt][3];
            if (bias) { v0 += bias[c]; v1 += bias[c + 1]; v2 += bias[c]; v3 += bias[c + 1]; }
            if (accumulate) {
                C[r * N + c]           += v0;
                C[r * N + c + 1]       += v1;
                C[(r + 8) * N + c]     += v2;
                C[(r + 8) * N + c + 1] += v3;
            } else {
                C[r * N + c]           = v0;
                C[r * N + c + 1]       = v1;
                C[(r + 8) * N + c]     = v2;
                C[(r + 8) * N + c + 1] = v3;
            }
        }
    }
}

// ---------------- elementwise ----------------
__global__ void copy_kernel(const float* __restrict__ src, float* __restrict__ dst, int n) {
    int i = blockIdx.x * blockDim.x + threadIdx.x;
    if (i < n) dst[i] = src[i];
}

// rmsnorm + bf16 split (fp32 out optional; hi/lo optional)
__global__ void rmsnorm_split(const float* __restrict__ x, const float* __restrict__ w,
                              float* __restrict__ outf,
                              __nv_bfloat16* __restrict__ hi, __nv_bfloat16* __restrict__ lo) {
    int tok = blockIdx.x;
    int tid = threadIdx.x;
    const float* xr = x + (long)tok * DIMV;
    float v0 = xr[tid], v1 = xr[tid + 256], v2 = xr[tid + 512];
    __shared__ float red[256];
    red[tid] = v0 * v0 + v1 * v1 + v2 * v2;
    __syncthreads();
    for (int off = 128; off > 0; off >>= 1) {
        if (tid < off) red[tid] += red[tid + off];
        __syncthreads();
    }
    float inv = rsqrtf(red[0] / (float)DIMV + 1e-6f);
    float r0 = v0 * inv * w[tid];
    float r1 = v1 * inv * w[tid + 256];
    float r2 = v2 * inv * w[tid + 512];
    long base = (long)tok * DIMV;
    if (outf) { outf[base + tid] = r0; outf[base + tid + 256] = r1; outf[base + tid + 512] = r2; }
    if (hi) {
        __nv_bfloat16 h0 = __float2bfloat16(r0), h1 = __float2bfloat16(r1), h2 = __float2bfloat16(r2);
        hi[base + tid] = h0; hi[base + tid + 256] = h1; hi[base + tid + 512] = h2;
        lo[base + tid]       = __float2bfloat16(r0 - __bfloat162float(h0));
        lo[base + tid + 256] = __float2bfloat16(r1 - __bfloat162float(h1));
        lo[base + tid + 512] = __float2bfloat16(r2 - __bfloat162float(h2));
    }
}

// ---------------- mix & gate projection: one warp per token ----------------
__global__ __launch_bounds__(128) void mixgate_kernel(
    const float* __restrict__ tn,
    const float* __restrict__ Wmix, const float* __restrict__ bmix,
    const float* __restrict__ Wg,
    float* __restrict__ mix, float* __restrict__ gate)
{
    int tok = blockIdx.x * 4 + (threadIdx.x >> 5);
    int lane = threadIdx.x & 31;
    const float* x = tn + (long)tok * DIMV;
    float t[24];
    #pragma unroll
    for (int e = 0; e < 24; e++) t[e] = x[lane + 32 * e];
    for (int col = 0; col < HEADS; col++) {
        float am = 0.f, ag = 0.f;
        #pragma unroll
        for (int e = 0; e < 24; e++) {
            int d = lane + 32 * e;
            am += t[e] * Wmix[d * HEADS + col];
            ag += t[e] * Wg[d * HEADS + col];
        }
        #pragma unroll
        for (int off = 16; off > 0; off >>= 1) {
            am += __shfl_xor_sync(0xffffffffu, am, off);
            ag += __shfl_xor_sync(0xffffffffu, ag, off);
        }
        if (lane == 0) {
            mix[tok * HEADS + col]  = 1.f / (1.f + __expf(-(am + bmix[col])));
            gate[tok * HEADS + col] = 1.f / (1.f + __expf(-ag));
        }
    }
}

__device__ __forceinline__ float softclamp(float acc) {
    // 50*tanh(acc*(1/8)*(1/50))
    float t = __expf(acc * 0.005f);
    return 50.f * __fdividef(t - 1.f, t + 1.f);
}

// ---------------- space attention (fused vlerp + knorm, one-pass softmax) ----------------
#define ASP_SMEM (2 * SS * DH * 4 + SS * 4)
__global__ __launch_bounds__(256, 1) void attn_space(
    const float* __restrict__ qkv, const float* __restrict__ rv,
    const float* __restrict__ mix, const float* __restrict__ gate,
    const float* __restrict__ kgam,
    __nv_bfloat16* __restrict__ ohi, __nv_bfloat16* __restrict__ olo)
{
    int r = blockIdx.x, h = blockIdx.y;
    long base = (long)r * SS;
    extern __shared__ float sm[];
    float* Ks = sm;
    float* Vs = sm + SS * DH;
    float* mixs = sm + 2 * SS * DH;
    int tid = threadIdx.x;

    if (tid < SS) mixs[tid] = mix[(base + tid) * HEADS + h];
    __syncthreads();

    for (int idx = tid; idx < SS * DH; idx += 256) {
        int j = idx >> 6, d = idx & 63;
        long tok = base + j;
        float vv = qkv[tok * QKVW + 1536 + h * DH + d];
        Vs[idx] = vv + mixs[j] * (rv[tok * DIMV + h * DH + d] - vv);
        Ks[idx] = qkv[tok * QKVW + 768 + h * DH + d];
    }
    __syncthreads();

    // normalize K rows: warp w handles rows [w*32, w*32+32)
    {
        int wid = tid >> 5, lane = tid & 31;
        float g1 = (kgam[h * DH + lane] + 1.f) * 8.0f;
        float g2 = (kgam[h * DH + lane + 32] + 1.f) * 8.0f;
        for (int j = wid * 32; j < wid * 32 + 32; j++) {
            float a = Ks[j * DH + lane], b = Ks[j * DH + lane + 32];
            float ss = a * a + b * b;
            #pragma unroll
            for (int off = 16; off > 0; off >>= 1) ss += __shfl_xor_sync(0xffffffffu, ss, off);
            float inv = 1.f / fmaxf(sqrtf(ss), 1e-12f);
            Ks[j * DH + lane]      = a * inv * g1;
            Ks[j * DH + lane + 32] = b * inv * g2;
        }
    }
    __syncthreads();

    long mytok = base + tid;
    float4 qr[16];
    const float4* qp = (const float4*)(qkv + mytok * QKVW + h * DH);
    #pragma unroll
    for (int e = 0; e < 16; e++) qr[e] = qp[e];

    // one pass: softclamped scores bounded by +-50, no max needed
    float s = 0.f;
    float4 oa[16];
    #pragma unroll
    for (int e = 0; e < 16; e++) oa[e] = make_float4(0.f, 0.f, 0.f, 0.f);
    for (int j = 0; j < SS; j++) {
        const float4* kp = (const float4*)(Ks + j * DH);
        float acc = 0.f;
        #pragma unroll
        for (int e = 0; e < 16; e++) {
            float4 kv = kp[e];
            acc += qr[e].x * kv.x + qr[e].y * kv.y + qr[e].z * kv.z + qr[e].w * kv.w;
        }
        float p = __expf(softclamp(acc));
        s += p;
        const float4* vp = (const float4*)(Vs + j * DH);
        #pragma unroll
        for (int e = 0; e < 16; e++) {
            float4 vv = vp[e];
            oa[e].x += p * vv.x; oa[e].y += p * vv.y;
            oa[e].z += p * vv.z; oa[e].w += p * vv.w;
        }
    }
    float gg = gate[mytok * HEADS + h] / s;
    long ob = mytok * DIMV + h * DH;
    #pragma unroll
    for (int e = 0; e < 16; e++) {
        float vals[4] = {oa[e].x * gg, oa[e].y * gg, oa[e].z * gg, oa[e].w * gg};
        #pragma unroll
        for (int u = 0; u < 4; u++) {
            __nv_bfloat16 hh = __float2bfloat16(vals[u]);
            ohi[ob + e * 4 + u] = hh;
            olo[ob + e * 4 + u] = __float2bfloat16(vals[u] - __bfloat162float(hh));
        }
    }
}

// ---------------- time attention (causal, fused vlerp + knorm + rotary, one-pass) ----------------
__global__ __launch_bounds__(32) void attn_time(
    const float* __restrict__ qkv, const float* __restrict__ rv,
    const float* __restrict__ mix, const float* __restrict__ gate,
    const float* __restrict__ kgam,
    __nv_bfloat16* __restrict__ ohi, __nv_bfloat16* __restrict__ olo)
{
    int r = blockIdx.x, h = blockIdx.y;
    int b = r / SS, s0 = r % SS;
    long base = (long)b * (TT * SS) + s0;
    __shared__ float Ks[TT * DH], Vs[TT * DH], mixs[TT];
    int tid = threadIdx.x;   // lane == tid (one warp)

    mixs[tid] = mix[(base + (long)tid * SS) * HEADS + h];
    __syncwarp();
    for (int idx = tid; idx < TT * DH; idx += 32) {
        int j = idx >> 6, d = idx & 63;
        long tok = base + (long)j * SS;
        float vv = qkv[tok * QKVW + 1536 + h * DH + d];
        Vs[idx] = vv + mixs[j] * (rv[tok * DIMV + h * DH + d] - vv);
        Ks[idx] = qkv[tok * QKVW + 768 + h * DH + d];
    }
    __syncwarp();

    // normalize + rotary on K rows (key j has time index j)
    {
        float g1 = (kgam[h * DH + tid] + 1.f) * 8.0f;
        float g2 = (kgam[h * DH + tid + 32] + 1.f) * 8.0f;
        float invf = __powf(10000.0f, -(float)(2 * tid) / (float)DH);
        for (int j = 0; j < TT; j++) {
            float a = Ks[j * DH + tid], b2 = Ks[j * DH + tid + 32];
            float ss = a * a + b2 * b2;
            #pragma unroll
            for (int off = 16; off > 0; off >>= 1) ss += __shfl_xor_sync(0xffffffffu, ss, off);
            float inv = 1.f / fmaxf(sqrtf(ss), 1e-12f);
            a = a * inv * g1;
            b2 = b2 * inv * g2;
            float ang = (float)j * invf;
            float cc = cosf(ang), sn = sinf(ang);
            Ks[j * DH + tid]      = a * cc - b2 * sn;
            Ks[j * DH + tid + 32] = b2 * cc + a * sn;
        }
    }
    __syncwarp();

    long mytok = base + (long)tid * SS;
    float qf[64];
    {
        const float4* qp = (const float4*)(qkv + mytok * QKVW + h * DH);
        #pragma unroll
        for (int e = 0; e < 16; e++) ((float4*)qf)[e] = qp[e];
        // rotary on q with t = tid
        #pragma unroll
        for (int d = 0; d < 32; d++) {
            float invf = __powf(10000.0f, -(float)(2 * d) / (float)DH);
            float ang = (float)tid * invf;
            float cc = cosf(ang), sn = sinf(ang);
            float x1 = qf[d], x2 = qf[d + 32];
            qf[d]      = x1 * cc - x2 * sn;
            qf[d + 32] = x2 * cc + x1 * sn;
        }
    }

    int nkeys = tid + 1;   // causal
    float s = 0.f;
    float oa[64];
    #pragma unroll
    for (int e = 0; e < 64; e++) oa[e] = 0.f;
    for (int j = 0; j < nkeys; j++) {
        const float* kp = Ks + j * DH;
        float acc = 0.f;
        #pragma unroll
        for (int e = 0; e < 64; e++) acc += qf[e] * kp[e];
        float p = __expf(softclamp(acc));
        s += p;
        const float* vp = Vs + j * DH;
        #pragma unroll
        for (int e = 0; e < 64; e++) oa[e] += p * vp[e];
    }
    float gg = gate[mytok * HEADS + h] / s;
    long ob = mytok * DIMV + h * DH;
    #pragma unroll
    for (int e = 0; e < 64; e++) {
        float val = oa[e] * gg;
        __nv_bfloat16 hh = __float2bfloat16(val);
        ohi[ob + e] = hh;
        olo[ob + e] = __float2bfloat16(val - __bfloat162float(hh));
    }
}

// ---------------- a * gelu(g) -> bf16 split ----------------
__global__ void act_split(const float* __restrict__ h,
                          __nv_bfloat16* __restrict__ hi, __nv_bfloat16* __restrict__ lo) {
    int idx = blockIdx.x * blockDim.x + threadIdx.x;
    if (idx >= NTOK * DFF) return;
    int tok = idx / DFF;
    int c = idx % DFF;
    float a = h[(long)tok * (2 * DFF) + c];
    float g = h[(long)tok * (2 * DFF) + DFF + c];
    float r = a * 0.5f * g * (1.f + erff(g * 0.70710678118654752f));
    __nv_bfloat16 hh = __float2bfloat16(r);
    hi[idx] = hh;
    lo[idx] = __float2bfloat16(r - __bfloat162float(hh));
}

// ---------------- launch ----------------
extern "C" void kernel_launch(void* const* d_in, const int* in_sizes, int n_in,
                              void* d_out, int out_size) {
    const float* tokens      = (const float*)d_in[0];
    const float* attn_norm_w = (const float*)d_in[1];
    const float* Wq          = (const float*)d_in[2];
    const float* Wk          = (const float*)d_in[3];
    const float* Wv          = (const float*)d_in[4];
    const float* Wo          = (const float*)d_in[5];
    const float* Wg          = (const float*)d_in[6];
    const float* Wmix        = (const float*)d_in[7];
    const float* bmix        = (const float*)d_in[8];
    const float* kgam        = (const float*)d_in[9];
    const float* ff_norm_w   = (const float*)d_in[10];
    const float* Win         = (const float*)d_in[11];
    const float* bi_in       = (const float*)d_in[12];
    const float* Wout        = (const float*)d_in[13];
    const float* b_out       = (const float*)d_in[14];
    const float* vr_norm_w   = (const float*)d_in[15];
    const float* vr_W        = (const float*)d_in[16];
    const float* final_norm_w= (const float*)d_in[17];

    float *x, *tn, *qkv, *rv, *h, *mix, *gate;
    __nv_bfloat16 *wthi, *wtlo, *ahi, *alo;
    cudaGetSymbolAddress((void**)&x,   g_x);
    cudaGetSymbolAddress((void**)&tn,  g_tn);
    cudaGetSymbolAddress((void**)&qkv, g_qkv);
    cudaGetSymbolAddress((void**)&rv,  g_rv);
    cudaGetSymbolAddress((void**)&h,   g_h);
    cudaGetSymbolAddress((void**)&mix, g_mix);
    cudaGetSymbolAddress((void**)&gate,g_gate);
    cudaGetSymbolAddress((void**)&wthi,g_wthi);
    cudaGetSymbolAddress((void**)&wtlo,g_wtlo);
    cudaGetSymbolAddress((void**)&ahi, g_ahi);
    cudaGetSymbolAddress((void**)&alo, g_alo);

    static int attr_done = 0;
    if (!attr_done) {
        cudaFuncSetAttribute(gemm_bf16, cudaFuncAttributeMaxDynamicSharedMemorySize, GEMM_SMEM);
        cudaFuncSetAttribute(attn_space, cudaFuncAttributeMaxDynamicSharedMemorySize, ASP_SMEM);
        attr_done = 1;
    }

    const int NTOT = NTOK * DIMV;
    dim3 ts_blk(32, 8);

    // ---- transpose-split all weights ----
    tsplit_kernel<<<dim3(768/32, 768/32), ts_blk>>>(vr_W, wthi, wtlo, 768, 768);
    for (int i = 0; i < 8; i++) {
        size_t lb = SZ_SQ + (size_t)i * SZ_LAYER;
        tsplit_kernel<<<dim3(768/32, 768/32), ts_blk>>>(Wq + (long)i*SZ_SQ,  wthi + lb,           wtlo + lb,           768, 768);
        tsplit_kernel<<<dim3(768/32, 768/32), ts_blk>>>(Wk + (long)i*SZ_SQ,  wthi + lb + SZ_SQ,   wtlo + lb + SZ_SQ,   768, 768);
        tsplit_kernel<<<dim3(768/32, 768/32), ts_blk>>>(Wv + (long)i*SZ_SQ,  wthi + lb + 2*SZ_SQ, wtlo + lb + 2*SZ_SQ, 768, 768);
        tsplit_kernel<<<dim3(768/32, 768/32), ts_blk>>>(Wo + (long)i*SZ_SQ,  wthi + lb + 3*SZ_SQ, wtlo + lb + 3*SZ_SQ, 768, 768);
        tsplit_kernel<<<dim3(4096/32, 768/32), ts_blk>>>(Win + (long)i*SZ_WIN, wthi + lb + 4*SZ_SQ, wtlo + lb + 4*SZ_SQ, 768, 4096);
        tsplit_kernel<<<dim3(768/32, 2048/32), ts_blk>>>(Wout + (long)i*SZ_WOUT, wthi + lb + 4*SZ_SQ + SZ_WIN, wtlo + lb + 4*SZ_SQ + SZ_WIN, 2048, 768);
    }

    copy_kernel<<<(NTOT + 255) / 256, 256>>>(tokens, x, NTOT);

    // value residual: rv = rmsnorm(tokens) @ vr_W
    rmsnorm_split<<<NTOK, 256>>>(tokens, vr_norm_w, nullptr, ahi, alo);
    gemm_bf16<<<dim3(6, 128), 256, GEMM_SMEM>>>(ahi, alo, wthi, wtlo, nullptr, rv, DIMV, DIMV, 0);

    for (int i = 0; i < 8; i++) {
        size_t lb = SZ_SQ + (size_t)i * SZ_LAYER;
        const __nv_bfloat16* wh = wthi + lb;
        const __nv_bfloat16* wl = wtlo + lb;
        const float* aw   = attn_norm_w + (long)i * DIMV;
        const float* wg   = Wg   + (long)i * DIMV * HEADS;
        const float* wmix = Wmix + (long)i * DIMV * HEADS;
        const float* bm   = bmix + (long)i * HEADS;
        const float* kg   = kgam + (long)i * HEADS * DH;
        const float* fw   = ff_norm_w + (long)i * DIMV;
        const float* bi   = bi_in + (long)i * (2 * DFF);
        const float* bo   = b_out + (long)i * DIMV;
        int is_time = ((i + 1) % 4 == 0) ? 1 : 0;

        // attention block
        rmsnorm_split<<<NTOK, 256>>>(x, aw, tn, ahi, alo);
        gemm_bf16<<<dim3(18, 128), 256, GEMM_SMEM>>>(ahi, alo, wh, wl, nullptr, qkv, QKVW, DIMV, 0);
        mixgate_kernel<<<NTOK / 4, 128>>>(tn, wmix, bm, wg, mix, gate);
        if (is_time) attn_time<<<dim3(NTOK / TT, HEADS), 32>>>(qkv, rv, mix, gate, kg, ahi, alo);
        else         attn_space<<<dim3(NTOK / SS, HEADS), 256, ASP_SMEM>>>(qkv, rv, mix, gate, kg, ahi, alo);
        gemm_bf16<<<dim3(6, 128), 256, GEMM_SMEM>>>(ahi, alo, wh + 3*SZ_SQ, wl + 3*SZ_SQ, nullptr, x, DIMV, DIMV, 1);

        // feed-forward block
        rmsnorm_split<<<NTOK, 256>>>(x, fw, nullptr, ahi, alo);
        gemm_bf16<<<dim3(32, 128), 256, GEMM_SMEM>>>(ahi, alo, wh + 4*SZ_SQ, wl + 4*SZ_SQ, bi, h, 2 * DFF, DIMV, 0);
        act_split<<<(NTOK * DFF + 255) / 256, 256>>>(h, ahi, alo);
        gemm_bf16<<<dim3(6, 128), 256, GEMM_SMEM>>>(ahi, alo, wh + 4*SZ_SQ + SZ_WIN, wl + 4*SZ_SQ + SZ_WIN, bo, x, DIMV, DFF, 1);
    }

    rmsnorm_split<<<NTOK, 256>>>(x, final_norm_w, (float*)d_out, nullptr, nullptr);
}

// round 11
// speedup vs baseline: 5.5469x; 1.0097x over previous
#include <cuda_runtime.h>
#include <cuda_bf16.h>
#include <math.h>
#include <stdint.h>

#define NTOK 16384   // B*T*S = 2*32*256
#define DIMV 768
#define HEADS 12
#define DH 64
#define DFF 2048
#define TT 32
#define SS 256
#define QKVW 2304    // fused qkv row width

// weight sizes
#define SZ_SQ   (768*768)
#define SZ_WIN  (768*4096)
#define SZ_WOUT (2048*768)
#define SZ_LAYER (4*SZ_SQ + SZ_WIN + SZ_WOUT)
#define SZ_WTOT (SZ_SQ + 8*SZ_LAYER)

// ---------------- scratch ----------------
__device__ float g_x[NTOK * DIMV];
__device__ float g_tn[NTOK * DIMV];
__device__ float g_qkv[NTOK * QKVW];
__device__ float g_rv[NTOK * DIMV];
__device__ float g_h[NTOK * 2 * DFF];
__device__ float g_mix[NTOK * HEADS];
__device__ float g_gate[NTOK * HEADS];
__device__ __nv_bfloat16 g_wthi[SZ_WTOT];
__device__ __nv_bfloat16 g_wtlo[SZ_WTOT];
__device__ __nv_bfloat16 g_ahi[NTOK * DFF];
__device__ __nv_bfloat16 g_alo[NTOK * DFF];

// ---------------- packed f32x2 helpers ----------------
typedef unsigned long long ull;
#define FMA2(acc, a, b) \
    asm("fma.rn.f32x2 %0, %1, %2, %0;" : "+l"(acc) : "l"(a), "l"(b))
__device__ __forceinline__ ull pack2(float x) {
    ull r;
    asm("mov.b64 %0, {%1, %1};" : "=l"(r) : "r"(__float_as_uint(x)));
    return r;
}
__device__ __forceinline__ float hsum2(ull v) {
    uint32_t lo, hi;
    asm("mov.b64 {%0, %1}, %2;" : "=r"(lo), "=r"(hi) : "l"(v));
    return __uint_as_float(lo) + __uint_as_float(hi);
}
__device__ __forceinline__ void unpack2(ull v, float& a, float& b) {
    uint32_t lo, hi;
    asm("mov.b64 {%0, %1}, %2;" : "=r"(lo), "=r"(hi) : "l"(v));
    a = __uint_as_float(lo); b = __uint_as_float(hi);
}

// ==================== weight transpose + split ====================
__global__ void tsplit_kernel(const float* __restrict__ W,
                              __nv_bfloat16* __restrict__ hi, __nv_bfloat16* __restrict__ lo,
                              int K, int N) {
    __shared__ float tile[32][33];
    int bn = blockIdx.x * 32, bk = blockIdx.y * 32;
    int tx = threadIdx.x, ty = threadIdx.y;
    #pragma unroll
    for (int i = ty; i < 32; i += 8)
        tile[i][tx] = W[(long)(bk + i) * N + bn + tx];
    __syncthreads();
    #pragma unroll
    for (int i = ty; i < 32; i += 8) {
        float x = tile[tx][i];
        __nv_bfloat16 h = __float2bfloat16(x);
        long out = (long)(bn + i) * K + bk + tx;
        hi[out] = h;
        lo[out] = __float2bfloat16(x - __bfloat162float(h));
    }
}

// ==================== bf16 HMMA GEMM (ldmatrix + cp.async double-buffer) ====================
#define CH_BYTES 10240
#define BUF_BYTES (4 * CH_BYTES)
#define GEMM_SMEM (2 * BUF_BYTES)

__device__ __forceinline__ uint32_t smem_u32(const void* p) {
    uint32_t a;
    asm("{ .reg .u64 t; cvta.to.shared.u64 t, %1; cvt.u32.u64 %0, t; }" : "=r"(a) : "l"(p));
    return a;
}
__device__ __forceinline__ void cp16(uint32_t dst, const void* src) {
    asm volatile("cp.async.ca.shared.global [%0], [%1], 16;" :: "r"(dst), "l"(src));
}
__device__ __forceinline__ void cp_commit() { asm volatile("cp.async.commit_group;"); }
__device__ __forceinline__ void cp_wait1() { asm volatile("cp.async.wait_group 1;"); }
__device__ __forceinline__ void cp_wait0() { asm volatile("cp.async.wait_group 0;"); }

__device__ __forceinline__ void mma_bf16(float* d, const uint32_t* a, const uint32_t* b) {
    asm volatile(
        "mma.sync.aligned.m16n8k16.row.col.f32.bf16.bf16.f32 "
        "{%0,%1,%2,%3}, {%4,%5,%6,%7}, {%8,%9}, {%0,%1,%2,%3};"
        : "+f"(d[0]), "+f"(d[1]), "+f"(d[2]), "+f"(d[3])
        : "r"(a[0]), "r"(a[1]), "r"(a[2]), "r"(a[3]), "r"(b[0]), "r"(b[1]));
}
__device__ __forceinline__ void ldsm4(uint32_t addr, uint32_t* d) {
    asm volatile("ldmatrix.sync.aligned.m8n8.x4.shared.b16 {%0,%1,%2,%3}, [%4];"
                 : "=r"(d[0]), "=r"(d[1]), "=r"(d[2]), "=r"(d[3]) : "r"(addr));
}

__global__ __launch_bounds__(256, 2) void gemm_bf16(
    const __nv_bfloat16* __restrict__ Ah, const __nv_bfloat16* __restrict__ Al,
    const __nv_bfloat16* __restrict__ Bh, const __nv_bfloat16* __restrict__ Bl,
    const float* __restrict__ bias, float* __restrict__ C,
    int N, int K, int accumulate)
{
    extern __shared__ char smem[];
    uint32_t sb = smem_u32(smem);
    int tid = threadIdx.x, wid = tid >> 5, lane = tid & 31;
    int m0 = blockIdx.y * 128, n0 = blockIdx.x * 128;
    int wm = (wid & 1) * 64, wn = (wid >> 1) * 32;
    int g = lane >> 2, tig = lane & 3;
    int mi = lane >> 3, r8 = lane & 7;
    uint32_t offA = (uint32_t)(((mi & 1) * 8 + r8) * 80 + (mi >> 1) * 16);
    uint32_t offB = (uint32_t)(((mi >> 1) * 8 + r8) * 80 + (mi & 1) * 16);

    float acc[4][4][4];
    #pragma unroll
    for (int mt = 0; mt < 4; mt++)
        #pragma unroll
        for (int nt = 0; nt < 4; nt++)
            #pragma unroll
            for (int e = 0; e < 4; e++) acc[mt][nt][e] = 0.f;

    int nchunks = K >> 5;
    int r0 = tid >> 2, s0 = (tid & 3) * 8;
    int r1 = (tid + 256) >> 2, s1 = s0;

    #define LOADCHUNK(b, kc_) do {                                                     \
        uint32_t base = sb + (b) * BUF_BYTES;                                          \
        cp16(base + r0 * 80 + (s0 << 1),                 Ah + (long)(m0 + r0) * K + (kc_) + s0); \
        cp16(base + CH_BYTES + r0 * 80 + (s0 << 1),      Al + (long)(m0 + r0) * K + (kc_) + s0); \
        cp16(base + 2 * CH_BYTES + r0 * 80 + (s0 << 1),  Bh + (long)(n0 + r0) * K + (kc_) + s0); \
        cp16(base + 3 * CH_BYTES + r0 * 80 + (s0 << 1),  Bl + (long)(n0 + r0) * K + (kc_) + s0); \
        cp16(base + r1 * 80 + (s1 << 1),                 Ah + (long)(m0 + r1) * K + (kc_) + s1); \
        cp16(base + CH_BYTES + r1 * 80 + (s1 << 1),      Al + (long)(m0 + r1) * K + (kc_) + s1); \
        cp16(base + 2 * CH_BYTES + r1 * 80 + (s1 << 1),  Bh + (long)(n0 + r1) * K + (kc_) + s1); \
        cp16(base + 3 * CH_BYTES + r1 * 80 + (s1 << 1),  Bl + (long)(n0 + r1) * K + (kc_) + s1); \
    } while (0)

    LOADCHUNK(0, 0);
    cp_commit();

    for (int c = 0; c < nchunks; c++) {
        if (c + 1 < nchunks) {
            LOADCHUNK((c + 1) & 1, (c + 1) << 5);
            cp_commit();
            cp_wait1();
        } else {
            cp_wait0();
        }
        __syncthreads();

        uint32_t bufAh = sb + (c & 1) * BUF_BYTES;
        uint32_t bufAl = bufAh + CH_BYTES;
        uint32_t bufBh = bufAh + 2 * CH_BYTES;
        uint32_t bufBl = bufAh + 3 * CH_BYTES;

        #pragma unroll
        for (int ks = 0; ks < 32; ks += 16) {
            uint32_t kb = (uint32_t)(ks * 2);
            uint32_t bh[8], bl[8];
            ldsm4(bufBh + (uint32_t)(wn) * 80 + kb + offB, bh);
            ldsm4(bufBh + (uint32_t)(wn + 16) * 80 + kb + offB, bh + 4);
            ldsm4(bufBl + (uint32_t)(wn) * 80 + kb + offB, bl);
            ldsm4(bufBl + (uint32_t)(wn + 16) * 80 + kb + offB, bl + 4);
            #pragma unroll
            for (int mt = 0; mt < 4; mt++) {
                uint32_t ah[4], al[4];
                ldsm4(bufAh + (uint32_t)(wm + mt * 16) * 80 + kb + offA, ah);
                ldsm4(bufAl + (uint32_t)(wm + mt * 16) * 80 + kb + offA, al);
                #pragma unroll
                for (int nt = 0; nt < 4; nt++) {
                    mma_bf16(acc[mt][nt], ah, bh + nt * 2);
                    mma_bf16(acc[mt][nt], ah, bl + nt * 2);
                    mma_bf16(acc[mt][nt], al, bh + nt * 2);
                }
            }
        }
        __syncthreads();
    }

    #pragma unroll
    for (int mt = 0; mt < 4; mt++) {
        long r = m0 + wm + mt * 16 + g;
        #pragma unroll
        for (int nt = 0; nt < 4; nt++) {
            int c = n0 + wn + nt * 8 + tig * 2;
            float v0 = acc[mt][nt][0], v1 = acc[mt][nt][1];
            float v2 = acc[mt][nt][2], v3 = acc[mt][nt][3];
            if (bias) { v0 += bias[c]; v1 += bias[c + 1]; v2 += bias[c]; v3 += bias[c + 1]; }
            if (accumulate) {
                C[r * N + c]           += v0;
                C[r * N + c + 1]       += v1;
                C[(r + 8) * N + c]     += v2;
                C[(r + 8) * N + c + 1] += v3;
            } else {
                C[r * N + c]           = v0;
                C[r * N + c + 1]       = v1;
                C[(r + 8) * N + c]     = v2;
                C[(r + 8) * N + c + 1] = v3;
            }
        }
    }
}

// ---------------- elementwise ----------------
__global__ void copy_kernel(const float* __restrict__ src, float* __restrict__ dst, int n) {
    int i = blockIdx.x * blockDim.x + threadIdx.x;
    if (i < n) dst[i] = src[i];
}

// rmsnorm + bf16 split (fp32 out optional; hi/lo optional)
__global__ void rmsnorm_split(const float* __restrict__ x, const float* __restrict__ w,
                              float* __restrict__ outf,
                              __nv_bfloat16* __restrict__ hi, __nv_bfloat16* __restrict__ lo) {
    int tok = blockIdx.x;
    int tid = threadIdx.x;
    const float* xr = x + (long)tok * DIMV;
    float v0 = xr[tid], v1 = xr[tid + 256], v2 = xr[tid + 512];
    __shared__ float red[256];
    red[tid] = v0 * v0 + v1 * v1 + v2 * v2;
    __syncthreads();
    for (int off = 128; off > 0; off >>= 1) {
        if (tid < off) red[tid] += red[tid + off];
        __syncthreads();
    }
    float inv = rsqrtf(red[0] / (float)DIMV + 1e-6f);
    float r0 = v0 * inv * w[tid];
    float r1 = v1 * inv * w[tid + 256];
    float r2 = v2 * inv * w[tid + 512];
    long base = (long)tok * DIMV;
    if (outf) { outf[base + tid] = r0; outf[base + tid + 256] = r1; outf[base + tid + 512] = r2; }
    if (hi) {
        __nv_bfloat16 h0 = __float2bfloat16(r0), h1 = __float2bfloat16(r1), h2 = __float2bfloat16(r2);
        hi[base + tid] = h0; hi[base + tid + 256] = h1; hi[base + tid + 512] = h2;
        lo[base + tid]       = __float2bfloat16(r0 - __bfloat162float(h0));
        lo[base + tid + 256] = __float2bfloat16(r1 - __bfloat162float(h1));
        lo[base + tid + 512] = __float2bfloat16(r2 - __bfloat162float(h2));
    }
}

// ---------------- mix & gate projection: one warp per token ----------------
__global__ __launch_bounds__(128) void mixgate_kernel(
    const float* __restrict__ tn,
    const float* __restrict__ Wmix, const float* __restrict__ bmix,
    const float* __restrict__ Wg,
    float* __restrict__ mix, float* __restrict__ gate)
{
    int tok = blockIdx.x * 4 + (threadIdx.x >> 5);
    int lane = threadIdx.x & 31;
    const float* x = tn + (long)tok * DIMV;
    float t[24];
    #pragma unroll
    for (int e = 0; e < 24; e++) t[e] = x[lane + 32 * e];
    for (int col = 0; col < HEADS; col++) {
        float am = 0.f, ag = 0.f;
        #pragma unroll
        for (int e = 0; e < 24; e++) {
            int d = lane + 32 * e;
            am += t[e] * Wmix[d * HEADS + col];
            ag += t[e] * Wg[d * HEADS + col];
        }
        #pragma unroll
        for (int off = 16; off > 0; off >>= 1) {
            am += __shfl_xor_sync(0xffffffffu, am, off);
            ag += __shfl_xor_sync(0xffffffffu, ag, off);
        }
        if (lane == 0) {
            mix[tok * HEADS + col]  = 1.f / (1.f + __expf(-(am + bmix[col])));
            gate[tok * HEADS + col] = 1.f / (1.f + __expf(-ag));
        }
    }
}

__device__ __forceinline__ float softclamp(float acc) {
    // 50*tanh(acc*(1/8)*(1/50))
    float t = __expf(acc * 0.005f);
    return 50.f * __fdividef(t - 1.f, t + 1.f);
}

// ---------------- space attention (fused vlerp + knorm, one-pass, f32x2) ----------------
#define ASP_SMEM (2 * SS * DH * 4 + SS * 4)
__global__ __launch_bounds__(256, 1) void attn_space(
    const float* __restrict__ qkv, const float* __restrict__ rv,
    const float* __restrict__ mix, const float* __restrict__ gate,
    const float* __restrict__ kgam,
    __nv_bfloat16* __restrict__ ohi, __nv_bfloat16* __restrict__ olo)
{
    int r = blockIdx.x, h = blockIdx.y;
    long base = (long)r * SS;
    extern __shared__ float sm[];
    float* Ks = sm;
    float* Vs = sm + SS * DH;
    float* mixs = sm + 2 * SS * DH;
    int tid = threadIdx.x;

    if (tid < SS) mixs[tid] = mix[(base + tid) * HEADS + h];
    __syncthreads();

    for (int idx = tid; idx < SS * DH; idx += 256) {
        int j = idx >> 6, d = idx & 63;
        long tok = base + j;
        float vv = qkv[tok * QKVW + 1536 + h * DH + d];
        Vs[idx] = vv + mixs[j] * (rv[tok * DIMV + h * DH + d] - vv);
        Ks[idx] = qkv[tok * QKVW + 768 + h * DH + d];
    }
    __syncthreads();

    // normalize K rows
    {
        int wid = tid >> 5, lane = tid & 31;
        float g1 = (kgam[h * DH + lane] + 1.f) * 8.0f;
        float g2 = (kgam[h * DH + lane + 32] + 1.f) * 8.0f;
        for (int j = wid * 32; j < wid * 32 + 32; j++) {
            float a = Ks[j * DH + lane], b = Ks[j * DH + lane + 32];
            float ss = a * a + b * b;
            #pragma unroll
            for (int off = 16; off > 0; off >>= 1) ss += __shfl_xor_sync(0xffffffffu, ss, off);
            float inv = 1.f / fmaxf(sqrtf(ss), 1e-12f);
            Ks[j * DH + lane]      = a * inv * g1;
            Ks[j * DH + lane + 32] = b * inv * g2;
        }
    }
    __syncthreads();

    long mytok = base + tid;
    ull qr2[32];
    {
        const ull* qp = (const ull*)(qkv + mytok * QKVW + h * DH);
        #pragma unroll
        for (int e = 0; e < 32; e++) qr2[e] = qp[e];
    }

    float s = 0.f;
    ull oa[32];
    #pragma unroll
    for (int e = 0; e < 32; e++) oa[e] = 0ull;
    for (int j = 0; j < SS; j++) {
        const ull* kp = (const ull*)(Ks + j * DH);
        ull acc2 = 0ull;
        #pragma unroll
        for (int e = 0; e < 32; e++) FMA2(acc2, qr2[e], kp[e]);
        float p = __expf(softclamp(hsum2(acc2)));
        s += p;
        ull p2 = pack2(p);
        const ull* vp = (const ull*)(Vs + j * DH);
        #pragma unroll
        for (int e = 0; e < 32; e++) FMA2(oa[e], p2, vp[e]);
    }
    float gg = gate[mytok * HEADS + h] / s;
    long ob = mytok * DIMV + h * DH;
    #pragma unroll
    for (int e = 0; e < 32; e++) {
        float a, b;
        unpack2(oa[e], a, b);
        a *= gg; b *= gg;
        __nv_bfloat16 ha = __float2bfloat16(a), hb = __float2bfloat16(b);
        ohi[ob + e * 2]     = ha;
        ohi[ob + e * 2 + 1] = hb;
        olo[ob + e * 2]     = __float2bfloat16(a - __bfloat162float(ha));
        olo[ob + e * 2 + 1] = __float2bfloat16(b - __bfloat162float(hb));
    }
}

// ---------------- time attention (causal, fused vlerp + knorm + rotary, f32x2) ----------------
__global__ __launch_bounds__(32) void attn_time(
    const float* __restrict__ qkv, const float* __restrict__ rv,
    const float* __restrict__ mix, const float* __restrict__ gate,
    const float* __restrict__ kgam,
    __nv_bfloat16* __restrict__ ohi, __nv_bfloat16* __restrict__ olo)
{
    int r = blockIdx.x, h = blockIdx.y;
    int b = r / SS, s0 = r % SS;
    long base = (long)b * (TT * SS) + s0;
    __shared__ float Ks[TT * DH], Vs[TT * DH], mixs[TT];
    int tid = threadIdx.x;   // one warp

    mixs[tid] = mix[(base + (long)tid * SS) * HEADS + h];
    __syncwarp();
    for (int idx = tid; idx < TT * DH; idx += 32) {
        int j = idx >> 6, d = idx & 63;
        long tok = base + (long)j * SS;
        float vv = qkv[tok * QKVW + 1536 + h * DH + d];
        Vs[idx] = vv + mixs[j] * (rv[tok * DIMV + h * DH + d] - vv);
        Ks[idx] = qkv[tok * QKVW + 768 + h * DH + d];
    }
    __syncwarp();

    // normalize + rotary on K rows (key j has time index j)
    {
        float g1 = (kgam[h * DH + tid] + 1.f) * 8.0f;
        float g2 = (kgam[h * DH + tid + 32] + 1.f) * 8.0f;
        float invf = __powf(10000.0f, -(float)(2 * tid) / (float)DH);
        for (int j = 0; j < TT; j++) {
            float a = Ks[j * DH + tid], b2 = Ks[j * DH + tid + 32];
            float ss = a * a + b2 * b2;
            #pragma unroll
            for (int off = 16; off > 0; off >>= 1) ss += __shfl_xor_sync(0xffffffffu, ss, off);
            float inv = 1.f / fmaxf(sqrtf(ss), 1e-12f);
            a = a * inv * g1;
            b2 = b2 * inv * g2;
            float ang = (float)j * invf;
            float cc = cosf(ang), sn = sinf(ang);
            Ks[j * DH + tid]      = a * cc - b2 * sn;
            Ks[j * DH + tid + 32] = b2 * cc + a * sn;
        }
    }
    __syncwarp();

    long mytok = base + (long)tid * SS;
    float qf[64];
    {
        const float4* qp = (const float4*)(qkv + mytok * QKVW + h * DH);
        #pragma unroll
        for (int e = 0; e < 16; e++) ((float4*)qf)[e] = qp[e];
        #pragma unroll
        for (int d = 0; d < 32; d++) {
            float invf = __powf(10000.0f, -(float)(2 * d) / (float)DH);
            float ang = (float)tid * invf;
            float cc = cosf(ang), sn = sinf(ang);
            float x1 = qf[d], x2 = qf[d + 32];
            qf[d]      = x1 * cc - x2 * sn;
            qf[d + 32] = x2 * cc + x1 * sn;
        }
    }
    ull qr2[32];
    #pragma unroll
    for (int e = 0; e < 32; e++) qr2[e] = ((const ull*)qf)[e];

    int nkeys = tid + 1;   // causal
    float s = 0.f;
    ull oa[32];
    #pragma unroll
    for (int e = 0; e < 32; e++) oa[e] = 0ull;
    for (int j = 0; j < nkeys; j++) {
        const ull* kp = (const ull*)(Ks + j * DH);
        ull acc2 = 0ull;
        #pragma unroll
        for (int e = 0; e < 32; e++) FMA2(acc2, qr2[e], kp[e]);
        float p = __expf(softclamp(hsum2(acc2)));
        s += p;
        ull p2 = pack2(p);
        const ull* vp = (const ull*)(Vs + j * DH);
        #pragma unroll
        for (int e = 0; e < 32; e++) FMA2(oa[e], p2, vp[e]);
    }
    float gg = gate[mytok * HEADS + h] / s;
    long ob = mytok * DIMV + h * DH;
    #pragma unroll
    for (int e = 0; e < 32; e++) {
        float a, b;
        unpack2(oa[e], a, b);
        a *= gg; b *= gg;
        __nv_bfloat16 ha = __float2bfloat16(a), hb = __float2bfloat16(b);
        ohi[ob + e * 2]     = ha;
        ohi[ob + e * 2 + 1] = hb;
        olo[ob + e * 2]     = __float2bfloat16(a - __bfloat162float(ha));
        olo[ob + e * 2 + 1] = __float2bfloat16(b - __bfloat162float(hb));
    }
}

// ---------------- a * gelu(g) -> bf16 split ----------------
__global__ void act_split(const float* __restrict__ h,
                          __nv_bfloat16* __restrict__ hi, __nv_bfloat16* __restrict__ lo) {
    int idx = blockIdx.x * blockDim.x + threadIdx.x;
    if (idx >= NTOK * DFF) return;
    int tok = idx / DFF;
    int c = idx % DFF;
    float a = h[(long)tok * (2 * DFF) + c];
    float g = h[(long)tok * (2 * DFF) + DFF + c];
    float r = a * 0.5f * g * (1.f + erff(g * 0.70710678118654752f));
    __nv_bfloat16 hh = __float2bfloat16(r);
    hi[idx] = hh;
    lo[idx] = __float2bfloat16(r - __bfloat162float(hh));
}

// ---------------- launch ----------------
extern "C" void kernel_launch(void* const* d_in, const int* in_sizes, int n_in,
                              void* d_out, int out_size) {
    const float* tokens      = (const float*)d_in[0];
    const float* attn_norm_w = (const float*)d_in[1];
    const float* Wq          = (const float*)d_in[2];
    const float* Wk          = (const float*)d_in[3];
    const float* Wv          = (const float*)d_in[4];
    const float* Wo          = (const float*)d_in[5];
    const float* Wg          = (const float*)d_in[6];
    const float* Wmix        = (const float*)d_in[7];
    const float* bmix        = (const float*)d_in[8];
    const float* kgam        = (const float*)d_in[9];
    const float* ff_norm_w   = (const float*)d_in[10];
    const float* Win         = (const float*)d_in[11];
    const float* bi_in       = (const float*)d_in[12];
    const float* Wout        = (const float*)d_in[13];
    const float* b_out       = (const float*)d_in[14];
    const float* vr_norm_w   = (const float*)d_in[15];
    const float* vr_W        = (const float*)d_in[16];
    const float* final_norm_w= (const float*)d_in[17];

    float *x, *tn, *qkv, *rv, *h, *mix, *gate;
    __nv_bfloat16 *wthi, *wtlo, *ahi, *alo;
    cudaGetSymbolAddress((void**)&x,   g_x);
    cudaGetSymbolAddress((void**)&tn,  g_tn);
    cudaGetSymbolAddress((void**)&qkv, g_qkv);
    cudaGetSymbolAddress((void**)&rv,  g_rv);
    cudaGetSymbolAddress((void**)&h,   g_h);
    cudaGetSymbolAddress((void**)&mix, g_mix);
    cudaGetSymbolAddress((void**)&gate,g_gate);
    cudaGetSymbolAddress((void**)&wthi,g_wthi);
    cudaGetSymbolAddress((void**)&wtlo,g_wtlo);
    cudaGetSymbolAddress((void**)&ahi, g_ahi);
    cudaGetSymbolAddress((void**)&alo, g_alo);

    static int attr_done = 0;
    if (!attr_done) {
        cudaFuncSetAttribute(gemm_bf16, cudaFuncAttributeMaxDynamicSharedMemorySize, GEMM_SMEM);
        cudaFuncSetAttribute(attn_space, cudaFuncAttributeMaxDynamicSharedMemorySize, ASP_SMEM);
        attr_done = 1;
    }

    const int NTOT = NTOK * DIMV;
    dim3 ts_blk(32, 8);

    // ---- transpose-split all weights ----
    tsplit_kernel<<<dim3(768/32, 768/32), ts_blk>>>(vr_W, wthi, wtlo, 768, 768);
    for (int i = 0; i < 8; i++) {
        size_t lb = SZ_SQ + (size_t)i * SZ_LAYER;
        tsplit_kernel<<<dim3(768/32, 768/32), ts_blk>>>(Wq + (long)i*SZ_SQ,  wthi + lb,           wtlo + lb,           768, 768);
        tsplit_kernel<<<dim3(768/32, 768/32), ts_blk>>>(Wk + (long)i*SZ_SQ,  wthi + lb + SZ_SQ,   wtlo + lb + SZ_SQ,   768, 768);
        tsplit_kernel<<<dim3(768/32, 768/32), ts_blk>>>(Wv + (long)i*SZ_SQ,  wthi + lb + 2*SZ_SQ, wtlo + lb + 2*SZ_SQ, 768, 768);
        tsplit_kernel<<<dim3(768/32, 768/32), ts_blk>>>(Wo + (long)i*SZ_SQ,  wthi + lb + 3*SZ_SQ, wtlo + lb + 3*SZ_SQ, 768, 768);
        tsplit_kernel<<<dim3(4096/32, 768/32), ts_blk>>>(Win + (long)i*SZ_WIN, wthi + lb + 4*SZ_SQ, wtlo + lb + 4*SZ_SQ, 768, 4096);
        tsplit_kernel<<<dim3(768/32, 2048/32), ts_blk>>>(Wout + (long)i*SZ_WOUT, wthi + lb + 4*SZ_SQ + SZ_WIN, wtlo + lb + 4*SZ_SQ + SZ_WIN, 2048, 768);
    }

    copy_kernel<<<(NTOT + 255) / 256, 256>>>(tokens, x, NTOT);

    // value residual: rv = rmsnorm(tokens) @ vr_W
    rmsnorm_split<<<NTOK, 256>>>(tokens, vr_norm_w, nullptr, ahi, alo);
    gemm_bf16<<<dim3(6, 128), 256, GEMM_SMEM>>>(ahi, alo, wthi, wtlo, nullptr, rv, DIMV, DIMV, 0);

    for (int i = 0; i < 8; i++) {
        size_t lb = SZ_SQ + (size_t)i * SZ_LAYER;
        const __nv_bfloat16* wh = wthi + lb;
        const __nv_bfloat16* wl = wtlo + lb;
        const float* aw   = attn_norm_w + (long)i * DIMV;
        const float* wg   = Wg   + (long)i * DIMV * HEADS;
        const float* wmix = Wmix + (long)i * DIMV * HEADS;
        const float* bm   = bmix + (long)i * HEADS;
        const float* kg   = kgam + (long)i * HEADS * DH;
        const float* fw   = ff_norm_w + (long)i * DIMV;
        const float* bi   = bi_in + (long)i * (2 * DFF);
        const float* bo   = b_out + (long)i * DIMV;
        int is_time = ((i + 1) % 4 == 0) ? 1 : 0;

        // attention block
        rmsnorm_split<<<NTOK, 256>>>(x, aw, tn, ahi, alo);
        gemm_bf16<<<dim3(18, 128), 256, GEMM_SMEM>>>(ahi, alo, wh, wl, nullptr, qkv, QKVW, DIMV, 0);
        mixgate_kernel<<<NTOK / 4, 128>>>(tn, wmix, bm, wg, mix, gate);
        if (is_time) attn_time<<<dim3(NTOK / TT, HEADS), 32>>>(qkv, rv, mix, gate, kg, ahi, alo);
        else         attn_space<<<dim3(NTOK / SS, HEADS), 256, ASP_SMEM>>>(qkv, rv, mix, gate, kg, ahi, alo);
        gemm_bf16<<<dim3(6, 128), 256, GEMM_SMEM>>>(ahi, alo, wh + 3*SZ_SQ, wl + 3*SZ_SQ, nullptr, x, DIMV, DIMV, 1);

        // feed-forward block
        rmsnorm_split<<<NTOK, 256>>>(x, fw, nullptr, ahi, alo);
        gemm_bf16<<<dim3(32, 128), 256, GEMM_SMEM>>>(ahi, alo, wh + 4*SZ_SQ, wl + 4*SZ_SQ, bi, h, 2 * DFF, DIMV, 0);
        act_split<<<(NTOK * DFF + 255) / 256, 256>>>(h, ahi, alo);
        gemm_bf16<<<dim3(6, 128), 256, GEMM_SMEM>>>(ahi, alo, wh + 4*SZ_SQ + SZ_WIN, wl + 4*SZ_SQ + SZ_WIN, bo, x, DIMV, DFF, 1);
    }

    rmsnorm_split<<<NTOK, 256>>>(x, final_norm_w, (float*)d_out, nullptr, nullptr);
}

// round 13
// speedup vs baseline: 6.9633x; 1.2553x over previous
#include <cuda_runtime.h>
#include <cuda_fp16.h>
#include <math.h>
#include <stdint.h>

#define NTOK 16384   // B*T*S = 2*32*256
#define DIMV 768
#define HEADS 12
#define DH 64
#define DFF 2048
#define TT 32
#define SS 256
#define QKVW 2304

// weight sizes
#define SZ_SQ   (768*768)
#define SZ_WIN  (768*4096)
#define SZ_WOUT (2048*768)
#define SZ_LAYER (4*SZ_SQ + SZ_WIN + SZ_WOUT)
#define SZ_WTOT (SZ_SQ + 8*SZ_LAYER)

// ---------------- scratch ----------------
__device__ float g_x[NTOK * DIMV];
__device__ float g_tn[NTOK * DIMV];
__device__ float g_qkv[NTOK * QKVW];
__device__ float g_rv[NTOK * DIMV];
__device__ float g_mix[NTOK * HEADS];
__device__ float g_gate[NTOK * HEADS];
__device__ __half g_wthi[SZ_WTOT];
__device__ __half g_ahi[NTOK * DFF];
__device__ __half g_alo[NTOK * DFF];
__device__ __half g_bhi[NTOK * DFF];   // act-fused FFin output (separate: no aliasing)
__device__ __half g_blo[NTOK * DFF];

// ---------------- packed f32x2 helpers ----------------
typedef unsigned long long ull;
#define FMA2(acc, a, b) \
    asm("fma.rn.f32x2 %0, %1, %2, %0;" : "+l"(acc) : "l"(a), "l"(b))
__device__ __forceinline__ ull pack2(float x) {
    ull r;
    asm("mov.b64 %0, {%1, %1};" : "=l"(r) : "r"(__float_as_uint(x)));
    return r;
}
__device__ __forceinline__ float hsum2(ull v) {
    uint32_t lo, hi;
    asm("mov.b64 {%0, %1}, %2;" : "=r"(lo), "=r"(hi) : "l"(v));
    return __uint_as_float(lo) + __uint_as_float(hi);
}
__device__ __forceinline__ void unpack2(ull v, float& a, float& b) {
    uint32_t lo, hi;
    asm("mov.b64 {%0, %1}, %2;" : "=r"(lo), "=r"(hi) : "l"(v));
    a = __uint_as_float(lo); b = __uint_as_float(hi);
}

// ==================== weight transpose (fp16) ====================
__global__ void tsplit_kernel(const float* __restrict__ W,
                              __half* __restrict__ hi, int K, int N) {
    __shared__ float tile[32][33];
    int bn = blockIdx.x * 32, bk = blockIdx.y * 32;
    int tx = threadIdx.x, ty = threadIdx.y;
    #pragma unroll
    for (int i = ty; i < 32; i += 8)
        tile[i][tx] = W[(long)(bk + i) * N + bn + tx];
    __syncthreads();
    #pragma unroll
    for (int i = ty; i < 32; i += 8) {
        float x = tile[tx][i];
        hi[(long)(bn + i) * K + bk + tx] = __float2half_rn(x);
    }
}

// ==================== fp16 HMMA GEMM: 2-term (A hi/lo, B hi) ====================
#define CH_BYTES 10240
#define BUF_BYTES (3 * CH_BYTES)
#define GEMM_SMEM (2 * BUF_BYTES)

__device__ __forceinline__ uint32_t smem_u32(const void* p) {
    uint32_t a;
    asm("{ .reg .u64 t; cvta.to.shared.u64 t, %1; cvt.u32.u64 %0, t; }" : "=r"(a) : "l"(p));
    return a;
}
__device__ __forceinline__ void cp16(uint32_t dst, const void* src) {
    asm volatile("cp.async.ca.shared.global [%0], [%1], 16;" :: "r"(dst), "l"(src));
}
__device__ __forceinline__ void cp_commit() { asm volatile("cp.async.commit_group;"); }
__device__ __forceinline__ void cp_wait1() { asm volatile("cp.async.wait_group 1;"); }
__device__ __forceinline__ void cp_wait0() { asm volatile("cp.async.wait_group 0;"); }

__device__ __forceinline__ void mma_f16(float* d, const uint32_t* a, const uint32_t* b) {
    asm volatile(
        "mma.sync.aligned.m16n8k16.row.col.f32.f16.f16.f32 "
        "{%0,%1,%2,%3}, {%4,%5,%6,%7}, {%8,%9}, {%0,%1,%2,%3};"
        : "+f"(d[0]), "+f"(d[1]), "+f"(d[2]), "+f"(d[3])
        : "r"(a[0]), "r"(a[1]), "r"(a[2]), "r"(a[3]), "r"(b[0]), "r"(b[1]));
}
__device__ __forceinline__ void ldsm4(uint32_t addr, uint32_t* d) {
    asm volatile("ldmatrix.sync.aligned.m8n8.x4.shared.b16 {%0,%1,%2,%3}, [%4];"
                 : "=r"(d[0]), "=r"(d[1]), "=r"(d[2]), "=r"(d[3]) : "r"(addr));
}
__device__ __forceinline__ int brow_map(int j, int ilv) {
    return ilv ? ((j & 1) ? (DFF + (j >> 1)) : (j >> 1)) : j;
}

__global__ __launch_bounds__(256, 2) void gemm_f16(
    const __half* __restrict__ Ah, const __half* __restrict__ Al,
    const __half* __restrict__ Bh,
    const float* __restrict__ bias, float* __restrict__ C,
    __half* __restrict__ aout_hi, __half* __restrict__ aout_lo,
    int N, int K, int accumulate, int actfuse, int ilv)
{
    extern __shared__ char smem[];
    uint32_t sb = smem_u32(smem);
    int tid = threadIdx.x, wid = tid >> 5, lane = tid & 31;
    int m0 = blockIdx.y * 128, n0 = blockIdx.x * 128;
    int wm = (wid & 1) * 64, wn = (wid >> 1) * 32;
    int g = lane >> 2, tig = lane & 3;
    int mi = lane >> 3, r8 = lane & 7;
    uint32_t offA = (uint32_t)(((mi & 1) * 8 + r8) * 80 + (mi >> 1) * 16);
    uint32_t offB = (uint32_t)(((mi >> 1) * 8 + r8) * 80 + (mi & 1) * 16);

    float acc[4][4][4];
    #pragma unroll
    for (int mt = 0; mt < 4; mt++)
        #pragma unroll
        for (int nt = 0; nt < 4; nt++)
            #pragma unroll
            for (int e = 0; e < 4; e++) acc[mt][nt][e] = 0.f;

    int nchunks = K >> 5;
    int r0 = tid >> 2, s0 = (tid & 3) * 8;
    int r1 = r0 + 64, s1 = s0;
    int bR0 = brow_map(n0 + r0, ilv);
    int bR1 = brow_map(n0 + r1, ilv);

    #define LOADCHUNK(b, kc_) do {                                                     \
        uint32_t base = sb + (b) * BUF_BYTES;                                          \
        cp16(base + r0 * 80 + (s0 << 1),                Ah + (long)(m0 + r0) * K + (kc_) + s0); \
        cp16(base + CH_BYTES + r0 * 80 + (s0 << 1),     Al + (long)(m0 + r0) * K + (kc_) + s0); \
        cp16(base + 2 * CH_BYTES + r0 * 80 + (s0 << 1), Bh + (long)bR0 * K + (kc_) + s0); \
        cp16(base + r1 * 80 + (s1 << 1),                Ah + (long)(m0 + r1) * K + (kc_) + s1); \
        cp16(base + CH_BYTES + r1 * 80 + (s1 << 1),     Al + (long)(m0 + r1) * K + (kc_) + s1); \
        cp16(base + 2 * CH_BYTES + r1 * 80 + (s1 << 1), Bh + (long)bR1 * K + (kc_) + s1); \
    } while (0)

    LOADCHUNK(0, 0);
    cp_commit();

    for (int c = 0; c < nchunks; c++) {
        if (c + 1 < nchunks) {
            LOADCHUNK((c + 1) & 1, (c + 1) << 5);
            cp_commit();
            cp_wait1();
        } else {
            cp_wait0();
        }
        __syncthreads();

        uint32_t bufAh = sb + (c & 1) * BUF_BYTES;
        uint32_t bufAl = bufAh + CH_BYTES;
        uint32_t bufBh = bufAh + 2 * CH_BYTES;

        #pragma unroll
        for (int ks = 0; ks < 32; ks += 16) {
            uint32_t kb = (uint32_t)(ks * 2);
            uint32_t bh[8];
            ldsm4(bufBh + (uint32_t)(wn) * 80 + kb + offB, bh);
            ldsm4(bufBh + (uint32_t)(wn + 16) * 80 + kb + offB, bh + 4);
            #pragma unroll
            for (int mt = 0; mt < 4; mt++) {
                uint32_t ah[4], al[4];
                ldsm4(bufAh + (uint32_t)(wm + mt * 16) * 80 + kb + offA, ah);
                ldsm4(bufAl + (uint32_t)(wm + mt * 16) * 80 + kb + offA, al);
                #pragma unroll
                for (int nt = 0; nt < 4; nt++) {
                    mma_f16(acc[mt][nt], ah, bh + nt * 2);
                    mma_f16(acc[mt][nt], al, bh + nt * 2);
                }
            }
        }
        __syncthreads();
    }

    if (actfuse) {
        // columns are interleaved (a,g) pairs; compute a*gelu(g), write fp16 hi/lo
        #pragma unroll
        for (int mt = 0; mt < 4; mt++) {
            long r = m0 + wm + mt * 16 + g;
            #pragma unroll
            for (int nt = 0; nt < 4; nt++) {
                int pair = ((n0 + wn + nt * 8) >> 1) + tig;
                float ba = bias ? bias[pair] : 0.f;
                float bg = bias ? bias[DFF + pair] : 0.f;
                #pragma unroll
                for (int half = 0; half < 2; half++) {
                    float a = acc[mt][nt][half * 2] + ba;
                    float gg = acc[mt][nt][half * 2 + 1] + bg;
                    float rr = a * 0.5f * gg * (1.f + erff(gg * 0.70710678118654752f));
                    long idx = (r + half * 8) * DFF + pair;
                    __half hh = __float2half_rn(rr);
                    aout_hi[idx] = hh;
                    aout_lo[idx] = __float2half_rn(rr - __half2float(hh));
                }
            }
        }
    } else {
        #pragma unroll
        for (int mt = 0; mt < 4; mt++) {
            long r = m0 + wm + mt * 16 + g;
            #pragma unroll
            for (int nt = 0; nt < 4; nt++) {
                int c = n0 + wn + nt * 8 + tig * 2;
                float v0 = acc[mt][nt][0], v1 = acc[mt][nt][1];
                float v2 = acc[mt][nt][2], v3 = acc[mt][nt][3];
                if (bias) { v0 += bias[c]; v1 += bias[c + 1]; v2 += bias[c]; v3 += bias[c + 1]; }
                if (accumulate) {
                    C[r * N + c]           += v0;
                    C[r * N + c + 1]       += v1;
                    C[(r + 8) * N + c]     += v2;
                    C[(r + 8) * N + c + 1] += v3;
                } else {
                    C[r * N + c]           = v0;
                    C[r * N + c + 1]       = v1;
                    C[(r + 8) * N + c]     = v2;
                    C[(r + 8) * N + c + 1] = v3;
                }
            }
        }
    }
}

// ---------------- elementwise ----------------
__global__ void copy_kernel(const float* __restrict__ src, float* __restrict__ dst, int n) {
    int i = blockIdx.x * blockDim.x + threadIdx.x;
    if (i < n) dst[i] = src[i];
}

// rmsnorm + fp16 split
__global__ void rmsnorm_split(const float* __restrict__ x, const float* __restrict__ w,
                              float* __restrict__ outf,
                              __half* __restrict__ hi, __half* __restrict__ lo) {
    int tok = blockIdx.x;
    int tid = threadIdx.x;
    const float* xr = x + (long)tok * DIMV;
    float v0 = xr[tid], v1 = xr[tid + 256], v2 = xr[tid + 512];
    __shared__ float red[256];
    red[tid] = v0 * v0 + v1 * v1 + v2 * v2;
    __syncthreads();
    for (int off = 128; off > 0; off >>= 1) {
        if (tid < off) red[tid] += red[tid + off];
        __syncthreads();
    }
    float inv = rsqrtf(red[0] / (float)DIMV + 1e-6f);
    float r0 = v0 * inv * w[tid];
    float r1 = v1 * inv * w[tid + 256];
    float r2 = v2 * inv * w[tid + 512];
    long base = (long)tok * DIMV;
    if (outf) { outf[base + tid] = r0; outf[base + tid + 256] = r1; outf[base + tid + 512] = r2; }
    if (hi) {
        __half h0 = __float2half_rn(r0), h1 = __float2half_rn(r1), h2 = __float2half_rn(r2);
        hi[base + tid] = h0; hi[base + tid + 256] = h1; hi[base + tid + 512] = h2;
        lo[base + tid]       = __float2half_rn(r0 - __half2float(h0));
        lo[base + tid + 256] = __float2half_rn(r1 - __half2float(h1));
        lo[base + tid + 512] = __float2half_rn(r2 - __half2float(h2));
    }
}

// ---------------- mix & gate projection ----------------
__global__ __launch_bounds__(128) void mixgate_kernel(
    const float* __restrict__ tn,
    const float* __restrict__ Wmix, const float* __restrict__ bmix,
    const float* __restrict__ Wg,
    float* __restrict__ mix, float* __restrict__ gate)
{
    int tok = blockIdx.x * 4 + (threadIdx.x >> 5);
    int lane = threadIdx.x & 31;
    const float* x = tn + (long)tok * DIMV;
    float t[24];
    #pragma unroll
    for (int e = 0; e < 24; e++) t[e] = x[lane + 32 * e];
    for (int col = 0; col < HEADS; col++) {
        float am = 0.f, ag = 0.f;
        #pragma unroll
        for (int e = 0; e < 24; e++) {
            int d = lane + 32 * e;
            am += t[e] * Wmix[d * HEADS + col];
            ag += t[e] * Wg[d * HEADS + col];
        }
        #pragma unroll
        for (int off = 16; off > 0; off >>= 1) {
            am += __shfl_xor_sync(0xffffffffu, am, off);
            ag += __shfl_xor_sync(0xffffffffu, ag, off);
        }
        if (lane == 0) {
            mix[tok * HEADS + col]  = 1.f / (1.f + __expf(-(am + bmix[col])));
            gate[tok * HEADS + col] = 1.f / (1.f + __expf(-ag));
        }
    }
}

__device__ __forceinline__ float softclamp(float acc) {
    float t = __expf(acc * 0.005f);
    return 50.f * __fdividef(t - 1.f, t + 1.f);
}

// ---------------- space attention ----------------
#define ASP_SMEM (2 * SS * DH * 4 + SS * 4)
__global__ __launch_bounds__(256, 1) void attn_space(
    const float* __restrict__ qkv, const float* __restrict__ rv,
    const float* __restrict__ mix, const float* __restrict__ gate,
    const float* __restrict__ kgam,
    __half* __restrict__ ohi, __half* __restrict__ olo)
{
    int r = blockIdx.x, h = blockIdx.y;
    long base = (long)r * SS;
    extern __shared__ float sm[];
    float* Ks = sm;
    float* Vs = sm + SS * DH;
    float* mixs = sm + 2 * SS * DH;
    int tid = threadIdx.x;

    if (tid < SS) mixs[tid] = mix[(base + tid) * HEADS + h];
    __syncthreads();

    for (int idx = tid; idx < SS * DH; idx += 256) {
        int j = idx >> 6, d = idx & 63;
        long tok = base + j;
        float vv = qkv[tok * QKVW + 1536 + h * DH + d];
        Vs[idx] = vv + mixs[j] * (rv[tok * DIMV + h * DH + d] - vv);
        Ks[idx] = qkv[tok * QKVW + 768 + h * DH + d];
    }
    __syncthreads();

    {
        int wid = tid >> 5, lane = tid & 31;
        float g1 = (kgam[h * DH + lane] + 1.f) * 8.0f;
        float g2 = (kgam[h * DH + lane + 32] + 1.f) * 8.0f;
        for (int j = wid * 32; j < wid * 32 + 32; j++) {
            float a = Ks[j * DH + lane], b = Ks[j * DH + lane + 32];
            float ss = a * a + b * b;
            #pragma unroll
            for (int off = 16; off > 0; off >>= 1) ss += __shfl_xor_sync(0xffffffffu, ss, off);
            float inv = 1.f / fmaxf(sqrtf(ss), 1e-12f);
            Ks[j * DH + lane]      = a * inv * g1;
            Ks[j * DH + lane + 32] = b * inv * g2;
        }
    }
    __syncthreads();

    long mytok = base + tid;
    ull qr2[32];
    {
        const ull* qp = (const ull*)(qkv + mytok * QKVW + h * DH);
        #pragma unroll
        for (int e = 0; e < 32; e++) qr2[e] = qp[e];
    }

    float s = 0.f;
    ull oa[32];
    #pragma unroll
    for (int e = 0; e < 32; e++) oa[e] = 0ull;
    for (int j = 0; j < SS; j++) {
        const ull* kp = (const ull*)(Ks + j * DH);
        ull acc2 = 0ull;
        #pragma unroll
        for (int e = 0; e < 32; e++) FMA2(acc2, qr2[e], kp[e]);
        float p = __expf(softclamp(hsum2(acc2)));
        s += p;
        ull p2 = pack2(p);
        const ull* vp = (const ull*)(Vs + j * DH);
        #pragma unroll
        for (int e = 0; e < 32; e++) FMA2(oa[e], p2, vp[e]);
    }
    float gg = gate[mytok * HEADS + h] / s;
    long ob = mytok * DIMV + h * DH;
    #pragma unroll
    for (int e = 0; e < 32; e++) {
        float a, b;
        unpack2(oa[e], a, b);
        a *= gg; b *= gg;
        __half ha = __float2half_rn(a), hb = __float2half_rn(b);
        ohi[ob + e * 2]     = ha;
        ohi[ob + e * 2 + 1] = hb;
        olo[ob + e * 2]     = __float2half_rn(a - __half2float(ha));
        olo[ob + e * 2 + 1] = __float2half_rn(b - __half2float(hb));
    }
}

// ---------------- time attention (causal) ----------------
__global__ __launch_bounds__(32) void attn_time(
    const float* __restrict__ qkv, const float* __restrict__ rv,
    const float* __restrict__ mix, const float* __restrict__ gate,
    const float* __restrict__ kgam,
    __half* __restrict__ ohi, __half* __restrict__ olo)
{
    int r = blockIdx.x, h = blockIdx.y;
    int b = r / SS, s0 = r % SS;
    long base = (long)b * (TT * SS) + s0;
    __shared__ float Ks[TT * DH], Vs[TT * DH], mixs[TT];
    int tid = threadIdx.x;

    mixs[tid] = mix[(base + (long)tid * SS) * HEADS + h];
    __syncwarp();
    for (int idx = tid; idx < TT * DH; idx += 32) {
        int j = idx >> 6, d = idx & 63;
        long tok = base + (long)j * SS;
        float vv = qkv[tok * QKVW + 1536 + h * DH + d];
        Vs[idx] = vv + mixs[j] * (rv[tok * DIMV + h * DH + d] - vv);
        Ks[idx] = qkv[tok * QKVW + 768 + h * DH + d];
    }
    __syncwarp();

    {
        float g1 = (kgam[h * DH + tid] + 1.f) * 8.0f;
        float g2 = (kgam[h * DH + tid + 32] + 1.f) * 8.0f;
        float invf = __powf(10000.0f, -(float)(2 * tid) / (float)DH);
        for (int j = 0; j < TT; j++) {
            float a = Ks[j * DH + tid], b2 = Ks[j * DH + tid + 32];
            float ss = a * a + b2 * b2;
            #pragma unroll
            for (int off = 16; off > 0; off >>= 1) ss += __shfl_xor_sync(0xffffffffu, ss, off);
            float inv = 1.f / fmaxf(sqrtf(ss), 1e-12f);
            a = a * inv * g1;
            b2 = b2 * inv * g2;
            float ang = (float)j * invf;
            float cc = cosf(ang), sn = sinf(ang);
            Ks[j * DH + tid]      = a * cc - b2 * sn;
            Ks[j * DH + tid + 32] = b2 * cc + a * sn;
        }
    }
    __syncwarp();

    long mytok = base + (long)tid * SS;
    float qf[64];
    {
        const float4* qp = (const float4*)(qkv + mytok * QKVW + h * DH);
        #pragma unroll
        for (int e = 0; e < 16; e++) ((float4*)qf)[e] = qp[e];
        #pragma unroll
        for (int d = 0; d < 32; d++) {
            float invf = __powf(10000.0f, -(float)(2 * d) / (float)DH);
            float ang = (float)tid * invf;
            float cc = cosf(ang), sn = sinf(ang);
            float x1 = qf[d], x2 = qf[d + 32];
            qf[d]      = x1 * cc - x2 * sn;
            qf[d + 32] = x2 * cc + x1 * sn;
        }
    }
    ull qr2[32];
    #pragma unroll
    for (int e = 0; e < 32; e++) qr2[e] = ((const ull*)qf)[e];

    int nkeys = tid + 1;
    float s = 0.f;
    ull oa[32];
    #pragma unroll
    for (int e = 0; e < 32; e++) oa[e] = 0ull;
    for (int j = 0; j < nkeys; j++) {
        const ull* kp = (const ull*)(Ks + j * DH);
        ull acc2 = 0ull;
        #pragma unroll
        for (int e = 0; e < 32; e++) FMA2(acc2, qr2[e], kp[e]);
        float p = __expf(softclamp(hsum2(acc2)));
        s += p;
        ull p2 = pack2(p);
        const ull* vp = (const ull*)(Vs + j * DH);
        #pragma unroll
        for (int e = 0; e < 32; e++) FMA2(oa[e], p2, vp[e]);
    }
    float gg = gate[mytok * HEADS + h] / s;
    long ob = mytok * DIMV + h * DH;
    #pragma unroll
    for (int e = 0; e < 32; e++) {
        float a, b;
        unpack2(oa[e], a, b);
        a *= gg; b *= gg;
        __half ha = __float2half_rn(a), hb = __float2half_rn(b);
        ohi[ob + e * 2]     = ha;
        ohi[ob + e * 2 + 1] = hb;
        olo[ob + e * 2]     = __float2half_rn(a - __half2float(ha));
        olo[ob + e * 2 + 1] = __float2half_rn(b - __half2float(hb));
    }
}

// ---------------- launch ----------------
extern "C" void kernel_launch(void* const* d_in, const int* in_sizes, int n_in,
                              void* d_out, int out_size) {
    const float* tokens      = (const float*)d_in[0];
    const float* attn_norm_w = (const float*)d_in[1];
    const float* Wq          = (const float*)d_in[2];
    const float* Wk          = (const float*)d_in[3];
    const float* Wv          = (const float*)d_in[4];
    const float* Wo          = (const float*)d_in[5];
    const float* Wg          = (const float*)d_in[6];
    const float* Wmix        = (const float*)d_in[7];
    const float* bmix        = (const float*)d_in[8];
    const float* kgam        = (const float*)d_in[9];
    const float* ff_norm_w   = (const float*)d_in[10];
    const float* Win         = (const float*)d_in[11];
    const float* bi_in       = (const float*)d_in[12];
    const float* Wout        = (const float*)d_in[13];
    const float* b_out       = (const float*)d_in[14];
    const float* vr_norm_w   = (const float*)d_in[15];
    const float* vr_W        = (const float*)d_in[16];
    const float* final_norm_w= (const float*)d_in[17];

    float *x, *tn, *qkv, *rv, *mix, *gate;
    __half *wthi, *ahi, *alo, *bhi, *blo;
    cudaGetSymbolAddress((void**)&x,   g_x);
    cudaGetSymbolAddress((void**)&tn,  g_tn);
    cudaGetSymbolAddress((void**)&qkv, g_qkv);
    cudaGetSymbolAddress((void**)&rv,  g_rv);
    cudaGetSymbolAddress((void**)&mix, g_mix);
    cudaGetSymbolAddress((void**)&gate,g_gate);
    cudaGetSymbolAddress((void**)&wthi,g_wthi);
    cudaGetSymbolAddress((void**)&ahi, g_ahi);
    cudaGetSymbolAddress((void**)&alo, g_alo);
    cudaGetSymbolAddress((void**)&bhi, g_bhi);
    cudaGetSymbolAddress((void**)&blo, g_blo);

    static int attr_done = 0;
    if (!attr_done) {
        cudaFuncSetAttribute(gemm_f16, cudaFuncAttributeMaxDynamicSharedMemorySize, GEMM_SMEM);
        cudaFuncSetAttribute(attn_space, cudaFuncAttributeMaxDynamicSharedMemorySize, ASP_SMEM);
        attr_done = 1;
    }

    const int NTOT = NTOK * DIMV;
    dim3 ts_blk(32, 8);

    // ---- transpose weights to fp16 [N][K] ----
    tsplit_kernel<<<dim3(768/32, 768/32), ts_blk>>>(vr_W, wthi, 768, 768);
    for (int i = 0; i < 8; i++) {
        size_t lb = SZ_SQ + (size_t)i * SZ_LAYER;
        tsplit_kernel<<<dim3(768/32, 768/32), ts_blk>>>(Wq + (long)i*SZ_SQ,  wthi + lb,           768, 768);
        tsplit_kernel<<<dim3(768/32, 768/32), ts_blk>>>(Wk + (long)i*SZ_SQ,  wthi + lb + SZ_SQ,   768, 768);
        tsplit_kernel<<<dim3(768/32, 768/32), ts_blk>>>(Wv + (long)i*SZ_SQ,  wthi + lb + 2*SZ_SQ, 768, 768);
        tsplit_kernel<<<dim3(768/32, 768/32), ts_blk>>>(Wo + (long)i*SZ_SQ,  wthi + lb + 3*SZ_SQ, 768, 768);
        tsplit_kernel<<<dim3(4096/32, 768/32), ts_blk>>>(Win + (long)i*SZ_WIN, wthi + lb + 4*SZ_SQ, 768, 4096);
        tsplit_kernel<<<dim3(768/32, 2048/32), ts_blk>>>(Wout + (long)i*SZ_WOUT, wthi + lb + 4*SZ_SQ + SZ_WIN, 2048, 768);
    }

    copy_kernel<<<(NTOT + 255) / 256, 256>>>(tokens, x, NTOT);

    // value residual: rv = rmsnorm(tokens) @ vr_W
    rmsnorm_split<<<NTOK, 256>>>(tokens, vr_norm_w, nullptr, ahi, alo);
    gemm_f16<<<dim3(6, 128), 256, GEMM_SMEM>>>(ahi, alo, wthi, nullptr, rv,
                                               nullptr, nullptr, DIMV, DIMV, 0, 0, 0);

    for (int i = 0; i < 8; i++) {
        size_t lb = SZ_SQ + (size_t)i * SZ_LAYER;
        const __half* wh = wthi + lb;
        const float* aw   = attn_norm_w + (long)i * DIMV;
        const float* wg   = Wg   + (long)i * DIMV * HEADS;
        const float* wmix = Wmix + (long)i * DIMV * HEADS;
        const float* bm   = bmix + (long)i * HEADS;
        const float* kg   = kgam + (long)i * HEADS * DH;
        const float* fw   = ff_norm_w + (long)i * DIMV;
        const float* bi   = bi_in + (long)i * (2 * DFF);
        const float* bo   = b_out + (long)i * DIMV;
        int is_time = ((i + 1) % 4 == 0) ? 1 : 0;

        // attention block
        rmsnorm_split<<<NTOK, 256>>>(x, aw, tn, ahi, alo);
        gemm_f16<<<dim3(18, 128), 256, GEMM_SMEM>>>(ahi, alo, wh, nullptr, qkv,
                                                    nullptr, nullptr, QKVW, DIMV, 0, 0, 0);
        mixgate_kernel<<<NTOK / 4, 128>>>(tn, wmix, bm, wg, mix, gate);
        if (is_time) attn_time<<<dim3(NTOK / TT, HEADS), 32>>>(qkv, rv, mix, gate, kg, ahi, alo);
        else         attn_space<<<dim3(NTOK / SS, HEADS), 256, ASP_SMEM>>>(qkv, rv, mix, gate, kg, ahi, alo);
        gemm_f16<<<dim3(6, 128), 256, GEMM_SMEM>>>(ahi, alo, wh + 3*SZ_SQ, nullptr, x,
                                                   nullptr, nullptr, DIMV, DIMV, 1, 0, 0);

        // feed-forward block (act fused into FFin epilogue; output to SEPARATE bhi/blo)
        rmsnorm_split<<<NTOK, 256>>>(x, fw, nullptr, ahi, alo);
        gemm_f16<<<dim3(32, 128), 256, GEMM_SMEM>>>(ahi, alo, wh + 4*SZ_SQ, bi, nullptr,
                                                    bhi, blo, 4096, DIMV, 0, 1, 1);
        gemm_f16<<<dim3(6, 128), 256, GEMM_SMEM>>>(bhi, blo, wh + 4*SZ_SQ + SZ_WIN, bo, x,
                                                   nullptr, nullptr, DIMV, DFF, 1, 0, 0);
    }

    rmsnorm_split<<<NTOK, 256>>>(x, final_norm_w, (float*)d_out, nullptr, nullptr);
}

// round 16
// speedup vs baseline: 9.6323x; 1.3833x over previous
#include <cuda_runtime.h>
#include <cuda_fp16.h>
#include <math.h>
#include <stdint.h>

#define NTOK 16384   // B*T*S = 2*32*256
#define DIMV 768
#define HEADS 12
#define DH 64
#define DFF 2048
#define TT 32
#define SS 256
#define QKVW 2304

// weight sizes
#define SZ_SQ   (768*768)
#define SZ_WIN  (768*4096)
#define SZ_WOUT (2048*768)
#define SZ_LAYER (4*SZ_SQ + SZ_WIN + SZ_WOUT)
#define SZ_WTOT (SZ_SQ + 8*SZ_LAYER)

// ---------------- scratch ----------------
__device__ float g_x[NTOK * DIMV];
__device__ float g_tn[NTOK * DIMV];
__device__ float g_qkv[NTOK * QKVW];
__device__ float g_rv[NTOK * DIMV];
__device__ float g_mix[NTOK * HEADS];
__device__ float g_gate[NTOK * HEADS];
__device__ __half g_wthi[SZ_WTOT];
__device__ __half g_ahi[NTOK * DFF];
__device__ __half g_bhi[NTOK * DFF];   // act-fused FFin output (separate buffer: no aliasing)

// ---------------- packed f32x2 helpers ----------------
typedef unsigned long long ull;
#define FMA2(acc, a, b) \
    asm("fma.rn.f32x2 %0, %1, %2, %0;" : "+l"(acc) : "l"(a), "l"(b))
__device__ __forceinline__ ull pack2(float x) {
    ull r;
    asm("mov.b64 %0, {%1, %1};" : "=l"(r) : "r"(__float_as_uint(x)));
    return r;
}
__device__ __forceinline__ float hsum2(ull v) {
    uint32_t lo, hi;
    asm("mov.b64 {%0, %1}, %2;" : "=r"(lo), "=r"(hi) : "l"(v));
    return __uint_as_float(lo) + __uint_as_float(hi);
}
__device__ __forceinline__ void unpack2(ull v, float& a, float& b) {
    uint32_t lo, hi;
    asm("mov.b64 {%0, %1}, %2;" : "=r"(lo), "=r"(hi) : "l"(v));
    a = __uint_as_float(lo); b = __uint_as_float(hi);
}

// ==================== weight transpose (fp16) ====================
__global__ void tsplit_kernel(const float* __restrict__ W,
                              __half* __restrict__ hi, int K, int N) {
    __shared__ float tile[32][33];
    int bn = blockIdx.x * 32, bk = blockIdx.y * 32;
    int tx = threadIdx.x, ty = threadIdx.y;
    #pragma unroll
    for (int i = ty; i < 32; i += 8)
        tile[i][tx] = W[(long)(bk + i) * N + bn + tx];
    __syncthreads();
    #pragma unroll
    for (int i = ty; i < 32; i += 8) {
        float x = tile[tx][i];
        hi[(long)(bn + i) * K + bk + tx] = __float2half_rn(x);
    }
}

// ==================== fp16 HMMA GEMM: 1-term (pure fp16) ====================
#define CH_BYTES 10240
#define BUF_BYTES (2 * CH_BYTES)
#define GEMM_SMEM (2 * BUF_BYTES)

__device__ __forceinline__ uint32_t smem_u32(const void* p) {
    uint32_t a;
    asm("{ .reg .u64 t; cvta.to.shared.u64 t, %1; cvt.u32.u64 %0, t; }" : "=r"(a) : "l"(p));
    return a;
}
__device__ __forceinline__ void cp16(uint32_t dst, const void* src) {
    asm volatile("cp.async.ca.shared.global [%0], [%1], 16;" :: "r"(dst), "l"(src));
}
__device__ __forceinline__ void cp_commit() { asm volatile("cp.async.commit_group;"); }
__device__ __forceinline__ void cp_wait1() { asm volatile("cp.async.wait_group 1;"); }
__device__ __forceinline__ void cp_wait0() { asm volatile("cp.async.wait_group 0;"); }

__device__ __forceinline__ void mma_f16(float* d, const uint32_t* a, const uint32_t* b) {
    asm volatile(
        "mma.sync.aligned.m16n8k16.row.col.f32.f16.f16.f32 "
        "{%0,%1,%2,%3}, {%4,%5,%6,%7}, {%8,%9}, {%0,%1,%2,%3};"
        : "+f"(d[0]), "+f"(d[1]), "+f"(d[2]), "+f"(d[3])
        : "r"(a[0]), "r"(a[1]), "r"(a[2]), "r"(a[3]), "r"(b[0]), "r"(b[1]));
}
__device__ __forceinline__ void ldsm4(uint32_t addr, uint32_t* d) {
    asm volatile("ldmatrix.sync.aligned.m8n8.x4.shared.b16 {%0,%1,%2,%3}, [%4];"
                 : "=r"(d[0]), "=r"(d[1]), "=r"(d[2]), "=r"(d[3]) : "r"(addr));
}
__device__ __forceinline__ int brow_map(int j, int ilv) {
    return ilv ? ((j & 1) ? (DFF + (j >> 1)) : (j >> 1)) : j;
}

__global__ __launch_bounds__(256, 2) void gemm_f16(
    const __half* __restrict__ Ah, const __half* __restrict__ Bh,
    const float* __restrict__ bias, float* __restrict__ C,
    __half* __restrict__ aout_hi,
    int N, int K, int accumulate, int actfuse, int ilv)
{
    extern __shared__ char smem[];
    uint32_t sb = smem_u32(smem);
    int tid = threadIdx.x, wid = tid >> 5, lane = tid & 31;
    int m0 = blockIdx.y * 128, n0 = blockIdx.x * 128;
    int wm = (wid & 1) * 64, wn = (wid >> 1) * 32;
    int g = lane >> 2, tig = lane & 3;
    int mi = lane >> 3, r8 = lane & 7;
    uint32_t offA = (uint32_t)(((mi & 1) * 8 + r8) * 80 + (mi >> 1) * 16);
    uint32_t offB = (uint32_t)(((mi >> 1) * 8 + r8) * 80 + (mi & 1) * 16);

    float acc[4][4][4];
    #pragma unroll
    for (int mt = 0; mt < 4; mt++)
        #pragma unroll
        for (int nt = 0; nt < 4; nt++)
            #pragma unroll
            for (int e = 0; e < 4; e++) acc[mt][nt][e] = 0.f;

    int nchunks = K >> 5;
    int r0 = tid >> 2, s0 = (tid & 3) * 8;
    int r1 = r0 + 64, s1 = s0;
    int bR0 = brow_map(n0 + r0, ilv);
    int bR1 = brow_map(n0 + r1, ilv);

    #define LOADCHUNK(b, kc_) do {                                                     \
        uint32_t base = sb + (b) * BUF_BYTES;                                          \
        cp16(base + r0 * 80 + (s0 << 1),            Ah + (long)(m0 + r0) * K + (kc_) + s0); \
        cp16(base + CH_BYTES + r0 * 80 + (s0 << 1), Bh + (long)bR0 * K + (kc_) + s0);  \
        cp16(base + r1 * 80 + (s1 << 1),            Ah + (long)(m0 + r1) * K + (kc_) + s1); \
        cp16(base + CH_BYTES + r1 * 80 + (s1 << 1), Bh + (long)bR1 * K + (kc_) + s1);  \
    } while (0)

    LOADCHUNK(0, 0);
    cp_commit();

    for (int c = 0; c < nchunks; c++) {
        if (c + 1 < nchunks) {
            LOADCHUNK((c + 1) & 1, (c + 1) << 5);
            cp_commit();
            cp_wait1();
        } else {
            cp_wait0();
        }
        __syncthreads();

        uint32_t bufAh = sb + (c & 1) * BUF_BYTES;
        uint32_t bufBh = bufAh + CH_BYTES;

        #pragma unroll
        for (int ks = 0; ks < 32; ks += 16) {
            uint32_t kb = (uint32_t)(ks * 2);
            uint32_t bh[8];
            ldsm4(bufBh + (uint32_t)(wn) * 80 + kb + offB, bh);
            ldsm4(bufBh + (uint32_t)(wn + 16) * 80 + kb + offB, bh + 4);
            #pragma unroll
            for (int mt = 0; mt < 4; mt++) {
                uint32_t ah[4];
                ldsm4(bufAh + (uint32_t)(wm + mt * 16) * 80 + kb + offA, ah);
                #pragma unroll
                for (int nt = 0; nt < 4; nt++)
                    mma_f16(acc[mt][nt], ah, bh + nt * 2);
            }
        }
        __syncthreads();
    }

    if (actfuse) {
        // columns are interleaved (a,g) pairs; compute a*gelu(g), write fp16
        #pragma unroll
        for (int mt = 0; mt < 4; mt++) {
            long r = m0 + wm + mt * 16 + g;
            #pragma unroll
            for (int nt = 0; nt < 4; nt++) {
                int pair = ((n0 + wn + nt * 8) >> 1) + tig;
                float ba = bias ? bias[pair] : 0.f;
                float bg = bias ? bias[DFF + pair] : 0.f;
                #pragma unroll
                for (int half = 0; half < 2; half++) {
                    float a = acc[mt][nt][half * 2] + ba;
                    float gg = acc[mt][nt][half * 2 + 1] + bg;
                    float rr = a * 0.5f * gg * (1.f + erff(gg * 0.70710678118654752f));
                    aout_hi[(r + half * 8) * DFF + pair] = __float2half_rn(rr);
                }
            }
        }
    } else {
        #pragma unroll
        for (int mt = 0; mt < 4; mt++) {
            long r = m0 + wm + mt * 16 + g;
            #pragma unroll
            for (int nt = 0; nt < 4; nt++) {
                int c = n0 + wn + nt * 8 + tig * 2;
                float v0 = acc[mt][nt][0], v1 = acc[mt][nt][1];
                float v2 = acc[mt][nt][2], v3 = acc[mt][nt][3];
                if (bias) { v0 += bias[c]; v1 += bias[c + 1]; v2 += bias[c]; v3 += bias[c + 1]; }
                if (accumulate) {
                    C[r * N + c]           += v0;
                    C[r * N + c + 1]       += v1;
                    C[(r + 8) * N + c]     += v2;
                    C[(r + 8) * N + c + 1] += v3;
                } else {
                    C[r * N + c]           = v0;
                    C[r * N + c + 1]       = v1;
                    C[(r + 8) * N + c]     = v2;
                    C[(r + 8) * N + c + 1] = v3;
                }
            }
        }
    }
}

// ---------------- elementwise ----------------
__global__ void copy_kernel(const float* __restrict__ src, float* __restrict__ dst, int n) {
    int i = blockIdx.x * blockDim.x + threadIdx.x;
    if (i < n) dst[i] = src[i];
}

// rmsnorm + fp16 cast
__global__ void rmsnorm_split(const float* __restrict__ x, const float* __restrict__ w,
                              float* __restrict__ outf, __half* __restrict__ hi) {
    int tok = blockIdx.x;
    int tid = threadIdx.x;
    const float* xr = x + (long)tok * DIMV;
    float v0 = xr[tid], v1 = xr[tid + 256], v2 = xr[tid + 512];
    __shared__ float red[256];
    red[tid] = v0 * v0 + v1 * v1 + v2 * v2;
    __syncthreads();
    for (int off = 128; off > 0; off >>= 1) {
        if (tid < off) red[tid] += red[tid + off];
        __syncthreads();
    }
    float inv = rsqrtf(red[0] / (float)DIMV + 1e-6f);
    float r0 = v0 * inv * w[tid];
    float r1 = v1 * inv * w[tid + 256];
    float r2 = v2 * inv * w[tid + 512];
    long base = (long)tok * DIMV;
    if (outf) { outf[base + tid] = r0; outf[base + tid + 256] = r1; outf[base + tid + 512] = r2; }
    if (hi) {
        hi[base + tid]       = __float2half_rn(r0);
        hi[base + tid + 256] = __float2half_rn(r1);
        hi[base + tid + 512] = __float2half_rn(r2);
    }
}

// ---------------- mix & gate projection ----------------
__global__ __launch_bounds__(128) void mixgate_kernel(
    const float* __restrict__ tn,
    const float* __restrict__ Wmix, const float* __restrict__ bmix,
    const float* __restrict__ Wg,
    float* __restrict__ mix, float* __restrict__ gate)
{
    int tok = blockIdx.x * 4 + (threadIdx.x >> 5);
    int lane = threadIdx.x & 31;
    const float* x = tn + (long)tok * DIMV;
    float t[24];
    #pragma unroll
    for (int e = 0; e < 24; e++) t[e] = x[lane + 32 * e];
    for (int col = 0; col < HEADS; col++) {
        float am = 0.f, ag = 0.f;
        #pragma unroll
        for (int e = 0; e < 24; e++) {
            int d = lane + 32 * e;
            am += t[e] * Wmix[d * HEADS + col];
            ag += t[e] * Wg[d * HEADS + col];
        }
        #pragma unroll
        for (int off = 16; off > 0; off >>= 1) {
            am += __shfl_xor_sync(0xffffffffu, am, off);
            ag += __shfl_xor_sync(0xffffffffu, ag, off);
        }
        if (lane == 0) {
            mix[tok * HEADS + col]  = 1.f / (1.f + __expf(-(am + bmix[col])));
            gate[tok * HEADS + col] = 1.f / (1.f + __expf(-ag));
        }
    }
}

__device__ __forceinline__ float softclamp(float acc) {
    float t = __expf(acc * 0.005f);
    return 50.f * __fdividef(t - 1.f, t + 1.f);
}

// ---------------- space attention ----------------
#define ASP_SMEM (2 * SS * DH * 4 + SS * 4)
__global__ __launch_bounds__(256, 1) void attn_space(
    const float* __restrict__ qkv, const float* __restrict__ rv,
    const float* __restrict__ mix, const float* __restrict__ gate,
    const float* __restrict__ kgam, __half* __restrict__ ohi)
{
    int r = blockIdx.x, h = blockIdx.y;
    long base = (long)r * SS;
    extern __shared__ float sm[];
    float* Ks = sm;
    float* Vs = sm + SS * DH;
    float* mixs = sm + 2 * SS * DH;
    int tid = threadIdx.x;

    if (tid < SS) mixs[tid] = mix[(base + tid) * HEADS + h];
    __syncthreads();

    for (int idx = tid; idx < SS * DH; idx += 256) {
        int j = idx >> 6, d = idx & 63;
        long tok = base + j;
        float vv = qkv[tok * QKVW + 1536 + h * DH + d];
        Vs[idx] = vv + mixs[j] * (rv[tok * DIMV + h * DH + d] - vv);
        Ks[idx] = qkv[tok * QKVW + 768 + h * DH + d];
    }
    __syncthreads();

    {
        int wid = tid >> 5, lane = tid & 31;
        float g1 = (kgam[h * DH + lane] + 1.f) * 8.0f;
        float g2 = (kgam[h * DH + lane + 32] + 1.f) * 8.0f;
        for (int j = wid * 32; j < wid * 32 + 32; j++) {
            float a = Ks[j * DH + lane], b = Ks[j * DH + lane + 32];
            float ss = a * a + b * b;
            #pragma unroll
            for (int off = 16; off > 0; off >>= 1) ss += __shfl_xor_sync(0xffffffffu, ss, off);
            float inv = 1.f / fmaxf(sqrtf(ss), 1e-12f);
            Ks[j * DH + lane]      = a * inv * g1;
            Ks[j * DH + lane + 32] = b * inv * g2;
        }
    }
    __syncthreads();

    long mytok = base + tid;
    ull qr2[32];
    {
        const ull* qp = (const ull*)(qkv + mytok * QKVW + h * DH);
        #pragma unroll
        for (int e = 0; e < 32; e++) qr2[e] = qp[e];
    }

    float s = 0.f;
    ull oa[32];
    #pragma unroll
    for (int e = 0; e < 32; e++) oa[e] = 0ull;
    for (int j = 0; j < SS; j++) {
        const ull* kp = (const ull*)(Ks + j * DH);
        ull acc2 = 0ull;
        #pragma unroll
        for (int e = 0; e < 32; e++) FMA2(acc2, qr2[e], kp[e]);
        float p = __expf(softclamp(hsum2(acc2)));
        s += p;
        ull p2 = pack2(p);
        const ull* vp = (const ull*)(Vs + j * DH);
        #pragma unroll
        for (int e = 0; e < 32; e++) FMA2(oa[e], p2, vp[e]);
    }
    float gg = gate[mytok * HEADS + h] / s;
    long ob = mytok * DIMV + h * DH;
    #pragma unroll
    for (int e = 0; e < 32; e++) {
        float a, b;
        unpack2(oa[e], a, b);
        ohi[ob + e * 2]     = __float2half_rn(a * gg);
        ohi[ob + e * 2 + 1] = __float2half_rn(b * gg);
    }
}

// ---------------- time attention (causal) ----------------
__global__ __launch_bounds__(32) void attn_time(
    const float* __restrict__ qkv, const float* __restrict__ rv,
    const float* __restrict__ mix, const float* __restrict__ gate,
    const float* __restrict__ kgam, __half* __restrict__ ohi)
{
    int r = blockIdx.x, h = blockIdx.y;
    int b = r / SS, s0 = r % SS;
    long base = (long)b * (TT * SS) + s0;
    __shared__ float Ks[TT * DH], Vs[TT * DH], mixs[TT];
    int tid = threadIdx.x;

    mixs[tid] = mix[(base + (long)tid * SS) * HEADS + h];
    __syncwarp();
    for (int idx = tid; idx < TT * DH; idx += 32) {
        int j = idx >> 6, d = idx & 63;
        long tok = base + (long)j * SS;
        float vv = qkv[tok * QKVW + 1536 + h * DH + d];
        Vs[idx] = vv + mixs[j] * (rv[tok * DIMV + h * DH + d] - vv);
        Ks[idx] = qkv[tok * QKVW + 768 + h * DH + d];
    }
    __syncwarp();

    {
        float g1 = (kgam[h * DH + tid] + 1.f) * 8.0f;
        float g2 = (kgam[h * DH + tid + 32] + 1.f) * 8.0f;
        float invf = __powf(10000.0f, -(float)(2 * tid) / (float)DH);
        for (int j = 0; j < TT; j++) {
            float a = Ks[j * DH + tid], b2 = Ks[j * DH + tid + 32];
            float ss = a * a + b2 * b2;
            #pragma unroll
            for (int off = 16; off > 0; off >>= 1) ss += __shfl_xor_sync(0xffffffffu, ss, off);
            float inv = 1.f / fmaxf(sqrtf(ss), 1e-12f);
            a = a * inv * g1;
            b2 = b2 * inv * g2;
            float ang = (float)j * invf;
            float cc = cosf(ang), sn = sinf(ang);
            Ks[j * DH + tid]      = a * cc - b2 * sn;
            Ks[j * DH + tid + 32] = b2 * cc + a * sn;
        }
    }
    __syncwarp();

    long mytok = base + (long)tid * SS;
    float qf[64];
    {
        const float4* qp = (const float4*)(qkv + mytok * QKVW + h * DH);
        #pragma unroll
        for (int e = 0; e < 16; e++) ((float4*)qf)[e] = qp[e];
        #pragma unroll
        for (int d = 0; d < 32; d++) {
            float invf = __powf(10000.0f, -(float)(2 * d) / (float)DH);
            float ang = (float)tid * invf;
            float cc = cosf(ang), sn = sinf(ang);
            float x1 = qf[d], x2 = qf[d + 32];
            qf[d]      = x1 * cc - x2 * sn;
            qf[d + 32] = x2 * cc + x1 * sn;
        }
    }
    ull qr2[32];
    #pragma unroll
    for (int e = 0; e < 32; e++) qr2[e] = ((const ull*)qf)[e];

    int nkeys = tid + 1;
    float s = 0.f;
    ull oa[32];
    #pragma unroll
    for (int e = 0; e < 32; e++) oa[e] = 0ull;
    for (int j = 0; j < nkeys; j++) {
        const ull* kp = (const ull*)(Ks + j * DH);
        ull acc2 = 0ull;
        #pragma unroll
        for (int e = 0; e < 32; e++) FMA2(acc2, qr2[e], kp[e]);
        float p = __expf(softclamp(hsum2(acc2)));
        s += p;
        ull p2 = pack2(p);
        const ull* vp = (const ull*)(Vs + j * DH);
        #pragma unroll
        for (int e = 0; e < 32; e++) FMA2(oa[e], p2, vp[e]);
    }
    float gg = gate[mytok * HEADS + h] / s;
    long ob = mytok * DIMV + h * DH;
    #pragma unroll
    for (int e = 0; e < 32; e++) {
        float a, b;
        unpack2(oa[e], a, b);
        ohi[ob + e * 2]     = __float2half_rn(a * gg);
        ohi[ob + e * 2 + 1] = __float2half_rn(b * gg);
    }
}

// ---------------- launch ----------------
extern "C" void kernel_launch(void* const* d_in, const int* in_sizes, int n_in,
                              void* d_out, int out_size) {
    const float* tokens      = (const float*)d_in[0];
    const float* attn_norm_w = (const float*)d_in[1];
    const float* Wq          = (const float*)d_in[2];
    const float* Wk          = (const float*)d_in[3];
    const float* Wv          = (const float*)d_in[4];
    const float* Wo          = (const float*)d_in[5];
    const float* Wg          = (const float*)d_in[6];
    const float* Wmix        = (const float*)d_in[7];
    const float* bmix        = (const float*)d_in[8];
    const float* kgam        = (const float*)d_in[9];
    const float* ff_norm_w   = (const float*)d_in[10];
    const float* Win         = (const float*)d_in[11];
    const float* bi_in       = (const float*)d_in[12];
    const float* Wout        = (const float*)d_in[13];
    const float* b_out       = (const float*)d_in[14];
    const float* vr_norm_w   = (const float*)d_in[15];
    const float* vr_W        = (const float*)d_in[16];
    const float* final_norm_w= (const float*)d_in[17];

    float *x, *tn, *qkv, *rv, *mix, *gate;
    __half *wthi, *ahi, *bhi;
    cudaGetSymbolAddress((void**)&x,   g_x);
    cudaGetSymbolAddress((void**)&tn,  g_tn);
    cudaGetSymbolAddress((void**)&qkv, g_qkv);
    cudaGetSymbolAddress((void**)&rv,  g_rv);
    cudaGetSymbolAddress((void**)&mix, g_mix);
    cudaGetSymbolAddress((void**)&gate,g_gate);
    cudaGetSymbolAddress((void**)&wthi,g_wthi);
    cudaGetSymbolAddress((void**)&ahi, g_ahi);
    cudaGetSymbolAddress((void**)&bhi, g_bhi);

    static int attr_done = 0;
    if (!attr_done) {
        cudaFuncSetAttribute(gemm_f16, cudaFuncAttributeMaxDynamicSharedMemorySize, GEMM_SMEM);
        cudaFuncSetAttribute(attn_space, cudaFuncAttributeMaxDynamicSharedMemorySize, ASP_SMEM);
        attr_done = 1;
    }

    const int NTOT = NTOK * DIMV;
    dim3 ts_blk(32, 8);

    // ---- transpose weights to fp16 [N][K] ----
    tsplit_kernel<<<dim3(768/32, 768/32), ts_blk>>>(vr_W, wthi, 768, 768);
    for (int i = 0; i < 8; i++) {
        size_t lb = SZ_SQ + (size_t)i * SZ_LAYER;
        tsplit_kernel<<<dim3(768/32, 768/32), ts_blk>>>(Wq + (long)i*SZ_SQ,  wthi + lb,           768, 768);
        tsplit_kernel<<<dim3(768/32, 768/32), ts_blk>>>(Wk + (long)i*SZ_SQ,  wthi + lb + SZ_SQ,   768, 768);
        tsplit_kernel<<<dim3(768/32, 768/32), ts_blk>>>(Wv + (long)i*SZ_SQ,  wthi + lb + 2*SZ_SQ, 768, 768);
        tsplit_kernel<<<dim3(768/32, 768/32), ts_blk>>>(Wo + (long)i*SZ_SQ,  wthi + lb + 3*SZ_SQ, 768, 768);
        tsplit_kernel<<<dim3(4096/32, 768/32), ts_blk>>>(Win + (long)i*SZ_WIN, wthi + lb + 4*SZ_SQ, 768, 4096);
        tsplit_kernel<<<dim3(768/32, 2048/32), ts_blk>>>(Wout + (long)i*SZ_WOUT, wthi + lb + 4*SZ_SQ + SZ_WIN, 2048, 768);
    }

    copy_kernel<<<(NTOT + 255) / 256, 256>>>(tokens, x, NTOT);

    // value residual: rv = rmsnorm(tokens) @ vr_W
    rmsnorm_split<<<NTOK, 256>>>(tokens, vr_norm_w, nullptr, ahi);
    gemm_f16<<<dim3(6, 128), 256, GEMM_SMEM>>>(ahi, wthi, nullptr, rv, nullptr,
                                               DIMV, DIMV, 0, 0, 0);

    for (int i = 0; i < 8; i++) {
        size_t lb = SZ_SQ + (size_t)i * SZ_LAYER;
        const __half* wh = wthi + lb;
        const float* aw   = attn_norm_w + (long)i * DIMV;
        const float* wg   = Wg   + (long)i * DIMV * HEADS;
        const float* wmix = Wmix + (long)i * DIMV * HEADS;
        const float* bm   = bmix + (long)i * HEADS;
        const float* kg   = kgam + (long)i * HEADS * DH;
        const float* fw   = ff_norm_w + (long)i * DIMV;
        const float* bi   = bi_in + (long)i * (2 * DFF);
        const float* bo   = b_out + (long)i * DIMV;
        int is_time = ((i + 1) % 4 == 0) ? 1 : 0;

        // attention block
        rmsnorm_split<<<NTOK, 256>>>(x, aw, tn, ahi);
        gemm_f16<<<dim3(18, 128), 256, GEMM_SMEM>>>(ahi, wh, nullptr, qkv, nullptr,
                                                    QKVW, DIMV, 0, 0, 0);
        mixgate_kernel<<<NTOK / 4, 128>>>(tn, wmix, bm, wg, mix, gate);
        if (is_time) attn_time<<<dim3(NTOK / TT, HEADS), 32>>>(qkv, rv, mix, gate, kg, ahi);
        else         attn_space<<<dim3(NTOK / SS, HEADS), 256, ASP_SMEM>>>(qkv, rv, mix, gate, kg, ahi);
        gemm_f16<<<dim3(6, 128), 256, GEMM_SMEM>>>(ahi, wh + 3*SZ_SQ, nullptr, x, nullptr,
                                                   DIMV, DIMV, 1, 0, 0);

        // feed-forward block (act fused into FFin epilogue; output to separate bhi)
        rmsnorm_split<<<NTOK, 256>>>(x, fw, nullptr, ahi);
        gemm_f16<<<dim3(32, 128), 256, GEMM_SMEM>>>(ahi, wh + 4*SZ_SQ, bi, nullptr, bhi,
                                                    4096, DIMV, 0, 1, 1);
        gemm_f16<<<dim3(6, 128), 256, GEMM_SMEM>>>(bhi, wh + 4*SZ_SQ + SZ_WIN, bo, x, nullptr,
                                                   DIMV, DFF, 1, 0, 0);
    }

    rmsnorm_split<<<NTOK, 256>>>(x, final_norm_w, (float*)d_out, nullptr);
}